// round 4
// baseline (speedup 1.0000x reference)
#include <cuda_runtime.h>
#include <math.h>

#define TOK   2048      // B*S
#define HID   1024
#define KAUG  9216      // H*(1+NB)
#define NB    8
#define NHEAD 16
#define HDIM  64
#define SEQ   1024
#define BATCH 2
#define DFF   1024
#define NEXP  4

// ---------------- scratch (static device globals; no runtime alloc) ----------------
__device__ float g_phi[(size_t)TOK * KAUG];          // phi(hn) then phi(h2)
__device__ float g_qkv[(size_t)TOK * 3 * HID];
__device__ float g_ctx[(size_t)TOK * HID];
__device__ float g_x2[(size_t)TOK * HID];
__device__ float g_t1[(size_t)TOK * DFF];
__device__ float g_t2[(size_t)TOK * DFF];
__device__ float g_phit[(size_t)TOK * 9 * DFF];
__device__ float g_logits[TOK * NEXP];
__device__ int   g_cnt[NEXP];
__device__ int   g_eidx[NEXP * TOK];
__device__ float g_ew[NEXP * TOK];

// ---------------- cubic B-spline bases, G=5, K=3, grid = i*0.4-1 for i in [-3,8] ----
__device__ __forceinline__ void bspline8(float v, float* out) {
    float b[11];
#pragma unroll
    for (int t = 0; t < 11; t++) {
        float g0 = 0.4f * (t - 3) - 1.0f;
        float g1 = 0.4f * (t - 2) - 1.0f;
        b[t] = (v >= g0 && v < g1) ? 1.0f : 0.0f;
    }
#pragma unroll
    for (int j = 1; j <= 3; j++) {
        float inv = 1.0f / (0.4f * (float)j);
#pragma unroll
        for (int t = 0; t < 10; t++) {
            if (t < 11 - j) {
                float gt   = 0.4f * (t - 3) - 1.0f;
                float gtj1 = 0.4f * (t + j - 2) - 1.0f;
                b[t] = (v - gt) * inv * b[t] + (gtj1 - v) * inv * b[t + 1];
            }
        }
    }
#pragma unroll
    for (int c = 0; c < 8; c++) out[c] = b[c];
}

// ---------------- rmsnorm + phi expansion (+ optional gate logits) ------------------
__global__ void rmsnorm_phi_kernel(const float* __restrict__ x,
                                   const float* __restrict__ w,
                                   float* __restrict__ phi,
                                   const float* __restrict__ gate_w,
                                   float* __restrict__ logits) {
    int m = blockIdx.x;
    int tid = threadIdx.x;
    __shared__ float sx[HID];
    __shared__ float sred[256];
    const float* xr = x + (size_t)m * HID;
    float ss = 0.f;
    for (int f = tid; f < HID; f += 256) { float v = xr[f]; sx[f] = v; ss += v * v; }
    sred[tid] = ss; __syncthreads();
    for (int o = 128; o > 0; o >>= 1) { if (tid < o) sred[tid] += sred[tid + o]; __syncthreads(); }
    float rms = rsqrtf(sred[0] / (float)HID + 1e-6f);
    float gacc[4] = {0.f, 0.f, 0.f, 0.f};
    float* phir = phi + (size_t)m * KAUG;
    for (int f = tid; f < HID; f += 256) {
        float hn = sx[f] * rms * w[f];
        phir[f] = hn / (1.0f + expf(-hn));     // silu
        float bs[8];
        bspline8(hn, bs);
#pragma unroll
        for (int c = 0; c < 8; c++) phir[HID + f * 8 + c] = bs[c];
        if (gate_w) {
#pragma unroll
            for (int e = 0; e < 4; e++) gacc[e] += hn * gate_w[e * HID + f];
        }
    }
    if (gate_w) {
#pragma unroll
        for (int e = 0; e < 4; e++) {
            __syncthreads();
            sred[tid] = gacc[e]; __syncthreads();
            for (int o = 128; o > 0; o >>= 1) { if (tid < o) sred[tid] += sred[tid + o]; __syncthreads(); }
            if (tid == 0) logits[m * 4 + e] = sred[0];
        }
    }
}

// ---------------- phi expansion of t = t1*t2 (expert hidden), compacted rows --------
__global__ void mul_phi_kernel(const float* __restrict__ t1, const float* __restrict__ t2,
                               float* __restrict__ phit, const int* __restrict__ cnt) {
    int r = blockIdx.x;
    if (r >= *cnt) return;
    int tid = threadIdx.x;
    const float* a = t1 + (size_t)r * DFF;
    const float* b = t2 + (size_t)r * DFF;
    float* pr = phit + (size_t)r * (9 * DFF);
    for (int f = tid; f < DFF; f += 256) {
        float v = a[f] * b[f];
        pr[f] = v / (1.0f + expf(-v));
        float bs[8];
        bspline8(v, bs);
#pragma unroll
        for (int c = 0; c < 8; c++) pr[DFF + f * 8 + c] = bs[c];
    }
}

// ---------------- generic fused-KAN SGEMM: C[m,n] = sum_k A[m,k]*Waug[n,k] ----------
// EPI 0: plain store. EPI 1: +res+bias, dual store (C and C2). EPI 2: scatter-accum.
template <int EPI>
__global__ void kan_gemm(const float* __restrict__ A, int lda, const int* __restrict__ a_idx,
                         const float* __restrict__ Bbase, const float* __restrict__ Bspline,
                         const float* __restrict__ Bscaler, int Kin, int ldb,
                         float* __restrict__ C, int ldc,
                         int M, int N, int K, const int* __restrict__ cnt,
                         const float* __restrict__ res, const float* __restrict__ bias,
                         float* __restrict__ C2,
                         const int* __restrict__ out_idx, const float* __restrict__ out_w) {
    int Meff = cnt ? *cnt : M;
    int mBase = blockIdx.y * 128;
    int nBase = blockIdx.x * 128;
    if (mBase >= Meff) return;

    __shared__ float As[8][132];
    __shared__ float Bs[8][132];

    int tid = threadIdx.x;
    int lm = tid >> 1;            // 0..127
    int lk = (tid & 1) * 4;       // 0 or 4
    int tm = (tid >> 4) * 8;      // output row block (local)
    int tn = (tid & 15) * 8;      // output col block (local)

    float acc[8][8];
#pragma unroll
    for (int i = 0; i < 8; i++)
#pragma unroll
        for (int j = 0; j < 8; j++) acc[i][j] = 0.f;

    int arow = mBase + lm;
    bool avalid = arow < Meff;
    int arow_g = avalid ? (a_idx ? a_idx[arow] : arow) : 0;
    const float* aptr = A + (size_t)arow_g * lda + lk;
    int nrow = nBase + lm;

    for (int k0 = 0; k0 < K; k0 += 8) {
        float4 av = avalid ? *(const float4*)(aptr + k0) : make_float4(0.f, 0.f, 0.f, 0.f);
        As[lk + 0][lm] = av.x; As[lk + 1][lm] = av.y;
        As[lk + 2][lm] = av.z; As[lk + 3][lm] = av.w;

        int kg = k0 + lk;
        float4 bv;
        if (Bspline) {
            if (kg < Kin) {
                bv = *(const float4*)(Bbase + (size_t)nrow * Kin + kg);
            } else {
                int ko = kg - Kin;
                bv = *(const float4*)(Bspline + (size_t)nrow * (Kin * 8) + ko);
                float sc = Bscaler[(size_t)nrow * Kin + (ko >> 3)];
                bv.x *= sc; bv.y *= sc; bv.z *= sc; bv.w *= sc;
            }
        } else {
            bv = *(const float4*)(Bbase + (size_t)nrow * ldb + kg);
        }
        Bs[lk + 0][lm] = bv.x; Bs[lk + 1][lm] = bv.y;
        Bs[lk + 2][lm] = bv.z; Bs[lk + 3][lm] = bv.w;
        __syncthreads();

#pragma unroll
        for (int kk = 0; kk < 8; kk++) {
            float a0[8], b0[8];
            *(float4*)(a0)     = *(const float4*)&As[kk][tm];
            *(float4*)(a0 + 4) = *(const float4*)&As[kk][tm + 4];
            *(float4*)(b0)     = *(const float4*)&Bs[kk][tn];
            *(float4*)(b0 + 4) = *(const float4*)&Bs[kk][tn + 4];
#pragma unroll
            for (int i = 0; i < 8; i++)
#pragma unroll
                for (int j = 0; j < 8; j++) acc[i][j] += a0[i] * b0[j];
        }
        __syncthreads();
    }

#pragma unroll
    for (int i = 0; i < 8; i++) {
        int m = mBase + tm + i;
        if (m >= Meff) continue;
#pragma unroll
        for (int j = 0; j < 8; j++) {
            int n = nBase + tn + j;
            float v = acc[i][j];
            if (EPI == 0) {
                C[(size_t)m * ldc + n] = v;
            } else if (EPI == 1) {
                float r = v + res[(size_t)m * ldc + n] + bias[n];
                C[(size_t)m * ldc + n] = r;
                C2[(size_t)m * ldc + n] = r;
            } else {
                int tok = out_idx[m];
                C[(size_t)tok * ldc + n] += out_w[m] * v;
            }
        }
    }
}

// ---------------- RoPE on q,k in-place -------------------------------------------
__global__ void rope_kernel(float* __restrict__ qkv, const float* __restrict__ rc,
                            const float* __restrict__ rs) {
    int idx = blockIdx.x * 256 + threadIdx.x;
    if (idx >= TOK * NHEAD * 32) return;
    int d2 = idx & 31;
    int nh = (idx >> 5) & 15;
    int m = idx >> 9;
    int s = m & (SEQ - 1);
    float c = rc[s * 32 + d2], sn = rs[s * 32 + d2];
    float* p = qkv + (size_t)m * 3072 + nh * 192 + 2 * d2;
    float re = p[0], im = p[1];
    p[0] = re * c - im * sn; p[1] = re * sn + im * c;
    float* pk = p + 64;
    re = pk[0]; im = pk[1];
    pk[0] = re * c - im * sn; pk[1] = re * sn + im * c;
}

// ---------------- flash attention: 64-q-tile per CTA, streaming softmax -----------
// smem layout (dynamic): Qs[64][68] | Ks[64][68] | Ss[64][68] | Vs[64][68] | Pred[64][20]
#define FA_STRIDE 68
#define FA_TILE   (64 * FA_STRIDE)
__global__ void flash_attn_kernel(const float* __restrict__ qkv, float* __restrict__ ctx) {
    extern __shared__ float smem[];
    float* Qs   = smem;                 // [d][q]
    float* Ks   = Qs + FA_TILE;         // [d][k]
    float* Ss   = Ks + FA_TILE;         // [q][k]  (P tile)
    float* Vs   = Ss + FA_TILE;         // [k][d]
    float* Pred = Vs + FA_TILE;         // [q][16] partial reductions, stride 20

    int qt = blockIdx.x, bh = blockIdx.y;
    int b = bh >> 4, h = bh & 15;
    int tid = threadIdx.x;
    int r  = tid >> 2;                  // 0..63 (row loader)
    int c4 = (tid & 3) * 16;            // 0,16,32,48
    int q0 = (tid >> 4) * 4;            // 4 q rows owned
    int kc0 = (tid & 15) * 4;           // 4 cols owned (k or d)
    int pcol = tid & 15;

    // load Q tile transposed: Qs[d][q]
    const float* qbase = qkv + (size_t)(b * SEQ + qt * 64 + r) * 3072 + h * 192;
#pragma unroll
    for (int u = 0; u < 4; u++) {
        float4 qv = *(const float4*)(qbase + c4 + u * 4);
        Qs[(c4 + u * 4 + 0) * FA_STRIDE + r] = qv.x;
        Qs[(c4 + u * 4 + 1) * FA_STRIDE + r] = qv.y;
        Qs[(c4 + u * 4 + 2) * FA_STRIDE + r] = qv.z;
        Qs[(c4 + u * 4 + 3) * FA_STRIDE + r] = qv.w;
    }

    float o[4][4];
    float m_i[4], l_i[4];
#pragma unroll
    for (int i = 0; i < 4; i++) {
        m_i[i] = -1e30f; l_i[i] = 0.f;
#pragma unroll
        for (int j = 0; j < 4; j++) o[i][j] = 0.f;
    }

    for (int kt = 0; kt < SEQ / 64; kt++) {
        __syncthreads();   // previous iteration consumers done (also covers Q load on iter 0)
        // load K tile transposed [d][k], V tile [k][d]
        const float* kbase = qkv + (size_t)(b * SEQ + kt * 64 + r) * 3072 + h * 192 + 64;
        const float* vbase = kbase + 64;
#pragma unroll
        for (int u = 0; u < 4; u++) {
            float4 kv = *(const float4*)(kbase + c4 + u * 4);
            Ks[(c4 + u * 4 + 0) * FA_STRIDE + r] = kv.x;
            Ks[(c4 + u * 4 + 1) * FA_STRIDE + r] = kv.y;
            Ks[(c4 + u * 4 + 2) * FA_STRIDE + r] = kv.z;
            Ks[(c4 + u * 4 + 3) * FA_STRIDE + r] = kv.w;
            *(float4*)&Vs[r * FA_STRIDE + c4 + u * 4] = *(const float4*)(vbase + c4 + u * 4);
        }
        __syncthreads();

        // S = Q K^T / 8 (registers)
        float s[4][4];
#pragma unroll
        for (int i = 0; i < 4; i++)
#pragma unroll
            for (int j = 0; j < 4; j++) s[i][j] = 0.f;
#pragma unroll 8
        for (int d = 0; d < 64; d++) {
            float a0[4], b0[4];
            *(float4*)a0 = *(const float4*)&Qs[d * FA_STRIDE + q0];
            *(float4*)b0 = *(const float4*)&Ks[d * FA_STRIDE + kc0];
#pragma unroll
            for (int i = 0; i < 4; i++)
#pragma unroll
                for (int j = 0; j < 4; j++) s[i][j] += a0[i] * b0[j];
        }
#pragma unroll
        for (int i = 0; i < 4; i++)
#pragma unroll
            for (int j = 0; j < 4; j++) s[i][j] *= 0.125f;

        // partial row max -> Pred
#pragma unroll
        for (int i = 0; i < 4; i++) {
            float pm = fmaxf(fmaxf(s[i][0], s[i][1]), fmaxf(s[i][2], s[i][3]));
            Pred[(q0 + i) * 20 + pcol] = pm;
        }
        __syncthreads();
        float mnew[4], corr[4];
#pragma unroll
        for (int i = 0; i < 4; i++) {
            float mx = m_i[i];
            const float* pr = &Pred[(q0 + i) * 20];
#pragma unroll
            for (int t = 0; t < 16; t++) mx = fmaxf(mx, pr[t]);
            mnew[i] = mx;
            corr[i] = expf(m_i[i] - mx);
            m_i[i] = mx;
        }
        __syncthreads();   // all max-reads done before Pred reuse

        // P = exp(S - mnew); partial row sums
#pragma unroll
        for (int i = 0; i < 4; i++) {
            float ps = 0.f;
#pragma unroll
            for (int j = 0; j < 4; j++) {
                float p = expf(s[i][j] - mnew[i]);
                Ss[(q0 + i) * FA_STRIDE + kc0 + j] = p;
                ps += p;
            }
            Pred[(q0 + i) * 20 + pcol] = ps;
        }
        __syncthreads();

        // l update + rescale o
#pragma unroll
        for (int i = 0; i < 4; i++) {
            float rs = 0.f;
            const float* pr = &Pred[(q0 + i) * 20];
#pragma unroll
            for (int t = 0; t < 16; t++) rs += pr[t];
            l_i[i] = corr[i] * l_i[i] + rs;
#pragma unroll
            for (int j = 0; j < 4; j++) o[i][j] *= corr[i];
        }

        // o += P V
#pragma unroll 8
        for (int kk = 0; kk < 64; kk++) {
            float a0[4], b0[4];
            a0[0] = Ss[(q0 + 0) * FA_STRIDE + kk];
            a0[1] = Ss[(q0 + 1) * FA_STRIDE + kk];
            a0[2] = Ss[(q0 + 2) * FA_STRIDE + kk];
            a0[3] = Ss[(q0 + 3) * FA_STRIDE + kk];
            *(float4*)b0 = *(const float4*)&Vs[kk * FA_STRIDE + kc0];
#pragma unroll
            for (int i = 0; i < 4; i++)
#pragma unroll
                for (int j = 0; j < 4; j++) o[i][j] += a0[i] * b0[j];
        }
    }

    // normalize + write ctx (b, s, h*64+d)
#pragma unroll
    for (int i = 0; i < 4; i++) {
        float inv = 1.0f / l_i[i];
#pragma unroll
        for (int j = 0; j < 4; j++)
            ctx[(size_t)(b * SEQ + qt * 64 + q0 + i) * HID + h * 64 + kc0 + j] = o[i][j] * inv;
    }
}

// ---------------- MoE routing -----------------------------------------------------
__global__ void init_cnt_kernel() {
    if (threadIdx.x < NEXP) g_cnt[threadIdx.x] = 0;
}

__global__ void routing_kernel() {
    int m = blockIdx.x * 256 + threadIdx.x;
    if (m >= TOK) return;
    float l[4];
#pragma unroll
    for (int e = 0; e < 4; e++) l[e] = g_logits[m * 4 + e];
    int i0 = 0; float b0 = l[0];
#pragma unroll
    for (int e = 1; e < 4; e++) if (l[e] > b0) { b0 = l[e]; i0 = e; }
    int i1 = -1; float b1 = -1e30f;
#pragma unroll
    for (int e = 0; e < 4; e++) if (e != i0 && l[e] > b1) { b1 = l[e]; i1 = e; }
    float t = expf(b1 - b0);
    float w0 = 1.0f / (1.0f + t);
    float w1 = t / (1.0f + t);
    int p0 = atomicAdd(&g_cnt[i0], 1);
    g_eidx[i0 * TOK + p0] = m; g_ew[i0 * TOK + p0] = w0;
    int p1 = atomicAdd(&g_cnt[i1], 1);
    g_eidx[i1 * TOK + p1] = m; g_ew[i1 * TOK + p1] = w1;
}

// ---------------- host orchestration ----------------------------------------------
extern "C" void kernel_launch(void* const* d_in, const int* in_sizes, int n_in,
                              void* d_out, int out_size) {
    const float* x          = (const float*)d_in[0];
    const float* rot_cos    = (const float*)d_in[1];
    const float* rot_sin    = (const float*)d_in[2];
    const float* norm1_w    = (const float*)d_in[3];
    const float* norm2_w    = (const float*)d_in[4];
    const float* qkv_base   = (const float*)d_in[5];
    const float* qkv_spline = (const float*)d_in[6];
    const float* qkv_scaler = (const float*)d_in[7];
    const float* out_w      = (const float*)d_in[8];
    const float* out_b      = (const float*)d_in[9];
    const float* gate_w     = (const float*)d_in[10];
    const float* w1_base    = (const float*)d_in[11];
    const float* w1_spline  = (const float*)d_in[12];
    const float* w1_scaler  = (const float*)d_in[13];
    const float* w2_base    = (const float*)d_in[14];
    const float* w2_spline  = (const float*)d_in[15];
    const float* w2_scaler  = (const float*)d_in[16];
    const float* w3_base    = (const float*)d_in[17];
    const float* w3_spline  = (const float*)d_in[18];
    const float* w3_scaler  = (const float*)d_in[19];
    float* out = (float*)d_out;

    float *phi, *qkv, *ctx, *x2, *t1, *t2, *phit, *logits, *ew;
    int *cnt, *eidx;
    cudaGetSymbolAddress((void**)&phi,    g_phi);
    cudaGetSymbolAddress((void**)&qkv,    g_qkv);
    cudaGetSymbolAddress((void**)&ctx,    g_ctx);
    cudaGetSymbolAddress((void**)&x2,     g_x2);
    cudaGetSymbolAddress((void**)&t1,     g_t1);
    cudaGetSymbolAddress((void**)&t2,     g_t2);
    cudaGetSymbolAddress((void**)&phit,   g_phit);
    cudaGetSymbolAddress((void**)&logits, g_logits);
    cudaGetSymbolAddress((void**)&cnt,    g_cnt);
    cudaGetSymbolAddress((void**)&eidx,   g_eidx);
    cudaGetSymbolAddress((void**)&ew,     g_ew);

    const int fa_smem = (4 * FA_TILE + 64 * 20) * sizeof(float);
    cudaFuncSetAttribute(flash_attn_kernel, cudaFuncAttributeMaxDynamicSharedMemorySize, fa_smem);

    // 1) rmsnorm(x) -> phi(hn)
    rmsnorm_phi_kernel<<<TOK, 256>>>(x, norm1_w, phi, nullptr, nullptr);

    // 2) QKV = phi @ Waug^T (fused spline scaling)
    kan_gemm<0><<<dim3(3072 / 128, TOK / 128), 256>>>(
        phi, KAUG, nullptr, qkv_base, qkv_spline, qkv_scaler, HID, 0,
        qkv, 3072, TOK, 3072, KAUG, nullptr, nullptr, nullptr, nullptr, nullptr, nullptr);

    // 3) RoPE
    rope_kernel<<<(TOK * NHEAD * 32) / 256, 256>>>(qkv, rot_cos, rot_sin);

    // 4) attention (flash, no materialized scores)
    flash_attn_kernel<<<dim3(SEQ / 64, BATCH * NHEAD), 256, fa_smem>>>(qkv, ctx);

    // 5) x2 = x + ctx @ out_w^T + out_b  (also initializes d_out = x2)
    kan_gemm<1><<<dim3(HID / 128, TOK / 128), 256>>>(
        ctx, HID, nullptr, out_w, nullptr, nullptr, HID, HID,
        x2, HID, TOK, HID, HID, nullptr, x, out_b, out, nullptr, nullptr);

    // 6) rmsnorm(x2) -> phi(h2), gate logits
    rmsnorm_phi_kernel<<<TOK, 256>>>(x2, norm2_w, phi, gate_w, logits);

    // 7) routing (top-2 of 4, softmax weights)
    init_cnt_kernel<<<1, 32>>>();
    routing_kernel<<<TOK / 256, 256>>>();

    // 8) experts (sequential on stream; scratch reuse is safe)
    for (int e = 0; e < NEXP; e++) {
        const int* idx_e = eidx + e * TOK;
        const float* w_e = ew + e * TOK;
        kan_gemm<0><<<dim3(DFF / 128, TOK / 128), 256>>>(
            phi, KAUG, idx_e,
            w1_base + (size_t)e * DFF * HID, w1_spline + (size_t)e * DFF * HID * NB,
            w1_scaler + (size_t)e * DFF * HID, HID, 0,
            t1, DFF, TOK, DFF, KAUG, cnt + e, nullptr, nullptr, nullptr, nullptr, nullptr);
        kan_gemm<0><<<dim3(DFF / 128, TOK / 128), 256>>>(
            phi, KAUG, idx_e,
            w2_base + (size_t)e * DFF * HID, w2_spline + (size_t)e * DFF * HID * NB,
            w2_scaler + (size_t)e * DFF * HID, HID, 0,
            t2, DFF, TOK, DFF, KAUG, cnt + e, nullptr, nullptr, nullptr, nullptr, nullptr);
        mul_phi_kernel<<<TOK, 256>>>(t1, t2, phit, cnt + e);
        kan_gemm<2><<<dim3(HID / 128, TOK / 128), 256>>>(
            phit, 9 * DFF, nullptr,
            w3_base + (size_t)e * HID * DFF, w3_spline + (size_t)e * HID * DFF * NB,
            w3_scaler + (size_t)e * HID * DFF, DFF, 0,
            out, HID, TOK, HID, 9 * DFF, cnt + e, nullptr, nullptr, nullptr, idx_e, w_e);
    }
}

// round 5
// speedup vs baseline: 1.9701x; 1.9701x over previous
#include <cuda_runtime.h>
#include <cuda_bf16.h>
#include <math.h>

#define TOK   2048      // B*S
#define HID   1024
#define KAUG  9216      // H*(1+NB)
#define NB    8
#define NHEAD 16
#define HDIM  64
#define SEQ   1024
#define BATCH 2
#define DFF   1024
#define NEXP  4

// ---------------- scratch (static device globals; no runtime alloc) ----------------
__device__ float g_phi[(size_t)TOK * KAUG];          // phi(hn) then phi(h2)
__device__ float g_qkv[(size_t)TOK * 3 * HID];
__device__ float g_ctx[(size_t)TOK * HID];
__device__ float g_x2[(size_t)TOK * HID];
__device__ float g_t1[(size_t)TOK * DFF];
__device__ float g_t2[(size_t)TOK * DFF];
__device__ float g_phit[(size_t)TOK * 9 * DFF];
__device__ float g_logits[TOK * NEXP];
__device__ int   g_cnt[NEXP];
__device__ int   g_eidx[NEXP * TOK];
__device__ float g_ew[NEXP * TOK];

// ---------------- cubic B-spline bases, G=5, K=3, grid = i*0.4-1 for i in [-3,8] ----
__device__ __forceinline__ void bspline8(float v, float* out) {
    float b[11];
#pragma unroll
    for (int t = 0; t < 11; t++) {
        float g0 = 0.4f * (t - 3) - 1.0f;
        float g1 = 0.4f * (t - 2) - 1.0f;
        b[t] = (v >= g0 && v < g1) ? 1.0f : 0.0f;
    }
#pragma unroll
    for (int j = 1; j <= 3; j++) {
        float inv = 1.0f / (0.4f * (float)j);
#pragma unroll
        for (int t = 0; t < 10; t++) {
            if (t < 11 - j) {
                float gt   = 0.4f * (t - 3) - 1.0f;
                float gtj1 = 0.4f * (t + j - 2) - 1.0f;
                b[t] = (v - gt) * inv * b[t] + (gtj1 - v) * inv * b[t + 1];
            }
        }
    }
#pragma unroll
    for (int c = 0; c < 8; c++) out[c] = b[c];
}

// ---------------- rmsnorm + phi expansion (+ optional gate logits) ------------------
__global__ void rmsnorm_phi_kernel(const float* __restrict__ x,
                                   const float* __restrict__ w,
                                   float* __restrict__ phi,
                                   const float* __restrict__ gate_w,
                                   float* __restrict__ logits) {
    int m = blockIdx.x;
    int tid = threadIdx.x;
    __shared__ float sx[HID];
    __shared__ float sred[256];
    const float* xr = x + (size_t)m * HID;
    float ss = 0.f;
    for (int f = tid; f < HID; f += 256) { float v = xr[f]; sx[f] = v; ss += v * v; }
    sred[tid] = ss; __syncthreads();
    for (int o = 128; o > 0; o >>= 1) { if (tid < o) sred[tid] += sred[tid + o]; __syncthreads(); }
    float rms = rsqrtf(sred[0] / (float)HID + 1e-6f);
    float gacc[4] = {0.f, 0.f, 0.f, 0.f};
    float* phir = phi + (size_t)m * KAUG;
    for (int f = tid; f < HID; f += 256) {
        float hn = sx[f] * rms * w[f];
        phir[f] = hn / (1.0f + expf(-hn));     // silu
        float bs[8];
        bspline8(hn, bs);
#pragma unroll
        for (int c = 0; c < 8; c++) phir[HID + f * 8 + c] = bs[c];
        if (gate_w) {
#pragma unroll
            for (int e = 0; e < 4; e++) gacc[e] += hn * gate_w[e * HID + f];
        }
    }
    if (gate_w) {
#pragma unroll
        for (int e = 0; e < 4; e++) {
            __syncthreads();
            sred[tid] = gacc[e]; __syncthreads();
            for (int o = 128; o > 0; o >>= 1) { if (tid < o) sred[tid] += sred[tid + o]; __syncthreads(); }
            if (tid == 0) logits[m * 4 + e] = sred[0];
        }
    }
}

// ---------------- phi expansion of t = t1*t2 (expert hidden), compacted rows --------
__global__ void mul_phi_kernel(const float* __restrict__ t1, const float* __restrict__ t2,
                               float* __restrict__ phit, const int* __restrict__ cnt) {
    int r = blockIdx.x;
    if (r >= *cnt) return;
    int tid = threadIdx.x;
    const float* a = t1 + (size_t)r * DFF;
    const float* b = t2 + (size_t)r * DFF;
    float* pr = phit + (size_t)r * (9 * DFF);
    for (int f = tid; f < DFF; f += 256) {
        float v = a[f] * b[f];
        pr[f] = v / (1.0f + expf(-v));
        float bs[8];
        bspline8(v, bs);
#pragma unroll
        for (int c = 0; c < 8; c++) pr[DFF + f * 8 + c] = bs[c];
    }
}

// ---------------- bf16 split helpers ----------------------------------------------
__device__ __forceinline__ void split_pack(float x, float y, unsigned& hi, unsigned& lo) {
    __nv_bfloat16 xh = __float2bfloat16_rn(x);
    __nv_bfloat16 yh = __float2bfloat16_rn(y);
    float xr = x - __bfloat162float(xh);
    float yr = y - __bfloat162float(yh);
    __nv_bfloat162 h = __halves2bfloat162(xh, yh);           // low = x
    __nv_bfloat162 l = __floats2bfloat162_rn(xr, yr);
    hi = *reinterpret_cast<unsigned*>(&h);
    lo = *reinterpret_cast<unsigned*>(&l);
}

__device__ __forceinline__ void mma16816(float* c, unsigned a0, unsigned a1, unsigned a2,
                                         unsigned a3, unsigned b0, unsigned b1) {
    asm volatile(
        "mma.sync.aligned.m16n8k16.row.col.f32.bf16.bf16.f32 "
        "{%0,%1,%2,%3}, {%4,%5,%6,%7}, {%8,%9}, {%0,%1,%2,%3};\n"
        : "+f"(c[0]), "+f"(c[1]), "+f"(c[2]), "+f"(c[3])
        : "r"(a0), "r"(a1), "r"(a2), "r"(a3), "r"(b0), "r"(b1));
}

// ---------------- tensor-core fused-KAN GEMM: C[m,n] = sum_k A[m,k]*Waug[n,k] ------
// bf16 hi/lo split, 3 mma passes (hh, hl, lh) -> ~fp32 accuracy on tensor cores.
// EPI 0: plain store. EPI 1: +res+bias dual store. EPI 2: scatter-accum.
#define AW 9            // bf16x2 words per 16-k row (8) + 1 pad
template <int EPI>
__global__ void __launch_bounds__(256, 2)
kan_gemm_tc(const float* __restrict__ A, int lda, const int* __restrict__ a_idx,
            const float* __restrict__ Bbase, const float* __restrict__ Bspline,
            const float* __restrict__ Bscaler, int Kin, int ldb,
            float* __restrict__ C, int ldc,
            int M, int N, int K, const int* __restrict__ cnt,
            const float* __restrict__ res, const float* __restrict__ bias,
            float* __restrict__ C2,
            const int* __restrict__ out_idx, const float* __restrict__ out_w) {
    int Meff = cnt ? *cnt : M;
    int mBase = blockIdx.y * 128;
    int nBase = blockIdx.x * 128;
    if (mBase >= Meff) return;

    __shared__ unsigned AsH[2][128 * AW], AsL[2][128 * AW];
    __shared__ unsigned BsH[2][128 * AW], BsL[2][128 * AW];

    int tid = threadIdx.x;
    int lrow = tid >> 1;              // 0..127
    int lko  = (tid & 1) * 8;         // k offset 0 or 8 within 16-chunk
    int lw0  = lko >> 1;              // word offset 0 or 4

    int arow = mBase + lrow;
    bool avalid = arow < Meff;
    int arow_g = avalid ? (a_idx ? a_idx[arow] : arow) : 0;
    const float* aptr = A + (size_t)arow_g * lda + lko;
    int nrow = nBase + lrow;

    int w = tid >> 5, l = tid & 31;
    int wm = (w >> 2) * 64;
    int wn = (w & 3) * 32;
    int lq = l >> 2;                  // lane/4
    int lr = l & 3;                   // lane%4

    float acc[4][4][4];
#pragma unroll
    for (int mf = 0; mf < 4; mf++)
#pragma unroll
        for (int nf = 0; nf < 4; nf++)
#pragma unroll
            for (int t = 0; t < 4; t++) acc[mf][nf][t] = 0.f;

    float a8[8], b8[8];
    // ---- load chunk k0 into regs ----
    auto load_chunk = [&](int k0) {
        if (avalid) {
            float4 t0 = *(const float4*)(aptr + k0);
            float4 t1 = *(const float4*)(aptr + k0 + 4);
            a8[0] = t0.x; a8[1] = t0.y; a8[2] = t0.z; a8[3] = t0.w;
            a8[4] = t1.x; a8[5] = t1.y; a8[6] = t1.z; a8[7] = t1.w;
        } else {
#pragma unroll
            for (int i = 0; i < 8; i++) a8[i] = 0.f;
        }
        int kg = k0 + lko;
        float4 u0, u1;
        if (Bspline) {
            if (kg < Kin) {
                u0 = *(const float4*)(Bbase + (size_t)nrow * Kin + kg);
                u1 = *(const float4*)(Bbase + (size_t)nrow * Kin + kg + 4);
            } else {
                int ko = kg - Kin;
                u0 = *(const float4*)(Bspline + (size_t)nrow * (Kin * 8) + ko);
                u1 = *(const float4*)(Bspline + (size_t)nrow * (Kin * 8) + ko + 4);
                float sc = Bscaler[(size_t)nrow * Kin + (ko >> 3)];
                u0.x *= sc; u0.y *= sc; u0.z *= sc; u0.w *= sc;
                u1.x *= sc; u1.y *= sc; u1.z *= sc; u1.w *= sc;
            }
        } else {
            u0 = *(const float4*)(Bbase + (size_t)nrow * ldb + kg);
            u1 = *(const float4*)(Bbase + (size_t)nrow * ldb + kg + 4);
        }
        b8[0] = u0.x; b8[1] = u0.y; b8[2] = u0.z; b8[3] = u0.w;
        b8[4] = u1.x; b8[5] = u1.y; b8[6] = u1.z; b8[7] = u1.w;
    };
    auto store_chunk = [&](int buf) {
        unsigned* dAH = &AsH[buf][lrow * AW + lw0];
        unsigned* dAL = &AsL[buf][lrow * AW + lw0];
        unsigned* dBH = &BsH[buf][lrow * AW + lw0];
        unsigned* dBL = &BsL[buf][lrow * AW + lw0];
#pragma unroll
        for (int t = 0; t < 4; t++) {
            unsigned hi, lo;
            split_pack(a8[2 * t], a8[2 * t + 1], hi, lo);
            dAH[t] = hi; dAL[t] = lo;
            split_pack(b8[2 * t], b8[2 * t + 1], hi, lo);
            dBH[t] = hi; dBL[t] = lo;
        }
    };

    load_chunk(0);
    store_chunk(0);
    __syncthreads();

    int nChunks = K / 16;
    for (int kt = 0; kt < nChunks; kt++) {
        int cur = kt & 1;
        if (kt + 1 < nChunks) load_chunk((kt + 1) * 16);

        // 3 passes: (Ah,Bh), (Ah,Bl), (Al,Bh)
#pragma unroll
        for (int p = 0; p < 3; p++) {
            const unsigned* Awp = (p == 2) ? &AsL[cur][0] : &AsH[cur][0];
            const unsigned* Bwp = (p == 1) ? &BsL[cur][0] : &BsH[cur][0];
            unsigned bb[4][2];
#pragma unroll
            for (int nf = 0; nf < 4; nf++) {
                int col = wn + nf * 8 + lq;
                bb[nf][0] = Bwp[col * AW + lr];
                bb[nf][1] = Bwp[col * AW + lr + 4];
            }
#pragma unroll
            for (int mf = 0; mf < 4; mf++) {
                int row = wm + mf * 16 + lq;
                unsigned a0 = Awp[row * AW + lr];
                unsigned a1 = Awp[(row + 8) * AW + lr];
                unsigned a2 = Awp[row * AW + lr + 4];
                unsigned a3 = Awp[(row + 8) * AW + lr + 4];
#pragma unroll
                for (int nf = 0; nf < 4; nf++)
                    mma16816(acc[mf][nf], a0, a1, a2, a3, bb[nf][0], bb[nf][1]);
            }
        }

        if (kt + 1 < nChunks) store_chunk(cur ^ 1);
        __syncthreads();
    }

    // ---- epilogue ----
#pragma unroll
    for (int mf = 0; mf < 4; mf++) {
#pragma unroll
        for (int nf = 0; nf < 4; nf++) {
            float* c = acc[mf][nf];
            int r0 = mBase + wm + mf * 16 + lq;
            int c0 = nBase + wn + nf * 8 + 2 * lr;
#pragma unroll
            for (int half = 0; half < 2; half++) {
                int r = r0 + half * 8;
                if (r >= Meff) continue;
                float v0 = c[half * 2 + 0], v1 = c[half * 2 + 1];
                if (EPI == 0) {
                    C[(size_t)r * ldc + c0] = v0;
                    C[(size_t)r * ldc + c0 + 1] = v1;
                } else if (EPI == 1) {
                    float o0 = v0 + res[(size_t)r * ldc + c0] + bias[c0];
                    float o1 = v1 + res[(size_t)r * ldc + c0 + 1] + bias[c0 + 1];
                    C[(size_t)r * ldc + c0] = o0;  C2[(size_t)r * ldc + c0] = o0;
                    C[(size_t)r * ldc + c0 + 1] = o1; C2[(size_t)r * ldc + c0 + 1] = o1;
                } else {
                    int tok = out_idx[r];
                    float wgt = out_w[r];
                    C[(size_t)tok * ldc + c0] += wgt * v0;
                    C[(size_t)tok * ldc + c0 + 1] += wgt * v1;
                }
            }
        }
    }
}

// ---------------- RoPE on q,k in-place -------------------------------------------
__global__ void rope_kernel(float* __restrict__ qkv, const float* __restrict__ rc,
                            const float* __restrict__ rs) {
    int idx = blockIdx.x * 256 + threadIdx.x;
    if (idx >= TOK * NHEAD * 32) return;
    int d2 = idx & 31;
    int nh = (idx >> 5) & 15;
    int m = idx >> 9;
    int s = m & (SEQ - 1);
    float c = rc[s * 32 + d2], sn = rs[s * 32 + d2];
    float* p = qkv + (size_t)m * 3072 + nh * 192 + 2 * d2;
    float re = p[0], im = p[1];
    p[0] = re * c - im * sn; p[1] = re * sn + im * c;
    float* pk = p + 64;
    re = pk[0]; im = pk[1];
    pk[0] = re * c - im * sn; pk[1] = re * sn + im * c;
}

// ---------------- flash attention: 64-q-tile per CTA, streaming softmax -----------
#define FA_STRIDE 68
#define FA_TILE   (64 * FA_STRIDE)
__global__ void flash_attn_kernel(const float* __restrict__ qkv, float* __restrict__ ctx) {
    extern __shared__ float smem[];
    float* Qs   = smem;                 // [d][q]
    float* Ks   = Qs + FA_TILE;         // [d][k]
    float* Ss   = Ks + FA_TILE;         // [q][k]  (P tile)
    float* Vs   = Ss + FA_TILE;         // [k][d]
    float* Pred = Vs + FA_TILE;         // [q][16] partial reductions, stride 20

    int qt = blockIdx.x, bh = blockIdx.y;
    int b = bh >> 4, h = bh & 15;
    int tid = threadIdx.x;
    int r  = tid >> 2;
    int c4 = (tid & 3) * 16;
    int q0 = (tid >> 4) * 4;
    int kc0 = (tid & 15) * 4;
    int pcol = tid & 15;

    const float* qbase = qkv + (size_t)(b * SEQ + qt * 64 + r) * 3072 + h * 192;
#pragma unroll
    for (int u = 0; u < 4; u++) {
        float4 qv = *(const float4*)(qbase + c4 + u * 4);
        Qs[(c4 + u * 4 + 0) * FA_STRIDE + r] = qv.x;
        Qs[(c4 + u * 4 + 1) * FA_STRIDE + r] = qv.y;
        Qs[(c4 + u * 4 + 2) * FA_STRIDE + r] = qv.z;
        Qs[(c4 + u * 4 + 3) * FA_STRIDE + r] = qv.w;
    }

    float o[4][4];
    float m_i[4], l_i[4];
#pragma unroll
    for (int i = 0; i < 4; i++) {
        m_i[i] = -1e30f; l_i[i] = 0.f;
#pragma unroll
        for (int j = 0; j < 4; j++) o[i][j] = 0.f;
    }

    for (int kt = 0; kt < SEQ / 64; kt++) {
        __syncthreads();
        const float* kbase = qkv + (size_t)(b * SEQ + kt * 64 + r) * 3072 + h * 192 + 64;
        const float* vbase = kbase + 64;
#pragma unroll
        for (int u = 0; u < 4; u++) {
            float4 kv = *(const float4*)(kbase + c4 + u * 4);
            Ks[(c4 + u * 4 + 0) * FA_STRIDE + r] = kv.x;
            Ks[(c4 + u * 4 + 1) * FA_STRIDE + r] = kv.y;
            Ks[(c4 + u * 4 + 2) * FA_STRIDE + r] = kv.z;
            Ks[(c4 + u * 4 + 3) * FA_STRIDE + r] = kv.w;
            *(float4*)&Vs[r * FA_STRIDE + c4 + u * 4] = *(const float4*)(vbase + c4 + u * 4);
        }
        __syncthreads();

        float s[4][4];
#pragma unroll
        for (int i = 0; i < 4; i++)
#pragma unroll
            for (int j = 0; j < 4; j++) s[i][j] = 0.f;
#pragma unroll 8
        for (int d = 0; d < 64; d++) {
            float a0[4], b0[4];
            *(float4*)a0 = *(const float4*)&Qs[d * FA_STRIDE + q0];
            *(float4*)b0 = *(const float4*)&Ks[d * FA_STRIDE + kc0];
#pragma unroll
            for (int i = 0; i < 4; i++)
#pragma unroll
                for (int j = 0; j < 4; j++) s[i][j] += a0[i] * b0[j];
        }
#pragma unroll
        for (int i = 0; i < 4; i++)
#pragma unroll
            for (int j = 0; j < 4; j++) s[i][j] *= 0.125f;

#pragma unroll
        for (int i = 0; i < 4; i++) {
            float pm = fmaxf(fmaxf(s[i][0], s[i][1]), fmaxf(s[i][2], s[i][3]));
            Pred[(q0 + i) * 20 + pcol] = pm;
        }
        __syncthreads();
        float mnew[4], corr[4];
#pragma unroll
        for (int i = 0; i < 4; i++) {
            float mx = m_i[i];
            const float* pr = &Pred[(q0 + i) * 20];
#pragma unroll
            for (int t = 0; t < 16; t++) mx = fmaxf(mx, pr[t]);
            mnew[i] = mx;
            corr[i] = expf(m_i[i] - mx);
            m_i[i] = mx;
        }
        __syncthreads();

#pragma unroll
        for (int i = 0; i < 4; i++) {
            float ps = 0.f;
#pragma unroll
            for (int j = 0; j < 4; j++) {
                float p = expf(s[i][j] - mnew[i]);
                Ss[(q0 + i) * FA_STRIDE + kc0 + j] = p;
                ps += p;
            }
            Pred[(q0 + i) * 20 + pcol] = ps;
        }
        __syncthreads();

#pragma unroll
        for (int i = 0; i < 4; i++) {
            float rs = 0.f;
            const float* pr = &Pred[(q0 + i) * 20];
#pragma unroll
            for (int t = 0; t < 16; t++) rs += pr[t];
            l_i[i] = corr[i] * l_i[i] + rs;
#pragma unroll
            for (int j = 0; j < 4; j++) o[i][j] *= corr[i];
        }

#pragma unroll 8
        for (int kk = 0; kk < 64; kk++) {
            float a0[4], b0[4];
            a0[0] = Ss[(q0 + 0) * FA_STRIDE + kk];
            a0[1] = Ss[(q0 + 1) * FA_STRIDE + kk];
            a0[2] = Ss[(q0 + 2) * FA_STRIDE + kk];
            a0[3] = Ss[(q0 + 3) * FA_STRIDE + kk];
            *(float4*)b0 = *(const float4*)&Vs[kk * FA_STRIDE + kc0];
#pragma unroll
            for (int i = 0; i < 4; i++)
#pragma unroll
                for (int j = 0; j < 4; j++) o[i][j] += a0[i] * b0[j];
        }
    }

#pragma unroll
    for (int i = 0; i < 4; i++) {
        float inv = 1.0f / l_i[i];
#pragma unroll
        for (int j = 0; j < 4; j++)
            ctx[(size_t)(b * SEQ + qt * 64 + q0 + i) * HID + h * 64 + kc0 + j] = o[i][j] * inv;
    }
}

// ---------------- MoE routing -----------------------------------------------------
__global__ void init_cnt_kernel() {
    if (threadIdx.x < NEXP) g_cnt[threadIdx.x] = 0;
}

__global__ void routing_kernel() {
    int m = blockIdx.x * 256 + threadIdx.x;
    if (m >= TOK) return;
    float l[4];
#pragma unroll
    for (int e = 0; e < 4; e++) l[e] = g_logits[m * 4 + e];
    int i0 = 0; float b0 = l[0];
#pragma unroll
    for (int e = 1; e < 4; e++) if (l[e] > b0) { b0 = l[e]; i0 = e; }
    int i1 = -1; float b1 = -1e30f;
#pragma unroll
    for (int e = 0; e < 4; e++) if (e != i0 && l[e] > b1) { b1 = l[e]; i1 = e; }
    float t = expf(b1 - b0);
    float w0 = 1.0f / (1.0f + t);
    float w1 = t / (1.0f + t);
    int p0 = atomicAdd(&g_cnt[i0], 1);
    g_eidx[i0 * TOK + p0] = m; g_ew[i0 * TOK + p0] = w0;
    int p1 = atomicAdd(&g_cnt[i1], 1);
    g_eidx[i1 * TOK + p1] = m; g_ew[i1 * TOK + p1] = w1;
}

// ---------------- host orchestration ----------------------------------------------
extern "C" void kernel_launch(void* const* d_in, const int* in_sizes, int n_in,
                              void* d_out, int out_size) {
    const float* x          = (const float*)d_in[0];
    const float* rot_cos    = (const float*)d_in[1];
    const float* rot_sin    = (const float*)d_in[2];
    const float* norm1_w    = (const float*)d_in[3];
    const float* norm2_w    = (const float*)d_in[4];
    const float* qkv_base   = (const float*)d_in[5];
    const float* qkv_spline = (const float*)d_in[6];
    const float* qkv_scaler = (const float*)d_in[7];
    const float* out_w      = (const float*)d_in[8];
    const float* out_b      = (const float*)d_in[9];
    const float* gate_w     = (const float*)d_in[10];
    const float* w1_base    = (const float*)d_in[11];
    const float* w1_spline  = (const float*)d_in[12];
    const float* w1_scaler  = (const float*)d_in[13];
    const float* w2_base    = (const float*)d_in[14];
    const float* w2_spline  = (const float*)d_in[15];
    const float* w2_scaler  = (const float*)d_in[16];
    const float* w3_base    = (const float*)d_in[17];
    const float* w3_spline  = (const float*)d_in[18];
    const float* w3_scaler  = (const float*)d_in[19];
    float* out = (float*)d_out;

    float *phi, *qkv, *ctx, *x2, *t1, *t2, *phit, *logits, *ew;
    int *cnt, *eidx;
    cudaGetSymbolAddress((void**)&phi,    g_phi);
    cudaGetSymbolAddress((void**)&qkv,    g_qkv);
    cudaGetSymbolAddress((void**)&ctx,    g_ctx);
    cudaGetSymbolAddress((void**)&x2,     g_x2);
    cudaGetSymbolAddress((void**)&t1,     g_t1);
    cudaGetSymbolAddress((void**)&t2,     g_t2);
    cudaGetSymbolAddress((void**)&phit,   g_phit);
    cudaGetSymbolAddress((void**)&logits, g_logits);
    cudaGetSymbolAddress((void**)&cnt,    g_cnt);
    cudaGetSymbolAddress((void**)&eidx,   g_eidx);
    cudaGetSymbolAddress((void**)&ew,     g_ew);

    const int fa_smem = (4 * FA_TILE + 64 * 20) * sizeof(float);
    cudaFuncSetAttribute(flash_attn_kernel, cudaFuncAttributeMaxDynamicSharedMemorySize, fa_smem);

    // 1) rmsnorm(x) -> phi(hn)
    rmsnorm_phi_kernel<<<TOK, 256>>>(x, norm1_w, phi, nullptr, nullptr);

    // 2) QKV = phi @ Waug^T (fused spline scaling)
    kan_gemm_tc<0><<<dim3(3072 / 128, TOK / 128), 256>>>(
        phi, KAUG, nullptr, qkv_base, qkv_spline, qkv_scaler, HID, 0,
        qkv, 3072, TOK, 3072, KAUG, nullptr, nullptr, nullptr, nullptr, nullptr, nullptr);

    // 3) RoPE
    rope_kernel<<<(TOK * NHEAD * 32) / 256, 256>>>(qkv, rot_cos, rot_sin);

    // 4) attention (flash, no materialized scores)
    flash_attn_kernel<<<dim3(SEQ / 64, BATCH * NHEAD), 256, fa_smem>>>(qkv, ctx);

    // 5) x2 = x + ctx @ out_w^T + out_b  (also initializes d_out = x2)
    kan_gemm_tc<1><<<dim3(HID / 128, TOK / 128), 256>>>(
        ctx, HID, nullptr, out_w, nullptr, nullptr, HID, HID,
        x2, HID, TOK, HID, HID, nullptr, x, out_b, out, nullptr, nullptr);

    // 6) rmsnorm(x2) -> phi(h2), gate logits
    rmsnorm_phi_kernel<<<TOK, 256>>>(x2, norm2_w, phi, gate_w, logits);

    // 7) routing (top-2 of 4, softmax weights)
    init_cnt_kernel<<<1, 32>>>();
    routing_kernel<<<TOK / 256, 256>>>();

    // 8) experts (sequential on stream; scratch reuse is safe)
    for (int e = 0; e < NEXP; e++) {
        const int* idx_e = eidx + e * TOK;
        const float* w_e = ew + e * TOK;
        kan_gemm_tc<0><<<dim3(DFF / 128, TOK / 128), 256>>>(
            phi, KAUG, idx_e,
            w1_base + (size_t)e * DFF * HID, w1_spline + (size_t)e * DFF * HID * NB,
            w1_scaler + (size_t)e * DFF * HID, HID, 0,
            t1, DFF, TOK, DFF, KAUG, cnt + e, nullptr, nullptr, nullptr, nullptr, nullptr);
        kan_gemm_tc<0><<<dim3(DFF / 128, TOK / 128), 256>>>(
            phi, KAUG, idx_e,
            w2_base + (size_t)e * DFF * HID, w2_spline + (size_t)e * DFF * HID * NB,
            w2_scaler + (size_t)e * DFF * HID, HID, 0,
            t2, DFF, TOK, DFF, KAUG, cnt + e, nullptr, nullptr, nullptr, nullptr, nullptr);
        mul_phi_kernel<<<TOK, 256>>>(t1, t2, phit, cnt + e);
        kan_gemm_tc<2><<<dim3(HID / 128, TOK / 128), 256>>>(
            phit, 9 * DFF, nullptr,
            w3_base + (size_t)e * HID * DFF, w3_spline + (size_t)e * HID * DFF * NB,
            w3_scaler + (size_t)e * HID * DFF, DFF, 0,
            out, HID, TOK, HID, 9 * DFF, cnt + e, nullptr, nullptr, nullptr, idx_e, w_e);
    }
}

// round 7
// speedup vs baseline: 3.5307x; 1.7921x over previous
#include <cuda_runtime.h>
#include <cuda_bf16.h>
#include <math.h>
#include <stdint.h>

#define TOK   2048      // B*S
#define HID   1024
#define KAUG  9216      // H*(1+NB)
#define NB    8
#define NHEAD 16
#define HDIM  64
#define SEQ   1024
#define BATCH 2
#define DFF   1024
#define NEXP  4

// ---------------- scratch (static device globals; no runtime alloc) ----------------
__device__ __align__(16) __nv_bfloat16 g_phiH[(size_t)TOK * KAUG];
__device__ __align__(16) __nv_bfloat16 g_phiL[(size_t)TOK * KAUG];
__device__ __align__(16) __nv_bfloat16 g_phitH[(size_t)TOK * KAUG];
__device__ __align__(16) __nv_bfloat16 g_phitL[(size_t)TOK * KAUG];
__device__ __align__(16) __nv_bfloat16 g_ctxH[(size_t)TOK * HID];
__device__ __align__(16) __nv_bfloat16 g_ctxL[(size_t)TOK * HID];
__device__ __align__(16) __nv_bfloat16 g_qkvwH[(size_t)3072 * KAUG];
__device__ __align__(16) __nv_bfloat16 g_qkvwL[(size_t)3072 * KAUG];
__device__ __align__(16) __nv_bfloat16 g_w1H[(size_t)NEXP * DFF * KAUG];
__device__ __align__(16) __nv_bfloat16 g_w1L[(size_t)NEXP * DFF * KAUG];
__device__ __align__(16) __nv_bfloat16 g_w2H[(size_t)NEXP * DFF * KAUG];
__device__ __align__(16) __nv_bfloat16 g_w2L[(size_t)NEXP * DFF * KAUG];
__device__ __align__(16) __nv_bfloat16 g_w3H[(size_t)NEXP * HID * KAUG];
__device__ __align__(16) __nv_bfloat16 g_w3L[(size_t)NEXP * HID * KAUG];
__device__ __align__(16) __nv_bfloat16 g_owH[(size_t)HID * HID];
__device__ __align__(16) __nv_bfloat16 g_owL[(size_t)HID * HID];

__device__ float g_qkv[(size_t)TOK * 3 * HID];
__device__ float g_x2[(size_t)TOK * HID];
__device__ float g_t1[(size_t)TOK * DFF];
__device__ float g_t2[(size_t)TOK * DFF];
__device__ float g_logits[TOK * NEXP];
__device__ int   g_cnt[NEXP];
__device__ int   g_eidx[NEXP * TOK];
__device__ float g_ew[NEXP * TOK];

// ---------------- helpers ----------------------------------------------------------
__device__ __forceinline__ uint32_t smem_u32(const void* p) {
    uint32_t a;
    asm("{ .reg .u64 t; cvta.to.shared.u64 t, %1; cvt.u32.u64 %0, t; }" : "=r"(a) : "l"(p));
    return a;
}

__device__ __forceinline__ void hl_pair(float v, __nv_bfloat16& h, __nv_bfloat16& l) {
    h = __float2bfloat16_rn(v);
    l = __float2bfloat16_rn(v - __bfloat162float(h));
}

__device__ __forceinline__ void mma16816(float* c, uint32_t a0, uint32_t a1, uint32_t a2,
                                         uint32_t a3, uint32_t b0, uint32_t b1) {
    asm volatile(
        "mma.sync.aligned.m16n8k16.row.col.f32.bf16.bf16.f32 "
        "{%0,%1,%2,%3}, {%4,%5,%6,%7}, {%8,%9}, {%0,%1,%2,%3};\n"
        : "+f"(c[0]), "+f"(c[1]), "+f"(c[2]), "+f"(c[3])
        : "r"(a0), "r"(a1), "r"(a2), "r"(a3), "r"(b0), "r"(b1));
}

#define LDSM_X4(r0, r1, r2, r3, addr) \
    asm volatile("ldmatrix.sync.aligned.m8n8.x4.shared.b16 {%0,%1,%2,%3}, [%4];" \
                 : "=r"(r0), "=r"(r1), "=r"(r2), "=r"(r3) : "r"(addr))

// ---------------- cubic B-spline bases --------------------------------------------
__device__ __forceinline__ void bspline8(float v, float* out) {
    float b[11];
#pragma unroll
    for (int t = 0; t < 11; t++) {
        float g0 = 0.4f * (t - 3) - 1.0f;
        float g1 = 0.4f * (t - 2) - 1.0f;
        b[t] = (v >= g0 && v < g1) ? 1.0f : 0.0f;
    }
#pragma unroll
    for (int j = 1; j <= 3; j++) {
        float inv = 1.0f / (0.4f * (float)j);
#pragma unroll
        for (int t = 0; t < 10; t++) {
            if (t < 11 - j) {
                float gt   = 0.4f * (t - 3) - 1.0f;
                float gtj1 = 0.4f * (t + j - 2) - 1.0f;
                b[t] = (v - gt) * inv * b[t] + (gtj1 - v) * inv * b[t + 1];
            }
        }
    }
#pragma unroll
    for (int c = 0; c < 8; c++) out[c] = b[c];
}

// ---------------- weight conversion (Waug -> bf16 hi/lo, scaler folded) ------------
__global__ void conv_kan_w(const float* __restrict__ base, const float* __restrict__ spline,
                           const float* __restrict__ scaler, int Kin,
                           __nv_bfloat16* __restrict__ WH, __nv_bfloat16* __restrict__ WL) {
    int o = blockIdx.x;
    int KA = Kin * 9;
    const float* brow = base + (size_t)o * Kin;
    const float* srow = spline + (size_t)o * Kin * 8;
    const float* crow = scaler + (size_t)o * Kin;
    __nv_bfloat16* hrow = WH + (size_t)o * KA;
    __nv_bfloat16* lrow = WL + (size_t)o * KA;
    for (int c = threadIdx.x; c < Kin; c += 256) {
        __nv_bfloat16 h, l;
        hl_pair(brow[c], h, l);
        hrow[c] = h; lrow[c] = l;
    }
    for (int c = threadIdx.x; c < Kin * 8; c += 256) {
        __nv_bfloat16 h, l;
        hl_pair(srow[c] * crow[c >> 3], h, l);
        hrow[Kin + c] = h; lrow[Kin + c] = l;
    }
}

__global__ void conv_plain(const float* __restrict__ W,
                           __nv_bfloat16* __restrict__ WH, __nv_bfloat16* __restrict__ WL,
                           int total) {
    int i = blockIdx.x * 256 + threadIdx.x;
    if (i < total) {
        __nv_bfloat16 h, l;
        hl_pair(W[i], h, l);
        WH[i] = h; WL[i] = l;
    }
}

// ---------------- rmsnorm + phi (bf16 hi/lo) + optional gate logits ----------------
__global__ void rmsnorm_phi_kernel(const float* __restrict__ x,
                                   const float* __restrict__ w,
                                   __nv_bfloat16* __restrict__ phiH,
                                   __nv_bfloat16* __restrict__ phiL,
                                   const float* __restrict__ gate_w,
                                   float* __restrict__ logits) {
    int m = blockIdx.x;
    int tid = threadIdx.x;
    __shared__ float sx[HID];
    __shared__ float sred[256];
    const float* xr = x + (size_t)m * HID;
    float ss = 0.f;
    for (int f = tid; f < HID; f += 256) { float v = xr[f]; sx[f] = v; ss += v * v; }
    sred[tid] = ss; __syncthreads();
    for (int o = 128; o > 0; o >>= 1) { if (tid < o) sred[tid] += sred[tid + o]; __syncthreads(); }
    float rms = rsqrtf(sred[0] / (float)HID + 1e-6f);
    float gacc[4] = {0.f, 0.f, 0.f, 0.f};
    __nv_bfloat16* ph = phiH + (size_t)m * KAUG;
    __nv_bfloat16* pl = phiL + (size_t)m * KAUG;
    for (int f = tid; f < HID; f += 256) {
        float hn = sx[f] * rms * w[f];
        __nv_bfloat16 h, l;
        hl_pair(hn / (1.0f + expf(-hn)), h, l);
        ph[f] = h; pl[f] = l;
        float bs[8];
        bspline8(hn, bs);
#pragma unroll
        for (int c = 0; c < 8; c++) {
            hl_pair(bs[c], h, l);
            ph[HID + f * 8 + c] = h; pl[HID + f * 8 + c] = l;
        }
        if (gate_w) {
#pragma unroll
            for (int e = 0; e < 4; e++) gacc[e] += hn * gate_w[e * HID + f];
        }
    }
    if (gate_w) {
#pragma unroll
        for (int e = 0; e < 4; e++) {
            __syncthreads();
            sred[tid] = gacc[e]; __syncthreads();
            for (int o = 128; o > 0; o >>= 1) { if (tid < o) sred[tid] += sred[tid + o]; __syncthreads(); }
            if (tid == 0) logits[m * 4 + e] = sred[0];
        }
    }
}

// ---------------- phi expansion of t1*t2 (bf16 hi/lo) ------------------------------
__global__ void mul_phi_kernel(const float* __restrict__ t1, const float* __restrict__ t2,
                               __nv_bfloat16* __restrict__ phitH,
                               __nv_bfloat16* __restrict__ phitL,
                               const int* __restrict__ cnt) {
    int r = blockIdx.x;
    if (r >= *cnt) return;
    int tid = threadIdx.x;
    const float* a = t1 + (size_t)r * DFF;
    const float* b = t2 + (size_t)r * DFF;
    __nv_bfloat16* ph = phitH + (size_t)r * KAUG;
    __nv_bfloat16* pl = phitL + (size_t)r * KAUG;
    for (int f = tid; f < DFF; f += 256) {
        float v = a[f] * b[f];
        __nv_bfloat16 h, l;
        hl_pair(v / (1.0f + expf(-v)), h, l);
        ph[f] = h; pl[f] = l;
        float bs[8];
        bspline8(v, bs);
#pragma unroll
        for (int c = 0; c < 8; c++) {
            hl_pair(bs[c], h, l);
            ph[DFF + f * 8 + c] = h; pl[DFF + f * 8 + c] = l;
        }
    }
}

// ---------------- bf16 tensor-core GEMM: C[m,n] = sum_k A[m,k]*B[n,k] --------------
// A,B pre-split into hi/lo bf16; 3 mma passes (AhBh + AhBl + AlBh) ~ fp32 accuracy.
// EPI 0: plain store. EPI 1: +res+bias dual store. EPI 2: scatter-accum.
#define PITCH  80                      // bytes per k32 row (64B data + 16B pad)
#define TILEB  (128 * PITCH)           // 10240
#define STAGE  (4 * TILEB)             // AH AL BH BL
#define GM_DYN (512 + 2 * STAGE)

template <int EPI>
__global__ void __launch_bounds__(256, 2)
kan_gemm_bf(const __nv_bfloat16* __restrict__ AH, const __nv_bfloat16* __restrict__ AL,
            int lda, const int* __restrict__ a_idx,
            const __nv_bfloat16* __restrict__ BH, const __nv_bfloat16* __restrict__ BL,
            int ldb,
            float* __restrict__ C, int ldc, int M, int N, int K,
            const int* __restrict__ cnt,
            const float* __restrict__ res, const float* __restrict__ bias,
            float* __restrict__ C2,
            const int* __restrict__ out_idx, const float* __restrict__ out_wt) {
    int Meff = cnt ? *cnt : M;
    int mBase = blockIdx.y * 128;
    int nBase = blockIdx.x * 128;
    if (mBase >= Meff) return;

    extern __shared__ char sm[];
    int* rowmap = (int*)sm;
    uint32_t bufs_u = smem_u32(sm + 512);
    int tid = threadIdx.x;

    if (tid < 128) {
        int r = mBase + tid;
        int g = (r < Meff) ? r : mBase;
        rowmap[tid] = a_idx ? a_idx[g] : g;
    }
    __syncthreads();

    int w = tid >> 5, l = tid & 31;
    int wm = (w >> 2) * 64;
    int wn = (w & 3) * 32;
    int lq = l >> 2, lr = l & 3;
    uint32_t aOff = (uint32_t)(wm + (l & 15)) * PITCH + ((l >> 4) ? 16u : 0u);
    uint32_t bOff = (uint32_t)(wn + (l & 7) + ((l & 16) ? 8 : 0)) * PITCH + ((l & 8) ? 16u : 0u);

    float acc[4][4][4];
#pragma unroll
    for (int mf = 0; mf < 4; mf++)
#pragma unroll
        for (int nf = 0; nf < 4; nf++)
#pragma unroll
            for (int t = 0; t < 4; t++) acc[mf][nf][t] = 0.f;

    auto issue = [&](int s, int k0) {
#pragma unroll
        for (int it = 0; it < 8; it++) {
            int i = it * 256 + tid;
            int tens = i >> 9;
            int rem = i & 511;
            int row = rem >> 2;
            int seg = rem & 3;
            const __nv_bfloat16* src;
            if (tens < 2) {
                src = (tens == 0 ? AH : AL) + (size_t)rowmap[row] * lda + k0 + 8 * seg;
            } else {
                src = (tens == 2 ? BH : BL) + (size_t)(nBase + row) * ldb + k0 + 8 * seg;
            }
            uint32_t dst = bufs_u + (uint32_t)s * STAGE + (uint32_t)tens * TILEB +
                           (uint32_t)row * PITCH + (uint32_t)seg * 16;
            asm volatile("cp.async.cg.shared.global [%0], [%1], 16;" :: "r"(dst), "l"(src) : "memory");
        }
        asm volatile("cp.async.commit_group;" ::: "memory");
    };

    int nStages = K / 32;
    issue(0, 0);
    for (int ck = 0; ck < nStages; ck++) {
        if (ck) __syncthreads();                   // everyone done reading buf (ck-1)&1
        bool pre = (ck + 1 < nStages);
        if (pre) issue((ck + 1) & 1, (ck + 1) * 32);
        if (pre) asm volatile("cp.async.wait_group 1;" ::: "memory");
        else     asm volatile("cp.async.wait_group 0;" ::: "memory");
        __syncthreads();

        uint32_t base = bufs_u + (uint32_t)(ck & 1) * STAGE;
#pragma unroll
        for (int p = 0; p < 2; p++) {
            uint32_t koff = 32u * p;
            uint32_t bH[4][2], bL[4][2], af[4][4];
#pragma unroll
            for (int nh = 0; nh < 2; nh++) {
                uint32_t r0, r1, r2, r3;
                LDSM_X4(r0, r1, r2, r3, base + 2 * TILEB + bOff + nh * 16 * PITCH + koff);
                bH[2 * nh][0] = r0; bH[2 * nh][1] = r1; bH[2 * nh + 1][0] = r2; bH[2 * nh + 1][1] = r3;
                LDSM_X4(r0, r1, r2, r3, base + 3 * TILEB + bOff + nh * 16 * PITCH + koff);
                bL[2 * nh][0] = r0; bL[2 * nh][1] = r1; bL[2 * nh + 1][0] = r2; bL[2 * nh + 1][1] = r3;
            }
#pragma unroll
            for (int mf = 0; mf < 4; mf++)
                LDSM_X4(af[mf][0], af[mf][1], af[mf][2], af[mf][3],
                        base + 0 * TILEB + aOff + mf * 16 * PITCH + koff);
#pragma unroll
            for (int mf = 0; mf < 4; mf++)
#pragma unroll
                for (int nf = 0; nf < 4; nf++)
                    mma16816(acc[mf][nf], af[mf][0], af[mf][1], af[mf][2], af[mf][3],
                             bH[nf][0], bH[nf][1]);
#pragma unroll
            for (int mf = 0; mf < 4; mf++)
#pragma unroll
                for (int nf = 0; nf < 4; nf++)
                    mma16816(acc[mf][nf], af[mf][0], af[mf][1], af[mf][2], af[mf][3],
                             bL[nf][0], bL[nf][1]);
#pragma unroll
            for (int mf = 0; mf < 4; mf++)
                LDSM_X4(af[mf][0], af[mf][1], af[mf][2], af[mf][3],
                        base + 1 * TILEB + aOff + mf * 16 * PITCH + koff);
#pragma unroll
            for (int mf = 0; mf < 4; mf++)
#pragma unroll
                for (int nf = 0; nf < 4; nf++)
                    mma16816(acc[mf][nf], af[mf][0], af[mf][1], af[mf][2], af[mf][3],
                             bH[nf][0], bH[nf][1]);
        }
    }

    // ---- epilogue ----
#pragma unroll
    for (int mf = 0; mf < 4; mf++) {
#pragma unroll
        for (int nf = 0; nf < 4; nf++) {
            float* c = acc[mf][nf];
            int r0 = mBase + wm + mf * 16 + lq;
            int c0 = nBase + wn + nf * 8 + 2 * lr;
#pragma unroll
            for (int half = 0; half < 2; half++) {
                int r = r0 + half * 8;
                if (r >= Meff) continue;
                float v0 = c[half * 2 + 0], v1 = c[half * 2 + 1];
                if (EPI == 0) {
                    C[(size_t)r * ldc + c0] = v0;
                    C[(size_t)r * ldc + c0 + 1] = v1;
                } else if (EPI == 1) {
                    float o0 = v0 + res[(size_t)r * ldc + c0] + bias[c0];
                    float o1 = v1 + res[(size_t)r * ldc + c0 + 1] + bias[c0 + 1];
                    C[(size_t)r * ldc + c0] = o0;  C2[(size_t)r * ldc + c0] = o0;
                    C[(size_t)r * ldc + c0 + 1] = o1; C2[(size_t)r * ldc + c0 + 1] = o1;
                } else {
                    int tok = out_idx[r];
                    float wgt = out_wt[r];
                    C[(size_t)tok * ldc + c0] += wgt * v0;
                    C[(size_t)tok * ldc + c0 + 1] += wgt * v1;
                }
            }
        }
    }
}

// ---------------- RoPE ------------------------------------------------------------
__global__ void rope_kernel(float* __restrict__ qkv, const float* __restrict__ rc,
                            const float* __restrict__ rs) {
    int idx = blockIdx.x * 256 + threadIdx.x;
    if (idx >= TOK * NHEAD * 32) return;
    int d2 = idx & 31;
    int nh = (idx >> 5) & 15;
    int m = idx >> 9;
    int s = m & (SEQ - 1);
    float c = rc[s * 32 + d2], sn = rs[s * 32 + d2];
    float* p = qkv + (size_t)m * 3072 + nh * 192 + 2 * d2;
    float re = p[0], im = p[1];
    p[0] = re * c - im * sn; p[1] = re * sn + im * c;
    float* pk = p + 64;
    re = pk[0]; im = pk[1];
    pk[0] = re * c - im * sn; pk[1] = re * sn + im * c;
}

// ---------------- flash attention (writes ctx as bf16 hi/lo) ------------------------
#define FA_STRIDE 68
#define FA_TILE   (64 * FA_STRIDE)
__global__ void flash_attn_kernel(const float* __restrict__ qkv,
                                  __nv_bfloat16* __restrict__ ctxH,
                                  __nv_bfloat16* __restrict__ ctxL) {
    extern __shared__ float smem[];
    float* Qs   = smem;
    float* Ks   = Qs + FA_TILE;
    float* Ss   = Ks + FA_TILE;
    float* Vs   = Ss + FA_TILE;
    float* Pred = Vs + FA_TILE;

    int qt = blockIdx.x, bh = blockIdx.y;
    int b = bh >> 4, h = bh & 15;
    int tid = threadIdx.x;
    int r  = tid >> 2;
    int c4 = (tid & 3) * 16;
    int q0 = (tid >> 4) * 4;
    int kc0 = (tid & 15) * 4;
    int pcol = tid & 15;

    const float* qbase = qkv + (size_t)(b * SEQ + qt * 64 + r) * 3072 + h * 192;
#pragma unroll
    for (int u = 0; u < 4; u++) {
        float4 qv = *(const float4*)(qbase + c4 + u * 4);
        Qs[(c4 + u * 4 + 0) * FA_STRIDE + r] = qv.x;
        Qs[(c4 + u * 4 + 1) * FA_STRIDE + r] = qv.y;
        Qs[(c4 + u * 4 + 2) * FA_STRIDE + r] = qv.z;
        Qs[(c4 + u * 4 + 3) * FA_STRIDE + r] = qv.w;
    }

    float o[4][4];
    float m_i[4], l_i[4];
#pragma unroll
    for (int i = 0; i < 4; i++) {
        m_i[i] = -1e30f; l_i[i] = 0.f;
#pragma unroll
        for (int j = 0; j < 4; j++) o[i][j] = 0.f;
    }

    for (int kt = 0; kt < SEQ / 64; kt++) {
        __syncthreads();
        const float* kbase = qkv + (size_t)(b * SEQ + kt * 64 + r) * 3072 + h * 192 + 64;
        const float* vbase = kbase + 64;
#pragma unroll
        for (int u = 0; u < 4; u++) {
            float4 kv = *(const float4*)(kbase + c4 + u * 4);
            Ks[(c4 + u * 4 + 0) * FA_STRIDE + r] = kv.x;
            Ks[(c4 + u * 4 + 1) * FA_STRIDE + r] = kv.y;
            Ks[(c4 + u * 4 + 2) * FA_STRIDE + r] = kv.z;
            Ks[(c4 + u * 4 + 3) * FA_STRIDE + r] = kv.w;
            *(float4*)&Vs[r * FA_STRIDE + c4 + u * 4] = *(const float4*)(vbase + c4 + u * 4);
        }
        __syncthreads();

        float s[4][4];
#pragma unroll
        for (int i = 0; i < 4; i++)
#pragma unroll
            for (int j = 0; j < 4; j++) s[i][j] = 0.f;
#pragma unroll 8
        for (int d = 0; d < 64; d++) {
            float a0[4], b0[4];
            *(float4*)a0 = *(const float4*)&Qs[d * FA_STRIDE + q0];
            *(float4*)b0 = *(const float4*)&Ks[d * FA_STRIDE + kc0];
#pragma unroll
            for (int i = 0; i < 4; i++)
#pragma unroll
                for (int j = 0; j < 4; j++) s[i][j] += a0[i] * b0[j];
        }
#pragma unroll
        for (int i = 0; i < 4; i++)
#pragma unroll
            for (int j = 0; j < 4; j++) s[i][j] *= 0.125f;

#pragma unroll
        for (int i = 0; i < 4; i++) {
            float pm = fmaxf(fmaxf(s[i][0], s[i][1]), fmaxf(s[i][2], s[i][3]));
            Pred[(q0 + i) * 20 + pcol] = pm;
        }
        __syncthreads();
        float mnew[4], corr[4];
#pragma unroll
        for (int i = 0; i < 4; i++) {
            float mx = m_i[i];
            const float* pr = &Pred[(q0 + i) * 20];
#pragma unroll
            for (int t = 0; t < 16; t++) mx = fmaxf(mx, pr[t]);
            mnew[i] = mx;
            corr[i] = expf(m_i[i] - mx);
            m_i[i] = mx;
        }
        __syncthreads();

#pragma unroll
        for (int i = 0; i < 4; i++) {
            float ps = 0.f;
#pragma unroll
            for (int j = 0; j < 4; j++) {
                float p = expf(s[i][j] - mnew[i]);
                Ss[(q0 + i) * FA_STRIDE + kc0 + j] = p;
                ps += p;
            }
            Pred[(q0 + i) * 20 + pcol] = ps;
        }
        __syncthreads();

#pragma unroll
        for (int i = 0; i < 4; i++) {
            float rs = 0.f;
            const float* pr = &Pred[(q0 + i) * 20];
#pragma unroll
            for (int t = 0; t < 16; t++) rs += pr[t];
            l_i[i] = corr[i] * l_i[i] + rs;
#pragma unroll
            for (int j = 0; j < 4; j++) o[i][j] *= corr[i];
        }

#pragma unroll 8
        for (int kk = 0; kk < 64; kk++) {
            float a0[4], b0[4];
            a0[0] = Ss[(q0 + 0) * FA_STRIDE + kk];
            a0[1] = Ss[(q0 + 1) * FA_STRIDE + kk];
            a0[2] = Ss[(q0 + 2) * FA_STRIDE + kk];
            a0[3] = Ss[(q0 + 3) * FA_STRIDE + kk];
            *(float4*)b0 = *(const float4*)&Vs[kk * FA_STRIDE + kc0];
#pragma unroll
            for (int i = 0; i < 4; i++)
#pragma unroll
                for (int j = 0; j < 4; j++) o[i][j] += a0[i] * b0[j];
        }
    }

#pragma unroll
    for (int i = 0; i < 4; i++) {
        float inv = 1.0f / l_i[i];
#pragma unroll
        for (int j = 0; j < 4; j++) {
            size_t off = (size_t)(b * SEQ + qt * 64 + q0 + i) * HID + h * 64 + kc0 + j;
            __nv_bfloat16 hh, ll;
            hl_pair(o[i][j] * inv, hh, ll);
            ctxH[off] = hh; ctxL[off] = ll;
        }
    }
}

// ---------------- MoE routing -----------------------------------------------------
__global__ void init_cnt_kernel() {
    if (threadIdx.x < NEXP) g_cnt[threadIdx.x] = 0;
}

__global__ void routing_kernel() {
    int m = blockIdx.x * 256 + threadIdx.x;
    if (m >= TOK) return;
    float l[4];
#pragma unroll
    for (int e = 0; e < 4; e++) l[e] = g_logits[m * 4 + e];
    int i0 = 0; float b0 = l[0];
#pragma unroll
    for (int e = 1; e < 4; e++) if (l[e] > b0) { b0 = l[e]; i0 = e; }
    int i1 = -1; float b1 = -1e30f;
#pragma unroll
    for (int e = 0; e < 4; e++) if (e != i0 && l[e] > b1) { b1 = l[e]; i1 = e; }
    float t = expf(b1 - b0);
    float w0 = 1.0f / (1.0f + t);
    float w1 = t / (1.0f + t);
    int p0 = atomicAdd(&g_cnt[i0], 1);
    g_eidx[i0 * TOK + p0] = m; g_ew[i0 * TOK + p0] = w0;
    int p1 = atomicAdd(&g_cnt[i1], 1);
    g_eidx[i1 * TOK + p1] = m; g_ew[i1 * TOK + p1] = w1;
}

// ---------------- host orchestration ----------------------------------------------
extern "C" void kernel_launch(void* const* d_in, const int* in_sizes, int n_in,
                              void* d_out, int out_size) {
    const float* x          = (const float*)d_in[0];
    const float* rot_cos    = (const float*)d_in[1];
    const float* rot_sin    = (const float*)d_in[2];
    const float* norm1_w    = (const float*)d_in[3];
    const float* norm2_w    = (const float*)d_in[4];
    const float* qkv_base   = (const float*)d_in[5];
    const float* qkv_spline = (const float*)d_in[6];
    const float* qkv_scaler = (const float*)d_in[7];
    const float* out_w      = (const float*)d_in[8];
    const float* out_b      = (const float*)d_in[9];
    const float* gate_w     = (const float*)d_in[10];
    const float* w1_base    = (const float*)d_in[11];
    const float* w1_spline  = (const float*)d_in[12];
    const float* w1_scaler  = (const float*)d_in[13];
    const float* w2_base    = (const float*)d_in[14];
    const float* w2_spline  = (const float*)d_in[15];
    const float* w2_scaler  = (const float*)d_in[16];
    const float* w3_base    = (const float*)d_in[17];
    const float* w3_spline  = (const float*)d_in[18];
    const float* w3_scaler  = (const float*)d_in[19];
    float* out = (float*)d_out;

    __nv_bfloat16 *phiH, *phiL, *phitH, *phitL, *ctxH, *ctxL;
    __nv_bfloat16 *qwH, *qwL, *w1H, *w1L, *w2H, *w2L, *w3H, *w3L, *owH, *owL;
    float *qkv, *x2, *t1, *t2, *logits, *ew;
    int *cnt, *eidx;
    cudaGetSymbolAddress((void**)&phiH, g_phiH);   cudaGetSymbolAddress((void**)&phiL, g_phiL);
    cudaGetSymbolAddress((void**)&phitH, g_phitH); cudaGetSymbolAddress((void**)&phitL, g_phitL);
    cudaGetSymbolAddress((void**)&ctxH, g_ctxH);   cudaGetSymbolAddress((void**)&ctxL, g_ctxL);
    cudaGetSymbolAddress((void**)&qwH, g_qkvwH);   cudaGetSymbolAddress((void**)&qwL, g_qkvwL);
    cudaGetSymbolAddress((void**)&w1H, g_w1H);     cudaGetSymbolAddress((void**)&w1L, g_w1L);
    cudaGetSymbolAddress((void**)&w2H, g_w2H);     cudaGetSymbolAddress((void**)&w2L, g_w2L);
    cudaGetSymbolAddress((void**)&w3H, g_w3H);     cudaGetSymbolAddress((void**)&w3L, g_w3L);
    cudaGetSymbolAddress((void**)&owH, g_owH);     cudaGetSymbolAddress((void**)&owL, g_owL);
    cudaGetSymbolAddress((void**)&qkv, g_qkv);     cudaGetSymbolAddress((void**)&x2, g_x2);
    cudaGetSymbolAddress((void**)&t1, g_t1);       cudaGetSymbolAddress((void**)&t2, g_t2);
    cudaGetSymbolAddress((void**)&logits, g_logits);
    cudaGetSymbolAddress((void**)&cnt, g_cnt);
    cudaGetSymbolAddress((void**)&eidx, g_eidx);
    cudaGetSymbolAddress((void**)&ew, g_ew);

    const int fa_smem = (4 * FA_TILE + 64 * 20) * sizeof(float);
    cudaFuncSetAttribute(flash_attn_kernel, cudaFuncAttributeMaxDynamicSharedMemorySize, fa_smem);
    cudaFuncSetAttribute(kan_gemm_bf<0>, cudaFuncAttributeMaxDynamicSharedMemorySize, GM_DYN);
    cudaFuncSetAttribute(kan_gemm_bf<1>, cudaFuncAttributeMaxDynamicSharedMemorySize, GM_DYN);
    cudaFuncSetAttribute(kan_gemm_bf<2>, cudaFuncAttributeMaxDynamicSharedMemorySize, GM_DYN);

    // 0) weight conversion (hi/lo bf16, scaler folded)
    conv_kan_w<<<3072, 256>>>(qkv_base, qkv_spline, qkv_scaler, HID, qwH, qwL);
    conv_kan_w<<<NEXP * DFF, 256>>>(w1_base, w1_spline, w1_scaler, HID, w1H, w1L);
    conv_kan_w<<<NEXP * DFF, 256>>>(w2_base, w2_spline, w2_scaler, HID, w2H, w2L);
    conv_kan_w<<<NEXP * HID, 256>>>(w3_base, w3_spline, w3_scaler, DFF, w3H, w3L);
    conv_plain<<<(HID * HID + 255) / 256, 256>>>(out_w, owH, owL, HID * HID);

    // 1) rmsnorm(x) -> phi hi/lo
    rmsnorm_phi_kernel<<<TOK, 256>>>(x, norm1_w, phiH, phiL, nullptr, nullptr);

    // 2) QKV = phi @ Waug^T
    kan_gemm_bf<0><<<dim3(3072 / 128, TOK / 128), 256, GM_DYN>>>(
        phiH, phiL, KAUG, nullptr, qwH, qwL, KAUG,
        qkv, 3072, TOK, 3072, KAUG, nullptr, nullptr, nullptr, nullptr, nullptr, nullptr);

    // 3) RoPE
    rope_kernel<<<(TOK * NHEAD * 32) / 256, 256>>>(qkv, rot_cos, rot_sin);

    // 4) attention
    flash_attn_kernel<<<dim3(SEQ / 64, BATCH * NHEAD), 256, fa_smem>>>(qkv, ctxH, ctxL);

    // 5) x2 = x + ctx @ out_w^T + out_b (dual store into d_out)
    kan_gemm_bf<1><<<dim3(HID / 128, TOK / 128), 256, GM_DYN>>>(
        ctxH, ctxL, HID, nullptr, owH, owL, HID,
        x2, HID, TOK, HID, HID, nullptr, x, out_b, out, nullptr, nullptr);

    // 6) rmsnorm(x2) -> phi hi/lo, gate logits
    rmsnorm_phi_kernel<<<TOK, 256>>>(x2, norm2_w, phiH, phiL, gate_w, logits);

    // 7) routing
    init_cnt_kernel<<<1, 32>>>();
    routing_kernel<<<TOK / 256, 256>>>();

    // 8) experts
    for (int e = 0; e < NEXP; e++) {
        const int* idx_e = eidx + e * TOK;
        const float* w_e = ew + e * TOK;
        kan_gemm_bf<0><<<dim3(DFF / 128, TOK / 128), 256, GM_DYN>>>(
            phiH, phiL, KAUG, idx_e,
            w1H + (size_t)e * DFF * KAUG, w1L + (size_t)e * DFF * KAUG, KAUG,
            t1, DFF, TOK, DFF, KAUG, cnt + e, nullptr, nullptr, nullptr, nullptr, nullptr);
        kan_gemm_bf<0><<<dim3(DFF / 128, TOK / 128), 256, GM_DYN>>>(
            phiH, phiL, KAUG, idx_e,
            w2H + (size_t)e * DFF * KAUG, w2L + (size_t)e * DFF * KAUG, KAUG,
            t2, DFF, TOK, DFF, KAUG, cnt + e, nullptr, nullptr, nullptr, nullptr, nullptr);
        mul_phi_kernel<<<TOK, 256>>>(t1, t2, phitH, phitL, cnt + e);
        kan_gemm_bf<2><<<dim3(HID / 128, TOK / 128), 256, GM_DYN>>>(
            phitH, phitL, KAUG, nullptr,
            w3H + (size_t)e * HID * KAUG, w3L + (size_t)e * HID * KAUG, KAUG,
            out, HID, TOK, HID, KAUG, cnt + e, nullptr, nullptr, nullptr, idx_e, w_e);
    }
}

// round 8
// speedup vs baseline: 6.1766x; 1.7494x over previous
#include <cuda_runtime.h>
#include <cuda_bf16.h>
#include <math.h>
#include <stdint.h>

#define TOK   2048      // B*S
#define HID   1024
#define KAUG  9216      // H*(1+NB)
#define NB    8
#define NHEAD 16
#define HDIM  64
#define SEQ   1024
#define BATCH 2
#define DFF   1024
#define NEXP  4

// ---------------- scratch (static device globals; no runtime alloc) ----------------
__device__ __align__(16) __nv_bfloat16 g_phiH[(size_t)TOK * KAUG];
__device__ __align__(16) __nv_bfloat16 g_phiL[(size_t)TOK * KAUG];
__device__ __align__(16) __nv_bfloat16 g_phitH[(size_t)NEXP * TOK * KAUG];
__device__ __align__(16) __nv_bfloat16 g_phitL[(size_t)NEXP * TOK * KAUG];
__device__ __align__(16) __nv_bfloat16 g_ctxH[(size_t)TOK * HID];
__device__ __align__(16) __nv_bfloat16 g_ctxL[(size_t)TOK * HID];
__device__ __align__(16) __nv_bfloat16 g_qkvwH[(size_t)3072 * KAUG];
__device__ __align__(16) __nv_bfloat16 g_qkvwL[(size_t)3072 * KAUG];
__device__ __align__(16) __nv_bfloat16 g_w1H[(size_t)NEXP * DFF * KAUG];
__device__ __align__(16) __nv_bfloat16 g_w1L[(size_t)NEXP * DFF * KAUG];
__device__ __align__(16) __nv_bfloat16 g_w2H[(size_t)NEXP * DFF * KAUG];
__device__ __align__(16) __nv_bfloat16 g_w2L[(size_t)NEXP * DFF * KAUG];
__device__ __align__(16) __nv_bfloat16 g_w3H[(size_t)NEXP * HID * KAUG];
__device__ __align__(16) __nv_bfloat16 g_w3L[(size_t)NEXP * HID * KAUG];
__device__ __align__(16) __nv_bfloat16 g_owH[(size_t)HID * HID];
__device__ __align__(16) __nv_bfloat16 g_owL[(size_t)HID * HID];

__device__ float g_qkv[(size_t)TOK * 3 * HID];
__device__ float g_x2[(size_t)TOK * HID];
__device__ float g_t1[(size_t)NEXP * TOK * DFF];
__device__ float g_t2[(size_t)NEXP * TOK * DFF];
__device__ float g_logits[TOK * NEXP];
__device__ int   g_cnt[NEXP];
__device__ int   g_eidx[NEXP * TOK];
__device__ float g_ew[NEXP * TOK];

// ---------------- helpers ----------------------------------------------------------
__device__ __forceinline__ uint32_t smem_u32(const void* p) {
    uint32_t a;
    asm("{ .reg .u64 t; cvta.to.shared.u64 t, %1; cvt.u32.u64 %0, t; }" : "=r"(a) : "l"(p));
    return a;
}

__device__ __forceinline__ void hl_pair(float v, __nv_bfloat16& h, __nv_bfloat16& l) {
    h = __float2bfloat16_rn(v);
    l = __float2bfloat16_rn(v - __bfloat162float(h));
}

__device__ __forceinline__ void mma16816(float* c, uint32_t a0, uint32_t a1, uint32_t a2,
                                         uint32_t a3, uint32_t b0, uint32_t b1) {
    asm volatile(
        "mma.sync.aligned.m16n8k16.row.col.f32.bf16.bf16.f32 "
        "{%0,%1,%2,%3}, {%4,%5,%6,%7}, {%8,%9}, {%0,%1,%2,%3};\n"
        : "+f"(c[0]), "+f"(c[1]), "+f"(c[2]), "+f"(c[3])
        : "r"(a0), "r"(a1), "r"(a2), "r"(a3), "r"(b0), "r"(b1));
}

#define LDSM_X4(r0, r1, r2, r3, addr) \
    asm volatile("ldmatrix.sync.aligned.m8n8.x4.shared.b16 {%0,%1,%2,%3}, [%4];" \
                 : "=r"(r0), "=r"(r1), "=r"(r2), "=r"(r3) : "r"(addr))

// ---------------- cubic B-spline bases --------------------------------------------
__device__ __forceinline__ void bspline8(float v, float* out) {
    float b[11];
#pragma unroll
    for (int t = 0; t < 11; t++) {
        float g0 = 0.4f * (t - 3) - 1.0f;
        float g1 = 0.4f * (t - 2) - 1.0f;
        b[t] = (v >= g0 && v < g1) ? 1.0f : 0.0f;
    }
#pragma unroll
    for (int j = 1; j <= 3; j++) {
        float inv = 1.0f / (0.4f * (float)j);
#pragma unroll
        for (int t = 0; t < 10; t++) {
            if (t < 11 - j) {
                float gt   = 0.4f * (t - 3) - 1.0f;
                float gtj1 = 0.4f * (t + j - 2) - 1.0f;
                b[t] = (v - gt) * inv * b[t] + (gtj1 - v) * inv * b[t + 1];
            }
        }
    }
#pragma unroll
    for (int c = 0; c < 8; c++) out[c] = b[c];
}

// ---------------- weight conversion (Waug -> bf16 hi/lo, scaler folded) ------------
__global__ void conv_kan_w(const float* __restrict__ base, const float* __restrict__ spline,
                           const float* __restrict__ scaler, int Kin,
                           __nv_bfloat16* __restrict__ WH, __nv_bfloat16* __restrict__ WL) {
    int o = blockIdx.x;
    int KA = Kin * 9;
    const float* brow = base + (size_t)o * Kin;
    const float* srow = spline + (size_t)o * Kin * 8;
    const float* crow = scaler + (size_t)o * Kin;
    __nv_bfloat16* hrow = WH + (size_t)o * KA;
    __nv_bfloat16* lrow = WL + (size_t)o * KA;
    for (int c = threadIdx.x; c < Kin; c += 256) {
        __nv_bfloat16 h, l;
        hl_pair(brow[c], h, l);
        hrow[c] = h; lrow[c] = l;
    }
    for (int c = threadIdx.x; c < Kin * 8; c += 256) {
        __nv_bfloat16 h, l;
        hl_pair(srow[c] * crow[c >> 3], h, l);
        hrow[Kin + c] = h; lrow[Kin + c] = l;
    }
}

__global__ void conv_plain(const float* __restrict__ W,
                           __nv_bfloat16* __restrict__ WH, __nv_bfloat16* __restrict__ WL,
                           int total) {
    int i = blockIdx.x * 256 + threadIdx.x;
    if (i < total) {
        __nv_bfloat16 h, l;
        hl_pair(W[i], h, l);
        WH[i] = h; WL[i] = l;
    }
}

// ---------------- rmsnorm + phi (bf16 hi/lo) + optional gate logits ----------------
__global__ void rmsnorm_phi_kernel(const float* __restrict__ x,
                                   const float* __restrict__ w,
                                   __nv_bfloat16* __restrict__ phiH,
                                   __nv_bfloat16* __restrict__ phiL,
                                   const float* __restrict__ gate_w,
                                   float* __restrict__ logits) {
    int m = blockIdx.x;
    int tid = threadIdx.x;
    __shared__ float sx[HID];
    __shared__ float sred[256];
    const float* xr = x + (size_t)m * HID;
    float ss = 0.f;
    for (int f = tid; f < HID; f += 256) { float v = xr[f]; sx[f] = v; ss += v * v; }
    sred[tid] = ss; __syncthreads();
    for (int o = 128; o > 0; o >>= 1) { if (tid < o) sred[tid] += sred[tid + o]; __syncthreads(); }
    float rms = rsqrtf(sred[0] / (float)HID + 1e-6f);
    float gacc[4] = {0.f, 0.f, 0.f, 0.f};
    __nv_bfloat16* ph = phiH + (size_t)m * KAUG;
    __nv_bfloat16* pl = phiL + (size_t)m * KAUG;
    for (int f = tid; f < HID; f += 256) {
        float hn = sx[f] * rms * w[f];
        __nv_bfloat16 h, l;
        hl_pair(hn / (1.0f + expf(-hn)), h, l);
        ph[f] = h; pl[f] = l;
        float bs[8];
        bspline8(hn, bs);
#pragma unroll
        for (int c = 0; c < 8; c++) {
            hl_pair(bs[c], h, l);
            ph[HID + f * 8 + c] = h; pl[HID + f * 8 + c] = l;
        }
        if (gate_w) {
#pragma unroll
            for (int e = 0; e < 4; e++) gacc[e] += hn * gate_w[e * HID + f];
        }
    }
    if (gate_w) {
#pragma unroll
        for (int e = 0; e < 4; e++) {
            __syncthreads();
            sred[tid] = gacc[e]; __syncthreads();
            for (int o = 128; o > 0; o >>= 1) { if (tid < o) sred[tid] += sred[tid + o]; __syncthreads(); }
            if (tid == 0) logits[m * 4 + e] = sred[0];
        }
    }
}

// ---------------- phi expansion of t1*t2, batched over experts ---------------------
__global__ void mul_phi_kernel() {
    int e = blockIdx.y;
    int r = blockIdx.x;
    if (r >= g_cnt[e]) return;
    int tid = threadIdx.x;
    const float* a = g_t1 + (size_t)e * TOK * DFF + (size_t)r * DFF;
    const float* b = g_t2 + (size_t)e * TOK * DFF + (size_t)r * DFF;
    __nv_bfloat16* ph = g_phitH + (size_t)e * TOK * KAUG + (size_t)r * KAUG;
    __nv_bfloat16* pl = g_phitL + (size_t)e * TOK * KAUG + (size_t)r * KAUG;
    for (int f = tid; f < DFF; f += 256) {
        float v = a[f] * b[f];
        __nv_bfloat16 h, l;
        hl_pair(v / (1.0f + expf(-v)), h, l);
        ph[f] = h; pl[f] = l;
        float bs[8];
        bspline8(v, bs);
#pragma unroll
        for (int c = 0; c < 8; c++) {
            hl_pair(bs[c], h, l);
            ph[DFF + f * 8 + c] = h; pl[DFF + f * 8 + c] = l;
        }
    }
}

// ---------------- bf16 tensor-core GEMM body ---------------------------------------
// A,B pre-split hi/lo bf16; 3 mma passes (AhBh + AhBl + AlBh).
// EPI 0: plain store. EPI 1: +res+bias dual store. EPI 3: atomic scatter-accum.
#define PITCH  80
#define TILEB  (128 * PITCH)
#define STAGE  (4 * TILEB)
#define GM_DYN (512 + 2 * STAGE)

template <int EPI>
__device__ __forceinline__ void gemm_body(
    const __nv_bfloat16* __restrict__ AH, const __nv_bfloat16* __restrict__ AL,
    int lda, const int* __restrict__ a_idx,
    const __nv_bfloat16* __restrict__ BH, const __nv_bfloat16* __restrict__ BL, int ldb,
    float* __restrict__ C, int ldc, int M, int K,
    const int* __restrict__ cnt,
    const float* __restrict__ res, const float* __restrict__ bias, float* __restrict__ C2,
    const int* __restrict__ out_idx, const float* __restrict__ out_wt) {
    int Meff = cnt ? *cnt : M;
    int mBase = blockIdx.y * 128;
    int nBase = blockIdx.x * 128;
    if (mBase >= Meff) return;

    extern __shared__ char sm[];
    int* rowmap = (int*)sm;
    uint32_t bufs_u = smem_u32(sm + 512);
    int tid = threadIdx.x;

    if (tid < 128) {
        int r = mBase + tid;
        int g = (r < Meff) ? r : mBase;
        rowmap[tid] = a_idx ? a_idx[g] : g;
    }
    __syncthreads();

    int w = tid >> 5, l = tid & 31;
    int wm = (w >> 2) * 64;
    int wn = (w & 3) * 32;
    int lq = l >> 2, lr = l & 3;
    uint32_t aOff = (uint32_t)(wm + (l & 15)) * PITCH + ((l >> 4) ? 16u : 0u);
    uint32_t bOff = (uint32_t)(wn + (l & 7) + ((l & 16) ? 8 : 0)) * PITCH + ((l & 8) ? 16u : 0u);

    float acc[4][4][4];
#pragma unroll
    for (int mf = 0; mf < 4; mf++)
#pragma unroll
        for (int nf = 0; nf < 4; nf++)
#pragma unroll
            for (int t = 0; t < 4; t++) acc[mf][nf][t] = 0.f;

    auto issue = [&](int s, int k0) {
#pragma unroll
        for (int it = 0; it < 8; it++) {
            int i = it * 256 + tid;
            int tens = i >> 9;
            int rem = i & 511;
            int row = rem >> 2;
            int seg = rem & 3;
            const __nv_bfloat16* src;
            if (tens < 2) {
                src = (tens == 0 ? AH : AL) + (size_t)rowmap[row] * lda + k0 + 8 * seg;
            } else {
                src = (tens == 2 ? BH : BL) + (size_t)(nBase + row) * ldb + k0 + 8 * seg;
            }
            uint32_t dst = bufs_u + (uint32_t)s * STAGE + (uint32_t)tens * TILEB +
                           (uint32_t)row * PITCH + (uint32_t)seg * 16;
            asm volatile("cp.async.cg.shared.global [%0], [%1], 16;" :: "r"(dst), "l"(src) : "memory");
        }
        asm volatile("cp.async.commit_group;" ::: "memory");
    };

    int nStages = K / 32;
    issue(0, 0);
    for (int ck = 0; ck < nStages; ck++) {
        if (ck) __syncthreads();
        bool pre = (ck + 1 < nStages);
        if (pre) issue((ck + 1) & 1, (ck + 1) * 32);
        if (pre) asm volatile("cp.async.wait_group 1;" ::: "memory");
        else     asm volatile("cp.async.wait_group 0;" ::: "memory");
        __syncthreads();

        uint32_t base = bufs_u + (uint32_t)(ck & 1) * STAGE;
#pragma unroll
        for (int p = 0; p < 2; p++) {
            uint32_t koff = 32u * p;
            uint32_t bH[4][2], bL[4][2], af[4][4];
#pragma unroll
            for (int nh = 0; nh < 2; nh++) {
                uint32_t r0, r1, r2, r3;
                LDSM_X4(r0, r1, r2, r3, base + 2 * TILEB + bOff + nh * 16 * PITCH + koff);
                bH[2 * nh][0] = r0; bH[2 * nh][1] = r1; bH[2 * nh + 1][0] = r2; bH[2 * nh + 1][1] = r3;
                LDSM_X4(r0, r1, r2, r3, base + 3 * TILEB + bOff + nh * 16 * PITCH + koff);
                bL[2 * nh][0] = r0; bL[2 * nh][1] = r1; bL[2 * nh + 1][0] = r2; bL[2 * nh + 1][1] = r3;
            }
#pragma unroll
            for (int mf = 0; mf < 4; mf++)
                LDSM_X4(af[mf][0], af[mf][1], af[mf][2], af[mf][3],
                        base + 0 * TILEB + aOff + mf * 16 * PITCH + koff);
#pragma unroll
            for (int mf = 0; mf < 4; mf++)
#pragma unroll
                for (int nf = 0; nf < 4; nf++)
                    mma16816(acc[mf][nf], af[mf][0], af[mf][1], af[mf][2], af[mf][3],
                             bH[nf][0], bH[nf][1]);
#pragma unroll
            for (int mf = 0; mf < 4; mf++)
#pragma unroll
                for (int nf = 0; nf < 4; nf++)
                    mma16816(acc[mf][nf], af[mf][0], af[mf][1], af[mf][2], af[mf][3],
                             bL[nf][0], bL[nf][1]);
#pragma unroll
            for (int mf = 0; mf < 4; mf++)
                LDSM_X4(af[mf][0], af[mf][1], af[mf][2], af[mf][3],
                        base + 1 * TILEB + aOff + mf * 16 * PITCH + koff);
#pragma unroll
            for (int mf = 0; mf < 4; mf++)
#pragma unroll
                for (int nf = 0; nf < 4; nf++)
                    mma16816(acc[mf][nf], af[mf][0], af[mf][1], af[mf][2], af[mf][3],
                             bH[nf][0], bH[nf][1]);
        }
    }

    // ---- epilogue ----
#pragma unroll
    for (int mf = 0; mf < 4; mf++) {
#pragma unroll
        for (int nf = 0; nf < 4; nf++) {
            float* c = acc[mf][nf];
            int r0 = mBase + wm + mf * 16 + lq;
            int c0 = nBase + wn + nf * 8 + 2 * lr;
#pragma unroll
            for (int half = 0; half < 2; half++) {
                int r = r0 + half * 8;
                if (r >= Meff) continue;
                float v0 = c[half * 2 + 0], v1 = c[half * 2 + 1];
                if (EPI == 0) {
                    C[(size_t)r * ldc + c0] = v0;
                    C[(size_t)r * ldc + c0 + 1] = v1;
                } else if (EPI == 1) {
                    float o0 = v0 + res[(size_t)r * ldc + c0] + bias[c0];
                    float o1 = v1 + res[(size_t)r * ldc + c0 + 1] + bias[c0 + 1];
                    C[(size_t)r * ldc + c0] = o0;  C2[(size_t)r * ldc + c0] = o0;
                    C[(size_t)r * ldc + c0 + 1] = o1; C2[(size_t)r * ldc + c0 + 1] = o1;
                } else {
                    int tok = out_idx[r];
                    float wgt = out_wt[r];
                    atomicAdd(&C[(size_t)tok * ldc + c0], wgt * v0);
                    atomicAdd(&C[(size_t)tok * ldc + c0 + 1], wgt * v1);
                }
            }
        }
    }
}

// generic wrapper (QKV, out-proj)
template <int EPI>
__global__ void __launch_bounds__(256, 2)
kan_gemm_bf(const __nv_bfloat16* __restrict__ AH, const __nv_bfloat16* __restrict__ AL,
            int lda,
            const __nv_bfloat16* __restrict__ BH, const __nv_bfloat16* __restrict__ BL,
            int ldb,
            float* __restrict__ C, int ldc, int M, int K,
            const float* __restrict__ res, const float* __restrict__ bias,
            float* __restrict__ C2) {
    gemm_body<EPI>(AH, AL, lda, nullptr, BH, BL, ldb, C, ldc, M, K,
                   nullptr, res, bias, C2, nullptr, nullptr);
}

// batched w1+w2 over 4 experts: z = expert*2 + (0:w1, 1:w2)
__global__ void __launch_bounds__(256, 2)
kan_gemm_w12() {
    int z = blockIdx.z, e = z >> 1, sel = z & 1;
    const __nv_bfloat16* BH = (sel ? g_w2H : g_w1H) + (size_t)e * DFF * KAUG;
    const __nv_bfloat16* BL = (sel ? g_w2L : g_w1L) + (size_t)e * DFF * KAUG;
    float* C = (sel ? g_t2 : g_t1) + (size_t)e * TOK * DFF;
    gemm_body<0>(g_phiH, g_phiL, KAUG, g_eidx + e * TOK, BH, BL, KAUG,
                 C, DFF, TOK, KAUG, g_cnt + e, nullptr, nullptr, nullptr, nullptr, nullptr);
}

// batched w3 over 4 experts: z = expert; atomic scatter into out
__global__ void __launch_bounds__(256, 2)
kan_gemm_w3(float* __restrict__ out) {
    int e = blockIdx.z;
    gemm_body<3>(g_phitH + (size_t)e * TOK * KAUG, g_phitL + (size_t)e * TOK * KAUG,
                 KAUG, nullptr,
                 g_w3H + (size_t)e * HID * KAUG, g_w3L + (size_t)e * HID * KAUG, KAUG,
                 out, HID, TOK, KAUG, g_cnt + e, nullptr, nullptr, nullptr,
                 g_eidx + e * TOK, g_ew + e * TOK);
}

// ---------------- RoPE ------------------------------------------------------------
__global__ void rope_kernel(float* __restrict__ qkv, const float* __restrict__ rc,
                            const float* __restrict__ rs) {
    int idx = blockIdx.x * 256 + threadIdx.x;
    if (idx >= TOK * NHEAD * 32) return;
    int d2 = idx & 31;
    int nh = (idx >> 5) & 15;
    int m = idx >> 9;
    int s = m & (SEQ - 1);
    float c = rc[s * 32 + d2], sn = rs[s * 32 + d2];
    float* p = qkv + (size_t)m * 3072 + nh * 192 + 2 * d2;
    float re = p[0], im = p[1];
    p[0] = re * c - im * sn; p[1] = re * sn + im * c;
    float* pk = p + 64;
    re = pk[0]; im = pk[1];
    pk[0] = re * c - im * sn; pk[1] = re * sn + im * c;
}

// ---------------- flash attention (writes ctx as bf16 hi/lo) ------------------------
#define FA_STRIDE 68
#define FA_TILE   (64 * FA_STRIDE)
__global__ void flash_attn_kernel(const float* __restrict__ qkv,
                                  __nv_bfloat16* __restrict__ ctxH,
                                  __nv_bfloat16* __restrict__ ctxL) {
    extern __shared__ float smem[];
    float* Qs   = smem;
    float* Ks   = Qs + FA_TILE;
    float* Ss   = Ks + FA_TILE;
    float* Vs   = Ss + FA_TILE;
    float* Pred = Vs + FA_TILE;

    int qt = blockIdx.x, bh = blockIdx.y;
    int b = bh >> 4, h = bh & 15;
    int tid = threadIdx.x;
    int r  = tid >> 2;
    int c4 = (tid & 3) * 16;
    int q0 = (tid >> 4) * 4;
    int kc0 = (tid & 15) * 4;
    int pcol = tid & 15;

    const float* qbase = qkv + (size_t)(b * SEQ + qt * 64 + r) * 3072 + h * 192;
#pragma unroll
    for (int u = 0; u < 4; u++) {
        float4 qv = *(const float4*)(qbase + c4 + u * 4);
        Qs[(c4 + u * 4 + 0) * FA_STRIDE + r] = qv.x;
        Qs[(c4 + u * 4 + 1) * FA_STRIDE + r] = qv.y;
        Qs[(c4 + u * 4 + 2) * FA_STRIDE + r] = qv.z;
        Qs[(c4 + u * 4 + 3) * FA_STRIDE + r] = qv.w;
    }

    float o[4][4];
    float m_i[4], l_i[4];
#pragma unroll
    for (int i = 0; i < 4; i++) {
        m_i[i] = -1e30f; l_i[i] = 0.f;
#pragma unroll
        for (int j = 0; j < 4; j++) o[i][j] = 0.f;
    }

    for (int kt = 0; kt < SEQ / 64; kt++) {
        __syncthreads();
        const float* kbase = qkv + (size_t)(b * SEQ + kt * 64 + r) * 3072 + h * 192 + 64;
        const float* vbase = kbase + 64;
#pragma unroll
        for (int u = 0; u < 4; u++) {
            float4 kv = *(const float4*)(kbase + c4 + u * 4);
            Ks[(c4 + u * 4 + 0) * FA_STRIDE + r] = kv.x;
            Ks[(c4 + u * 4 + 1) * FA_STRIDE + r] = kv.y;
            Ks[(c4 + u * 4 + 2) * FA_STRIDE + r] = kv.z;
            Ks[(c4 + u * 4 + 3) * FA_STRIDE + r] = kv.w;
            *(float4*)&Vs[r * FA_STRIDE + c4 + u * 4] = *(const float4*)(vbase + c4 + u * 4);
        }
        __syncthreads();

        float s[4][4];
#pragma unroll
        for (int i = 0; i < 4; i++)
#pragma unroll
            for (int j = 0; j < 4; j++) s[i][j] = 0.f;
#pragma unroll 8
        for (int d = 0; d < 64; d++) {
            float a0[4], b0[4];
            *(float4*)a0 = *(const float4*)&Qs[d * FA_STRIDE + q0];
            *(float4*)b0 = *(const float4*)&Ks[d * FA_STRIDE + kc0];
#pragma unroll
            for (int i = 0; i < 4; i++)
#pragma unroll
                for (int j = 0; j < 4; j++) s[i][j] += a0[i] * b0[j];
        }
#pragma unroll
        for (int i = 0; i < 4; i++)
#pragma unroll
            for (int j = 0; j < 4; j++) s[i][j] *= 0.125f;

#pragma unroll
        for (int i = 0; i < 4; i++) {
            float pm = fmaxf(fmaxf(s[i][0], s[i][1]), fmaxf(s[i][2], s[i][3]));
            Pred[(q0 + i) * 20 + pcol] = pm;
        }
        __syncthreads();
        float mnew[4], corr[4];
#pragma unroll
        for (int i = 0; i < 4; i++) {
            float mx = m_i[i];
            const float* pr = &Pred[(q0 + i) * 20];
#pragma unroll
            for (int t = 0; t < 16; t++) mx = fmaxf(mx, pr[t]);
            mnew[i] = mx;
            corr[i] = expf(m_i[i] - mx);
            m_i[i] = mx;
        }
        __syncthreads();

#pragma unroll
        for (int i = 0; i < 4; i++) {
            float ps = 0.f;
#pragma unroll
            for (int j = 0; j < 4; j++) {
                float p = expf(s[i][j] - mnew[i]);
                Ss[(q0 + i) * FA_STRIDE + kc0 + j] = p;
                ps += p;
            }
            Pred[(q0 + i) * 20 + pcol] = ps;
        }
        __syncthreads();

#pragma unroll
        for (int i = 0; i < 4; i++) {
            float rs = 0.f;
            const float* pr = &Pred[(q0 + i) * 20];
#pragma unroll
            for (int t = 0; t < 16; t++) rs += pr[t];
            l_i[i] = corr[i] * l_i[i] + rs;
#pragma unroll
            for (int j = 0; j < 4; j++) o[i][j] *= corr[i];
        }

#pragma unroll 8
        for (int kk = 0; kk < 64; kk++) {
            float a0[4], b0[4];
            a0[0] = Ss[(q0 + 0) * FA_STRIDE + kk];
            a0[1] = Ss[(q0 + 1) * FA_STRIDE + kk];
            a0[2] = Ss[(q0 + 2) * FA_STRIDE + kk];
            a0[3] = Ss[(q0 + 3) * FA_STRIDE + kk];
            *(float4*)b0 = *(const float4*)&Vs[kk * FA_STRIDE + kc0];
#pragma unroll
            for (int i = 0; i < 4; i++)
#pragma unroll
                for (int j = 0; j < 4; j++) o[i][j] += a0[i] * b0[j];
        }
    }

#pragma unroll
    for (int i = 0; i < 4; i++) {
        float inv = 1.0f / l_i[i];
#pragma unroll
        for (int j = 0; j < 4; j++) {
            size_t off = (size_t)(b * SEQ + qt * 64 + q0 + i) * HID + h * 64 + kc0 + j;
            __nv_bfloat16 hh, ll;
            hl_pair(o[i][j] * inv, hh, ll);
            ctxH[off] = hh; ctxL[off] = ll;
        }
    }
}

// ---------------- MoE routing -----------------------------------------------------
__global__ void init_cnt_kernel() {
    if (threadIdx.x < NEXP) g_cnt[threadIdx.x] = 0;
}

__global__ void routing_kernel() {
    int m = blockIdx.x * 256 + threadIdx.x;
    if (m >= TOK) return;
    float l[4];
#pragma unroll
    for (int e = 0; e < 4; e++) l[e] = g_logits[m * 4 + e];
    int i0 = 0; float b0 = l[0];
#pragma unroll
    for (int e = 1; e < 4; e++) if (l[e] > b0) { b0 = l[e]; i0 = e; }
    int i1 = -1; float b1 = -1e30f;
#pragma unroll
    for (int e = 0; e < 4; e++) if (e != i0 && l[e] > b1) { b1 = l[e]; i1 = e; }
    float t = expf(b1 - b0);
    float w0 = 1.0f / (1.0f + t);
    float w1 = t / (1.0f + t);
    int p0 = atomicAdd(&g_cnt[i0], 1);
    g_eidx[i0 * TOK + p0] = m; g_ew[i0 * TOK + p0] = w0;
    int p1 = atomicAdd(&g_cnt[i1], 1);
    g_eidx[i1 * TOK + p1] = m; g_ew[i1 * TOK + p1] = w1;
}

// ---------------- host orchestration ----------------------------------------------
extern "C" void kernel_launch(void* const* d_in, const int* in_sizes, int n_in,
                              void* d_out, int out_size) {
    const float* x          = (const float*)d_in[0];
    const float* rot_cos    = (const float*)d_in[1];
    const float* rot_sin    = (const float*)d_in[2];
    const float* norm1_w    = (const float*)d_in[3];
    const float* norm2_w    = (const float*)d_in[4];
    const float* qkv_base   = (const float*)d_in[5];
    const float* qkv_spline = (const float*)d_in[6];
    const float* qkv_scaler = (const float*)d_in[7];
    const float* out_w      = (const float*)d_in[8];
    const float* out_b      = (const float*)d_in[9];
    const float* gate_w     = (const float*)d_in[10];
    const float* w1_base    = (const float*)d_in[11];
    const float* w1_spline  = (const float*)d_in[12];
    const float* w1_scaler  = (const float*)d_in[13];
    const float* w2_base    = (const float*)d_in[14];
    const float* w2_spline  = (const float*)d_in[15];
    const float* w2_scaler  = (const float*)d_in[16];
    const float* w3_base    = (const float*)d_in[17];
    const float* w3_spline  = (const float*)d_in[18];
    const float* w3_scaler  = (const float*)d_in[19];
    float* out = (float*)d_out;

    __nv_bfloat16 *phiH, *phiL, *ctxH, *ctxL;
    __nv_bfloat16 *qwH, *qwL, *w1H, *w1L, *w2H, *w2L, *w3H, *w3L, *owH, *owL;
    float *qkv, *x2, *logits;
    cudaGetSymbolAddress((void**)&phiH, g_phiH);   cudaGetSymbolAddress((void**)&phiL, g_phiL);
    cudaGetSymbolAddress((void**)&ctxH, g_ctxH);   cudaGetSymbolAddress((void**)&ctxL, g_ctxL);
    cudaGetSymbolAddress((void**)&qwH, g_qkvwH);   cudaGetSymbolAddress((void**)&qwL, g_qkvwL);
    cudaGetSymbolAddress((void**)&w1H, g_w1H);     cudaGetSymbolAddress((void**)&w1L, g_w1L);
    cudaGetSymbolAddress((void**)&w2H, g_w2H);     cudaGetSymbolAddress((void**)&w2L, g_w2L);
    cudaGetSymbolAddress((void**)&w3H, g_w3H);     cudaGetSymbolAddress((void**)&w3L, g_w3L);
    cudaGetSymbolAddress((void**)&owH, g_owH);     cudaGetSymbolAddress((void**)&owL, g_owL);
    cudaGetSymbolAddress((void**)&qkv, g_qkv);     cudaGetSymbolAddress((void**)&x2, g_x2);
    cudaGetSymbolAddress((void**)&logits, g_logits);

    const int fa_smem = (4 * FA_TILE + 64 * 20) * sizeof(float);
    cudaFuncSetAttribute(flash_attn_kernel, cudaFuncAttributeMaxDynamicSharedMemorySize, fa_smem);
    cudaFuncSetAttribute(kan_gemm_bf<0>, cudaFuncAttributeMaxDynamicSharedMemorySize, GM_DYN);
    cudaFuncSetAttribute(kan_gemm_bf<1>, cudaFuncAttributeMaxDynamicSharedMemorySize, GM_DYN);
    cudaFuncSetAttribute(kan_gemm_w12, cudaFuncAttributeMaxDynamicSharedMemorySize, GM_DYN);
    cudaFuncSetAttribute(kan_gemm_w3, cudaFuncAttributeMaxDynamicSharedMemorySize, GM_DYN);

    // 0) weight conversion (hi/lo bf16, scaler folded)
    conv_kan_w<<<3072, 256>>>(qkv_base, qkv_spline, qkv_scaler, HID, qwH, qwL);
    conv_kan_w<<<NEXP * DFF, 256>>>(w1_base, w1_spline, w1_scaler, HID, w1H, w1L);
    conv_kan_w<<<NEXP * DFF, 256>>>(w2_base, w2_spline, w2_scaler, HID, w2H, w2L);
    conv_kan_w<<<NEXP * HID, 256>>>(w3_base, w3_spline, w3_scaler, DFF, w3H, w3L);
    conv_plain<<<(HID * HID + 255) / 256, 256>>>(out_w, owH, owL, HID * HID);

    // 1) rmsnorm(x) -> phi hi/lo
    rmsnorm_phi_kernel<<<TOK, 256>>>(x, norm1_w, phiH, phiL, nullptr, nullptr);

    // 2) QKV = phi @ Waug^T
    kan_gemm_bf<0><<<dim3(3072 / 128, TOK / 128), 256, GM_DYN>>>(
        phiH, phiL, KAUG, qwH, qwL, KAUG, qkv, 3072, TOK, KAUG,
        nullptr, nullptr, nullptr);

    // 3) RoPE
    rope_kernel<<<(TOK * NHEAD * 32) / 256, 256>>>(qkv, rot_cos, rot_sin);

    // 4) attention
    flash_attn_kernel<<<dim3(SEQ / 64, BATCH * NHEAD), 256, fa_smem>>>(qkv, ctxH, ctxL);

    // 5) x2 = x + ctx @ out_w^T + out_b (dual store into d_out)
    kan_gemm_bf<1><<<dim3(HID / 128, TOK / 128), 256, GM_DYN>>>(
        ctxH, ctxL, HID, owH, owL, HID, x2, HID, TOK, HID,
        x, out_b, out);

    // 6) rmsnorm(x2) -> phi hi/lo, gate logits
    rmsnorm_phi_kernel<<<TOK, 256>>>(x2, norm2_w, phiH, phiL, gate_w, logits);

    // 7) routing
    init_cnt_kernel<<<1, 32>>>();
    routing_kernel<<<TOK / 256, 256>>>();

    // 8) MoE: all experts batched in z
    kan_gemm_w12<<<dim3(DFF / 128, TOK / 128, 2 * NEXP), 256, GM_DYN>>>();
    mul_phi_kernel<<<dim3(TOK, NEXP), 256>>>();
    kan_gemm_w3<<<dim3(HID / 128, TOK / 128, NEXP), 256, GM_DYN>>>(out);
}

// round 10
// speedup vs baseline: 6.9100x; 1.1187x over previous
#include <cuda_runtime.h>
#include <cuda_bf16.h>
#include <cuda_fp16.h>
#include <math.h>
#include <stdint.h>

#define TOK   2048      // B*S
#define HID   1024
#define KAUG  9216      // H*(1+NB)
#define NB    8
#define NHEAD 16
#define HDIM  64
#define SEQ   1024
#define BATCH 2
#define DFF   1024
#define NEXP  4

// ---------------- scratch (static device globals; no runtime alloc) ----------------
__device__ __align__(16) __half        g_phiH[(size_t)TOK * KAUG];   // fp16 hi
__device__ __align__(16) __half        g_phiL[(size_t)TOK * KAUG];   // fp16 lo
__device__ __align__(16) __nv_bfloat16 g_phitH[(size_t)NEXP * TOK * KAUG];
__device__ __align__(16) __nv_bfloat16 g_phitL[(size_t)NEXP * TOK * KAUG];
__device__ __align__(16) __nv_bfloat16 g_ctxH[(size_t)TOK * HID];
__device__ __align__(16) __nv_bfloat16 g_ctxL[(size_t)TOK * HID];
__device__ __align__(16) __half        g_qkvwH[(size_t)3072 * KAUG];
__device__ __align__(16) __half        g_qkvwL[(size_t)3072 * KAUG];
__device__ __align__(16) __half        g_w1F[(size_t)NEXP * DFF * KAUG];  // single fp16
__device__ __align__(16) __half        g_w2F[(size_t)NEXP * DFF * KAUG];  // single fp16
__device__ __align__(16) __nv_bfloat16 g_w3H[(size_t)NEXP * HID * KAUG];
__device__ __align__(16) __nv_bfloat16 g_w3L[(size_t)NEXP * HID * KAUG];
__device__ __align__(16) __nv_bfloat16 g_owH[(size_t)HID * HID];
__device__ __align__(16) __nv_bfloat16 g_owL[(size_t)HID * HID];

__device__ float g_qkv[(size_t)TOK * 3 * HID];
__device__ float g_x2[(size_t)TOK * HID];
__device__ float g_t1[(size_t)NEXP * TOK * DFF];
__device__ float g_t2[(size_t)NEXP * TOK * DFF];
__device__ float g_logits[TOK * NEXP];
__device__ int   g_cnt[NEXP];
__device__ int   g_eidx[NEXP * TOK];
__device__ float g_ew[NEXP * TOK];

// ---------------- helpers ----------------------------------------------------------
__device__ __forceinline__ uint32_t smem_u32(const void* p) {
    uint32_t a;
    asm("{ .reg .u64 t; cvta.to.shared.u64 t, %1; cvt.u32.u64 %0, t; }" : "=r"(a) : "l"(p));
    return a;
}

__device__ __forceinline__ void hl_pair(float v, __nv_bfloat16& h, __nv_bfloat16& l) {
    h = __float2bfloat16_rn(v);
    l = __float2bfloat16_rn(v - __bfloat162float(h));
}
__device__ __forceinline__ void hl_pair_h(float v, __half& h, __half& l) {
    h = __float2half_rn(v);
    l = __float2half_rn(v - __half2float(h));
}

template <int ISF16>
__device__ __forceinline__ void mma_any(float* c, uint32_t a0, uint32_t a1, uint32_t a2,
                                        uint32_t a3, uint32_t b0, uint32_t b1) {
    if (ISF16) {
        asm volatile(
            "mma.sync.aligned.m16n8k16.row.col.f32.f16.f16.f32 "
            "{%0,%1,%2,%3}, {%4,%5,%6,%7}, {%8,%9}, {%0,%1,%2,%3};\n"
            : "+f"(c[0]), "+f"(c[1]), "+f"(c[2]), "+f"(c[3])
            : "r"(a0), "r"(a1), "r"(a2), "r"(a3), "r"(b0), "r"(b1));
    } else {
        asm volatile(
            "mma.sync.aligned.m16n8k16.row.col.f32.bf16.bf16.f32 "
            "{%0,%1,%2,%3}, {%4,%5,%6,%7}, {%8,%9}, {%0,%1,%2,%3};\n"
            : "+f"(c[0]), "+f"(c[1]), "+f"(c[2]), "+f"(c[3])
            : "r"(a0), "r"(a1), "r"(a2), "r"(a3), "r"(b0), "r"(b1));
    }
}

#define LDSM_X4(r0, r1, r2, r3, addr) \
    asm volatile("ldmatrix.sync.aligned.m8n8.x4.shared.b16 {%0,%1,%2,%3}, [%4];" \
                 : "=r"(r0), "=r"(r1), "=r"(r2), "=r"(r3) : "r"(addr))

// ---------------- cubic B-spline bases --------------------------------------------
__device__ __forceinline__ void bspline8(float v, float* out) {
    float b[11];
#pragma unroll
    for (int t = 0; t < 11; t++) {
        float g0 = 0.4f * (t - 3) - 1.0f;
        float g1 = 0.4f * (t - 2) - 1.0f;
        b[t] = (v >= g0 && v < g1) ? 1.0f : 0.0f;
    }
#pragma unroll
    for (int j = 1; j <= 3; j++) {
        float inv = 1.0f / (0.4f * (float)j);
#pragma unroll
        for (int t = 0; t < 10; t++) {
            if (t < 11 - j) {
                float gt   = 0.4f * (t - 3) - 1.0f;
                float gtj1 = 0.4f * (t + j - 2) - 1.0f;
                b[t] = (v - gt) * inv * b[t] + (gtj1 - v) * inv * b[t + 1];
            }
        }
    }
#pragma unroll
    for (int c = 0; c < 8; c++) out[c] = b[c];
}

// ---------------- weight conversion kernels ----------------------------------------
// bf16 hi/lo pair (w3)
__global__ void conv_kan_w(const float* __restrict__ base, const float* __restrict__ spline,
                           const float* __restrict__ scaler, int Kin,
                           __nv_bfloat16* __restrict__ WH, __nv_bfloat16* __restrict__ WL) {
    int o = blockIdx.x;
    int KA = Kin * 9;
    const float* brow = base + (size_t)o * Kin;
    const float* srow = spline + (size_t)o * Kin * 8;
    const float* crow = scaler + (size_t)o * Kin;
    __nv_bfloat16* hrow = WH + (size_t)o * KA;
    __nv_bfloat16* lrow = WL + (size_t)o * KA;
    for (int c = threadIdx.x; c < Kin; c += 256) {
        __nv_bfloat16 h, l;
        hl_pair(brow[c], h, l);
        hrow[c] = h; lrow[c] = l;
    }
    for (int c = threadIdx.x; c < Kin * 8; c += 256) {
        __nv_bfloat16 h, l;
        hl_pair(srow[c] * crow[c >> 3], h, l);
        hrow[Kin + c] = h; lrow[Kin + c] = l;
    }
}

// fp16 hi/lo pair (qkv weights)
__global__ void conv_kan_w_h(const float* __restrict__ base, const float* __restrict__ spline,
                             const float* __restrict__ scaler, int Kin,
                             __half* __restrict__ WH, __half* __restrict__ WL) {
    int o = blockIdx.x;
    int KA = Kin * 9;
    const float* brow = base + (size_t)o * Kin;
    const float* srow = spline + (size_t)o * Kin * 8;
    const float* crow = scaler + (size_t)o * Kin;
    __half* hrow = WH + (size_t)o * KA;
    __half* lrow = WL + (size_t)o * KA;
    for (int c = threadIdx.x; c < Kin; c += 256) {
        __half h, l;
        hl_pair_h(brow[c], h, l);
        hrow[c] = h; lrow[c] = l;
    }
    for (int c = threadIdx.x; c < Kin * 8; c += 256) {
        __half h, l;
        hl_pair_h(srow[c] * crow[c >> 3], h, l);
        hrow[Kin + c] = h; lrow[Kin + c] = l;
    }
}

// single fp16 (w1, w2 — 2-pass B operand)
__global__ void conv_kan_w_h1(const float* __restrict__ base, const float* __restrict__ spline,
                              const float* __restrict__ scaler, int Kin,
                              __half* __restrict__ W) {
    int o = blockIdx.x;
    int KA = Kin * 9;
    const float* brow = base + (size_t)o * Kin;
    const float* srow = spline + (size_t)o * Kin * 8;
    const float* crow = scaler + (size_t)o * Kin;
    __half* row = W + (size_t)o * KA;
    for (int c = threadIdx.x; c < Kin; c += 256)
        row[c] = __float2half_rn(brow[c]);
    for (int c = threadIdx.x; c < Kin * 8; c += 256)
        row[Kin + c] = __float2half_rn(srow[c] * crow[c >> 3]);
}

__global__ void conv_plain(const float* __restrict__ W,
                           __nv_bfloat16* __restrict__ WH, __nv_bfloat16* __restrict__ WL,
                           int total) {
    int i = blockIdx.x * 256 + threadIdx.x;
    if (i < total) {
        __nv_bfloat16 h, l;
        hl_pair(W[i], h, l);
        WH[i] = h; WL[i] = l;
    }
}

// ---------------- rmsnorm + phi (fp16 hi/lo) + optional gate logits ----------------
__global__ void rmsnorm_phi_kernel(const float* __restrict__ x,
                                   const float* __restrict__ w,
                                   __half* __restrict__ phiH,
                                   __half* __restrict__ phiL,
                                   const float* __restrict__ gate_w,
                                   float* __restrict__ logits) {
    int m = blockIdx.x;
    int tid = threadIdx.x;
    __shared__ float sx[HID];
    __shared__ float sred[256];
    const float* xr = x + (size_t)m * HID;
    float ss = 0.f;
    for (int f = tid; f < HID; f += 256) { float v = xr[f]; sx[f] = v; ss += v * v; }
    sred[tid] = ss; __syncthreads();
    for (int o = 128; o > 0; o >>= 1) { if (tid < o) sred[tid] += sred[tid + o]; __syncthreads(); }
    float rms = rsqrtf(sred[0] / (float)HID + 1e-6f);
    float gacc[4] = {0.f, 0.f, 0.f, 0.f};
    __half* ph = phiH + (size_t)m * KAUG;
    __half* pl = phiL + (size_t)m * KAUG;
    for (int f = tid; f < HID; f += 256) {
        float hn = sx[f] * rms * w[f];
        __half h, l;
        hl_pair_h(hn / (1.0f + expf(-hn)), h, l);
        ph[f] = h; pl[f] = l;
        float bs[8];
        bspline8(hn, bs);
#pragma unroll
        for (int c = 0; c < 8; c++) {
            hl_pair_h(bs[c], h, l);
            ph[HID + f * 8 + c] = h; pl[HID + f * 8 + c] = l;
        }
        if (gate_w) {
#pragma unroll
            for (int e = 0; e < 4; e++) gacc[e] += hn * gate_w[e * HID + f];
        }
    }
    if (gate_w) {
#pragma unroll
        for (int e = 0; e < 4; e++) {
            __syncthreads();
            sred[tid] = gacc[e]; __syncthreads();
            for (int o = 128; o > 0; o >>= 1) { if (tid < o) sred[tid] += sred[tid + o]; __syncthreads(); }
            if (tid == 0) logits[m * 4 + e] = sred[0];
        }
    }
}

// ---------------- phi expansion of t1*t2, batched over experts (bf16) --------------
__global__ void mul_phi_kernel() {
    int e = blockIdx.y;
    int r = blockIdx.x;
    if (r >= g_cnt[e]) return;
    int tid = threadIdx.x;
    const float* a = g_t1 + (size_t)e * TOK * DFF + (size_t)r * DFF;
    const float* b = g_t2 + (size_t)e * TOK * DFF + (size_t)r * DFF;
    __nv_bfloat16* ph = g_phitH + (size_t)e * TOK * KAUG + (size_t)r * KAUG;
    __nv_bfloat16* pl = g_phitL + (size_t)e * TOK * KAUG + (size_t)r * KAUG;
    for (int f = tid; f < DFF; f += 256) {
        float v = a[f] * b[f];
        __nv_bfloat16 h, l;
        hl_pair(v / (1.0f + expf(-v)), h, l);
        ph[f] = h; pl[f] = l;
        float bs[8];
        bspline8(v, bs);
#pragma unroll
        for (int c = 0; c < 8; c++) {
            hl_pair(bs[c], h, l);
            ph[DFF + f * 8 + c] = h; pl[DFF + f * 8 + c] = l;
        }
    }
}

// ---------------- tensor-core GEMM body --------------------------------------------
// PASSES=3: tiles AH AL BH BL; AhBh + AhBl + AlBh.
// PASSES=2: tiles AH AL B;     AhB  + AlB   (B single-rounded fp16).
// EPI 0: plain. EPI 1: +res+bias dual store. EPI 3: atomic scatter. EPI 4: RoPE store.
#define PITCH  80
#define TILEB  (128 * PITCH)
#define GM_DYN3 (512 + 2 * 4 * TILEB)
#define GM_DYN2 (512 + 2 * 3 * TILEB)

template <int EPI, int PASSES, int ISF16>
__device__ __forceinline__ void gemm_body(
    const uint16_t* __restrict__ AH, const uint16_t* __restrict__ AL,
    int lda, const int* __restrict__ a_idx,
    const uint16_t* __restrict__ BH, const uint16_t* __restrict__ BL, int ldb,
    float* __restrict__ C, int ldc, int M, int K,
    const int* __restrict__ cnt,
    const float* __restrict__ aux0, const float* __restrict__ aux1, float* __restrict__ C2,
    const int* __restrict__ out_idx, const float* __restrict__ out_wt) {
    const int NT = (PASSES == 3) ? 4 : 3;
    const uint32_t STAGEB = (uint32_t)NT * TILEB;

    int Meff = cnt ? *cnt : M;
    int mBase = blockIdx.y * 128;
    int nBase = blockIdx.x * 128;
    if (mBase >= Meff) return;

    extern __shared__ char sm[];
    int* rowmap = (int*)sm;
    uint32_t bufs_u = smem_u32(sm + 512);
    int tid = threadIdx.x;

    if (tid < 128) {
        int r = mBase + tid;
        int g = (r < Meff) ? r : mBase;
        rowmap[tid] = a_idx ? a_idx[g] : g;
    }
    __syncthreads();

    int w = tid >> 5, l = tid & 31;
    int wm = (w >> 2) * 64;
    int wn = (w & 3) * 32;
    int lq = l >> 2, lr = l & 3;
    uint32_t aOff = (uint32_t)(wm + (l & 15)) * PITCH + ((l >> 4) ? 16u : 0u);
    uint32_t bOff = (uint32_t)(wn + (l & 7) + ((l & 16) ? 8 : 0)) * PITCH + ((l & 8) ? 16u : 0u);

    float acc[4][4][4];
#pragma unroll
    for (int mf = 0; mf < 4; mf++)
#pragma unroll
        for (int nf = 0; nf < 4; nf++)
#pragma unroll
            for (int t = 0; t < 4; t++) acc[mf][nf][t] = 0.f;

    auto issue = [&](int s, int k0) {
#pragma unroll
        for (int it = 0; it < 2 * NT; it++) {
            int i = it * 256 + tid;
            int tens = i >> 9;
            int rem = i & 511;
            int row = rem >> 2;
            int seg = rem & 3;
            const uint16_t* src;
            if (tens == 0)      src = AH + (size_t)rowmap[row] * lda + k0 + 8 * seg;
            else if (tens == 1) src = AL + (size_t)rowmap[row] * lda + k0 + 8 * seg;
            else if (tens == 2) src = BH + (size_t)(nBase + row) * ldb + k0 + 8 * seg;
            else                src = BL + (size_t)(nBase + row) * ldb + k0 + 8 * seg;
            uint32_t dst = bufs_u + (uint32_t)s * STAGEB + (uint32_t)tens * TILEB +
                           (uint32_t)row * PITCH + (uint32_t)seg * 16;
            asm volatile("cp.async.cg.shared.global [%0], [%1], 16;" :: "r"(dst), "l"(src) : "memory");
        }
        asm volatile("cp.async.commit_group;" ::: "memory");
    };

    int nStages = K / 32;
    issue(0, 0);
    for (int ck = 0; ck < nStages; ck++) {
        if (ck) __syncthreads();
        bool pre = (ck + 1 < nStages);
        if (pre) issue((ck + 1) & 1, (ck + 1) * 32);
        if (pre) asm volatile("cp.async.wait_group 1;" ::: "memory");
        else     asm volatile("cp.async.wait_group 0;" ::: "memory");
        __syncthreads();

        uint32_t base = bufs_u + (uint32_t)(ck & 1) * STAGEB;
#pragma unroll
        for (int p = 0; p < 2; p++) {
            uint32_t koff = 32u * p;
            if (PASSES == 3) {
                uint32_t bH[4][2], bL[4][2], af[4][4];
#pragma unroll
                for (int nh = 0; nh < 2; nh++) {
                    uint32_t r0, r1, r2, r3;
                    LDSM_X4(r0, r1, r2, r3, base + 2 * TILEB + bOff + nh * 16 * PITCH + koff);
                    bH[2 * nh][0] = r0; bH[2 * nh][1] = r1; bH[2 * nh + 1][0] = r2; bH[2 * nh + 1][1] = r3;
                    LDSM_X4(r0, r1, r2, r3, base + 3 * TILEB + bOff + nh * 16 * PITCH + koff);
                    bL[2 * nh][0] = r0; bL[2 * nh][1] = r1; bL[2 * nh + 1][0] = r2; bL[2 * nh + 1][1] = r3;
                }
#pragma unroll
                for (int mf = 0; mf < 4; mf++)
                    LDSM_X4(af[mf][0], af[mf][1], af[mf][2], af[mf][3],
                            base + 0 * TILEB + aOff + mf * 16 * PITCH + koff);
#pragma unroll
                for (int mf = 0; mf < 4; mf++)
#pragma unroll
                    for (int nf = 0; nf < 4; nf++)
                        mma_any<ISF16>(acc[mf][nf], af[mf][0], af[mf][1], af[mf][2], af[mf][3],
                                       bH[nf][0], bH[nf][1]);
#pragma unroll
                for (int mf = 0; mf < 4; mf++)
#pragma unroll
                    for (int nf = 0; nf < 4; nf++)
                        mma_any<ISF16>(acc[mf][nf], af[mf][0], af[mf][1], af[mf][2], af[mf][3],
                                       bL[nf][0], bL[nf][1]);
#pragma unroll
                for (int mf = 0; mf < 4; mf++)
                    LDSM_X4(af[mf][0], af[mf][1], af[mf][2], af[mf][3],
                            base + 1 * TILEB + aOff + mf * 16 * PITCH + koff);
#pragma unroll
                for (int mf = 0; mf < 4; mf++)
#pragma unroll
                    for (int nf = 0; nf < 4; nf++)
                        mma_any<ISF16>(acc[mf][nf], af[mf][0], af[mf][1], af[mf][2], af[mf][3],
                                       bH[nf][0], bH[nf][1]);
            } else {
                uint32_t bb[4][2], af[4][4];
#pragma unroll
                for (int nh = 0; nh < 2; nh++) {
                    uint32_t r0, r1, r2, r3;
                    LDSM_X4(r0, r1, r2, r3, base + 2 * TILEB + bOff + nh * 16 * PITCH + koff);
                    bb[2 * nh][0] = r0; bb[2 * nh][1] = r1; bb[2 * nh + 1][0] = r2; bb[2 * nh + 1][1] = r3;
                }
#pragma unroll
                for (int mf = 0; mf < 4; mf++)
                    LDSM_X4(af[mf][0], af[mf][1], af[mf][2], af[mf][3],
                            base + 0 * TILEB + aOff + mf * 16 * PITCH + koff);
#pragma unroll
                for (int mf = 0; mf < 4; mf++)
#pragma unroll
                    for (int nf = 0; nf < 4; nf++)
                        mma_any<ISF16>(acc[mf][nf], af[mf][0], af[mf][1], af[mf][2], af[mf][3],
                                       bb[nf][0], bb[nf][1]);
#pragma unroll
                for (int mf = 0; mf < 4; mf++)
                    LDSM_X4(af[mf][0], af[mf][1], af[mf][2], af[mf][3],
                            base + 1 * TILEB + aOff + mf * 16 * PITCH + koff);
#pragma unroll
                for (int mf = 0; mf < 4; mf++)
#pragma unroll
                    for (int nf = 0; nf < 4; nf++)
                        mma_any<ISF16>(acc[mf][nf], af[mf][0], af[mf][1], af[mf][2], af[mf][3],
                                       bb[nf][0], bb[nf][1]);
            }
        }
    }

    // ---- epilogue ----
#pragma unroll
    for (int mf = 0; mf < 4; mf++) {
#pragma unroll
        for (int nf = 0; nf < 4; nf++) {
            float* c = acc[mf][nf];
            int r0 = mBase + wm + mf * 16 + lq;
            int c0 = nBase + wn + nf * 8 + 2 * lr;
#pragma unroll
            for (int half = 0; half < 2; half++) {
                int r = r0 + half * 8;
                if (r >= Meff) continue;
                float v0 = c[half * 2 + 0], v1 = c[half * 2 + 1];
                if (EPI == 0) {
                    C[(size_t)r * ldc + c0] = v0;
                    C[(size_t)r * ldc + c0 + 1] = v1;
                } else if (EPI == 1) {
                    float o0 = v0 + aux0[(size_t)r * ldc + c0] + aux1[c0];
                    float o1 = v1 + aux0[(size_t)r * ldc + c0 + 1] + aux1[c0 + 1];
                    C[(size_t)r * ldc + c0] = o0;  C2[(size_t)r * ldc + c0] = o0;
                    C[(size_t)r * ldc + c0 + 1] = o1; C2[(size_t)r * ldc + c0 + 1] = o1;
                } else if (EPI == 3) {
                    int tok = out_idx[r];
                    float wgt = out_wt[r];
                    atomicAdd(&C[(size_t)tok * ldc + c0], wgt * v0);
                    atomicAdd(&C[(size_t)tok * ldc + c0 + 1], wgt * v1);
                } else {   // EPI == 4: RoPE on q,k pairs then store
                    int s = r & (SEQ - 1);
                    int sub = c0 % 192;
                    if (sub < 128) {
                        int d2 = (sub & 63) >> 1;
                        float cc = aux0[s * 32 + d2], sn = aux1[s * 32 + d2];
                        C[(size_t)r * ldc + c0]     = v0 * cc - v1 * sn;
                        C[(size_t)r * ldc + c0 + 1] = v0 * sn + v1 * cc;
                    } else {
                        C[(size_t)r * ldc + c0] = v0;
                        C[(size_t)r * ldc + c0 + 1] = v1;
                    }
                }
            }
        }
    }
}

// QKV: fp16 3-pass + fused RoPE
__global__ void __launch_bounds__(256, 2)
kan_gemm_qkv(const float* __restrict__ rc, const float* __restrict__ rs,
             float* __restrict__ qkv) {
    gemm_body<4, 3, 1>((const uint16_t*)g_phiH, (const uint16_t*)g_phiL, KAUG, nullptr,
                       (const uint16_t*)g_qkvwH, (const uint16_t*)g_qkvwL, KAUG,
                       qkv, 3072, TOK, KAUG, nullptr, rc, rs, nullptr, nullptr, nullptr);
}

// out-proj: bf16 3-pass, residual+bias dual store
__global__ void __launch_bounds__(256, 2)
kan_gemm_op(const float* __restrict__ x, const float* __restrict__ bias,
            float* __restrict__ x2, float* __restrict__ out) {
    gemm_body<1, 3, 0>((const uint16_t*)g_ctxH, (const uint16_t*)g_ctxL, HID, nullptr,
                       (const uint16_t*)g_owH, (const uint16_t*)g_owL, HID,
                       x2, HID, TOK, HID, nullptr, x, bias, out, nullptr, nullptr);
}

// batched w1+w2: fp16 2-pass (B single)
__global__ void __launch_bounds__(256, 2)
kan_gemm_w12() {
    int z = blockIdx.z, e = z >> 1, sel = z & 1;
    const uint16_t* B = (const uint16_t*)((sel ? g_w2F : g_w1F) + (size_t)e * DFF * KAUG);
    float* C = (sel ? g_t2 : g_t1) + (size_t)e * TOK * DFF;
    gemm_body<0, 2, 1>((const uint16_t*)g_phiH, (const uint16_t*)g_phiL, KAUG,
                       g_eidx + e * TOK, B, nullptr, KAUG,
                       C, DFF, TOK, KAUG, g_cnt + e, nullptr, nullptr, nullptr, nullptr, nullptr);
}

// batched w3: bf16 3-pass, atomic scatter
__global__ void __launch_bounds__(256, 2)
kan_gemm_w3(float* __restrict__ out) {
    int e = blockIdx.z;
    gemm_body<3, 3, 0>((const uint16_t*)(g_phitH + (size_t)e * TOK * KAUG),
                       (const uint16_t*)(g_phitL + (size_t)e * TOK * KAUG), KAUG, nullptr,
                       (const uint16_t*)(g_w3H + (size_t)e * HID * KAUG),
                       (const uint16_t*)(g_w3L + (size_t)e * HID * KAUG), KAUG,
                       out, HID, TOK, KAUG, g_cnt + e, nullptr, nullptr, nullptr,
                       g_eidx + e * TOK, g_ew + e * TOK);
}

// ---------------- flash attention (writes ctx as bf16 hi/lo) ------------------------
#define FA_STRIDE 68
#define FA_TILE   (64 * FA_STRIDE)
__global__ void flash_attn_kernel(const float* __restrict__ qkv,
                                  __nv_bfloat16* __restrict__ ctxH,
                                  __nv_bfloat16* __restrict__ ctxL) {
    extern __shared__ float smem[];
    float* Qs   = smem;
    float* Ks   = Qs + FA_TILE;
    float* Ss   = Ks + FA_TILE;
    float* Vs   = Ss + FA_TILE;
    float* Pred = Vs + FA_TILE;

    int qt = blockIdx.x, bh = blockIdx.y;
    int b = bh >> 4, h = bh & 15;
    int tid = threadIdx.x;
    int r  = tid >> 2;
    int c4 = (tid & 3) * 16;
    int q0 = (tid >> 4) * 4;
    int kc0 = (tid & 15) * 4;
    int pcol = tid & 15;

    const float* qbase = qkv + (size_t)(b * SEQ + qt * 64 + r) * 3072 + h * 192;
#pragma unroll
    for (int u = 0; u < 4; u++) {
        float4 qv = *(const float4*)(qbase + c4 + u * 4);
        Qs[(c4 + u * 4 + 0) * FA_STRIDE + r] = qv.x;
        Qs[(c4 + u * 4 + 1) * FA_STRIDE + r] = qv.y;
        Qs[(c4 + u * 4 + 2) * FA_STRIDE + r] = qv.z;
        Qs[(c4 + u * 4 + 3) * FA_STRIDE + r] = qv.w;
    }

    float o[4][4];
    float m_i[4], l_i[4];
#pragma unroll
    for (int i = 0; i < 4; i++) {
        m_i[i] = -1e30f; l_i[i] = 0.f;
#pragma unroll
        for (int j = 0; j < 4; j++) o[i][j] = 0.f;
    }

    for (int kt = 0; kt < SEQ / 64; kt++) {
        __syncthreads();
        const float* kbase = qkv + (size_t)(b * SEQ + kt * 64 + r) * 3072 + h * 192 + 64;
        const float* vbase = kbase + 64;
#pragma unroll
        for (int u = 0; u < 4; u++) {
            float4 kv = *(const float4*)(kbase + c4 + u * 4);
            Ks[(c4 + u * 4 + 0) * FA_STRIDE + r] = kv.x;
            Ks[(c4 + u * 4 + 1) * FA_STRIDE + r] = kv.y;
            Ks[(c4 + u * 4 + 2) * FA_STRIDE + r] = kv.z;
            Ks[(c4 + u * 4 + 3) * FA_STRIDE + r] = kv.w;
            *(float4*)&Vs[r * FA_STRIDE + c4 + u * 4] = *(const float4*)(vbase + c4 + u * 4);
        }
        __syncthreads();

        float s[4][4];
#pragma unroll
        for (int i = 0; i < 4; i++)
#pragma unroll
            for (int j = 0; j < 4; j++) s[i][j] = 0.f;
#pragma unroll 8
        for (int d = 0; d < 64; d++) {
            float a0[4], b0[4];
            *(float4*)a0 = *(const float4*)&Qs[d * FA_STRIDE + q0];
            *(float4*)b0 = *(const float4*)&Ks[d * FA_STRIDE + kc0];
#pragma unroll
            for (int i = 0; i < 4; i++)
#pragma unroll
                for (int j = 0; j < 4; j++) s[i][j] += a0[i] * b0[j];
        }
#pragma unroll
        for (int i = 0; i < 4; i++)
#pragma unroll
            for (int j = 0; j < 4; j++) s[i][j] *= 0.125f;

#pragma unroll
        for (int i = 0; i < 4; i++) {
            float pm = fmaxf(fmaxf(s[i][0], s[i][1]), fmaxf(s[i][2], s[i][3]));
            Pred[(q0 + i) * 20 + pcol] = pm;
        }
        __syncthreads();
        float mnew[4], corr[4];
#pragma unroll
        for (int i = 0; i < 4; i++) {
            float mx = m_i[i];
            const float* pr = &Pred[(q0 + i) * 20];
#pragma unroll
            for (int t = 0; t < 16; t++) mx = fmaxf(mx, pr[t]);
            mnew[i] = mx;
            corr[i] = expf(m_i[i] - mx);
            m_i[i] = mx;
        }
        __syncthreads();

#pragma unroll
        for (int i = 0; i < 4; i++) {
            float ps = 0.f;
#pragma unroll
            for (int j = 0; j < 4; j++) {
                float p = expf(s[i][j] - mnew[i]);
                Ss[(q0 + i) * FA_STRIDE + kc0 + j] = p;
                ps += p;
            }
            Pred[(q0 + i) * 20 + pcol] = ps;
        }
        __syncthreads();

#pragma unroll
        for (int i = 0; i < 4; i++) {
            float rs = 0.f;
            const float* pr = &Pred[(q0 + i) * 20];
#pragma unroll
            for (int t = 0; t < 16; t++) rs += pr[t];
            l_i[i] = corr[i] * l_i[i] + rs;
#pragma unroll
            for (int j = 0; j < 4; j++) o[i][j] *= corr[i];
        }

#pragma unroll 8
        for (int kk = 0; kk < 64; kk++) {
            float a0[4], b0[4];
            a0[0] = Ss[(q0 + 0) * FA_STRIDE + kk];
            a0[1] = Ss[(q0 + 1) * FA_STRIDE + kk];
            a0[2] = Ss[(q0 + 2) * FA_STRIDE + kk];
            a0[3] = Ss[(q0 + 3) * FA_STRIDE + kk];
            *(float4*)b0 = *(const float4*)&Vs[kk * FA_STRIDE + kc0];
#pragma unroll
            for (int i = 0; i < 4; i++)
#pragma unroll
                for (int j = 0; j < 4; j++) o[i][j] += a0[i] * b0[j];
        }
    }

#pragma unroll
    for (int i = 0; i < 4; i++) {
        float inv = 1.0f / l_i[i];
#pragma unroll
        for (int j = 0; j < 4; j++) {
            size_t off = (size_t)(b * SEQ + qt * 64 + q0 + i) * HID + h * 64 + kc0 + j;
            __nv_bfloat16 hh, ll;
            hl_pair(o[i][j] * inv, hh, ll);
            ctxH[off] = hh; ctxL[off] = ll;
        }
    }
}

// ---------------- MoE routing -----------------------------------------------------
__global__ void init_cnt_kernel() {
    if (threadIdx.x < NEXP) g_cnt[threadIdx.x] = 0;
}

__global__ void routing_kernel() {
    int m = blockIdx.x * 256 + threadIdx.x;
    if (m >= TOK) return;
    float l[4];
#pragma unroll
    for (int e = 0; e < 4; e++) l[e] = g_logits[m * 4 + e];
    int i0 = 0; float b0 = l[0];
#pragma unroll
    for (int e = 1; e < 4; e++) if (l[e] > b0) { b0 = l[e]; i0 = e; }
    int i1 = -1; float b1 = -1e30f;
#pragma unroll
    for (int e = 0; e < 4; e++) if (e != i0 && l[e] > b1) { b1 = l[e]; i1 = e; }
    float t = expf(b1 - b0);
    float w0 = 1.0f / (1.0f + t);
    float w1 = t / (1.0f + t);
    int p0 = atomicAdd(&g_cnt[i0], 1);
    g_eidx[i0 * TOK + p0] = m; g_ew[i0 * TOK + p0] = w0;
    int p1 = atomicAdd(&g_cnt[i1], 1);
    g_eidx[i1 * TOK + p1] = m; g_ew[i1 * TOK + p1] = w1;
}

// ---------------- host orchestration ----------------------------------------------
extern "C" void kernel_launch(void* const* d_in, const int* in_sizes, int n_in,
                              void* d_out, int out_size) {
    const float* x          = (const float*)d_in[0];
    const float* rot_cos    = (const float*)d_in[1];
    const float* rot_sin    = (const float*)d_in[2];
    const float* norm1_w    = (const float*)d_in[3];
    const float* norm2_w    = (const float*)d_in[4];
    const float* qkv_base   = (const float*)d_in[5];
    const float* qkv_spline = (const float*)d_in[6];
    const float* qkv_scaler = (const float*)d_in[7];
    const float* out_w      = (const float*)d_in[8];
    const float* out_b      = (const float*)d_in[9];
    const float* gate_w     = (const float*)d_in[10];
    const float* w1_base    = (const float*)d_in[11];
    const float* w1_spline  = (const float*)d_in[12];
    const float* w1_scaler  = (const float*)d_in[13];
    const float* w2_base    = (const float*)d_in[14];
    const float* w2_spline  = (const float*)d_in[15];
    const float* w2_scaler  = (const float*)d_in[16];
    const float* w3_base    = (const float*)d_in[17];
    const float* w3_spline  = (const float*)d_in[18];
    const float* w3_scaler  = (const float*)d_in[19];
    float* out = (float*)d_out;

    __half *phiH, *phiL, *qwH, *qwL, *w1F, *w2F;
    __nv_bfloat16 *ctxH, *ctxL, *w3H, *w3L, *owH, *owL;
    float *qkv, *x2, *logits;
    cudaGetSymbolAddress((void**)&phiH, g_phiH);   cudaGetSymbolAddress((void**)&phiL, g_phiL);
    cudaGetSymbolAddress((void**)&ctxH, g_ctxH);   cudaGetSymbolAddress((void**)&ctxL, g_ctxL);
    cudaGetSymbolAddress((void**)&qwH, g_qkvwH);   cudaGetSymbolAddress((void**)&qwL, g_qkvwL);
    cudaGetSymbolAddress((void**)&w1F, g_w1F);     cudaGetSymbolAddress((void**)&w2F, g_w2F);
    cudaGetSymbolAddress((void**)&w3H, g_w3H);     cudaGetSymbolAddress((void**)&w3L, g_w3L);
    cudaGetSymbolAddress((void**)&owH, g_owH);     cudaGetSymbolAddress((void**)&owL, g_owL);
    cudaGetSymbolAddress((void**)&qkv, g_qkv);     cudaGetSymbolAddress((void**)&x2, g_x2);
    cudaGetSymbolAddress((void**)&logits, g_logits);

    const int fa_smem = (4 * FA_TILE + 64 * 20) * sizeof(float);
    cudaFuncSetAttribute(flash_attn_kernel, cudaFuncAttributeMaxDynamicSharedMemorySize, fa_smem);
    cudaFuncSetAttribute(kan_gemm_qkv, cudaFuncAttributeMaxDynamicSharedMemorySize, GM_DYN3);
    cudaFuncSetAttribute(kan_gemm_op,  cudaFuncAttributeMaxDynamicSharedMemorySize, GM_DYN3);
    cudaFuncSetAttribute(kan_gemm_w12, cudaFuncAttributeMaxDynamicSharedMemorySize, GM_DYN2);
    cudaFuncSetAttribute(kan_gemm_w3,  cudaFuncAttributeMaxDynamicSharedMemorySize, GM_DYN3);

    // 0) weight conversion
    conv_kan_w_h<<<3072, 256>>>(qkv_base, qkv_spline, qkv_scaler, HID, qwH, qwL);
    conv_kan_w_h1<<<NEXP * DFF, 256>>>(w1_base, w1_spline, w1_scaler, HID, w1F);
    conv_kan_w_h1<<<NEXP * DFF, 256>>>(w2_base, w2_spline, w2_scaler, HID, w2F);
    conv_kan_w<<<NEXP * HID, 256>>>(w3_base, w3_spline, w3_scaler, DFF, w3H, w3L);
    conv_plain<<<(HID * HID + 255) / 256, 256>>>(out_w, owH, owL, HID * HID);

    // 1) rmsnorm(x) -> phi fp16 hi/lo
    rmsnorm_phi_kernel<<<TOK, 256>>>(x, norm1_w, phiH, phiL, nullptr, nullptr);

    // 2) QKV = phi @ Waug^T with fused RoPE
    kan_gemm_qkv<<<dim3(3072 / 128, TOK / 128), 256, GM_DYN3>>>(rot_cos, rot_sin, qkv);

    // 3) attention
    flash_attn_kernel<<<dim3(SEQ / 64, BATCH * NHEAD), 256, fa_smem>>>(qkv, ctxH, ctxL);

    // 4) x2 = x + ctx @ out_w^T + out_b (dual store into d_out)
    kan_gemm_op<<<dim3(HID / 128, TOK / 128), 256, GM_DYN3>>>(x, out_b, x2, out);

    // 5) rmsnorm(x2) -> phi fp16 hi/lo, gate logits
    rmsnorm_phi_kernel<<<TOK, 256>>>(x2, norm2_w, phiH, phiL, gate_w, logits);

    // 6) routing
    init_cnt_kernel<<<1, 32>>>();
    routing_kernel<<<TOK / 256, 256>>>();

    // 7) MoE batched
    kan_gemm_w12<<<dim3(DFF / 128, TOK / 128, 2 * NEXP), 256, GM_DYN2>>>();
    mul_phi_kernel<<<dim3(TOK, NEXP), 256>>>();
    kan_gemm_w3<<<dim3(HID / 128, TOK / 128, NEXP), 256, GM_DYN3>>>(out);
}

// round 11
// speedup vs baseline: 7.9791x; 1.1547x over previous
#include <cuda_runtime.h>
#include <cuda_bf16.h>
#include <cuda_fp16.h>
#include <math.h>
#include <stdint.h>

#define TOK   2048      // B*S
#define HID   1024
#define KAUG  9216      // H*(1+NB)
#define NB    8
#define NHEAD 16
#define HDIM  64
#define SEQ   1024
#define BATCH 2
#define DFF   1024
#define NEXP  4

// ---------------- scratch (static device globals; no runtime alloc) ----------------
__device__ __align__(16) __half        g_phiH[(size_t)TOK * KAUG];   // fp16 hi
__device__ __align__(16) __half        g_phiL[(size_t)TOK * KAUG];   // fp16 lo
__device__ __align__(16) __half        g_phitH[(size_t)NEXP * TOK * KAUG];
__device__ __align__(16) __half        g_phitL[(size_t)NEXP * TOK * KAUG];
__device__ __align__(16) __nv_bfloat16 g_ctxH[(size_t)TOK * HID];
__device__ __align__(16) __nv_bfloat16 g_ctxL[(size_t)TOK * HID];
__device__ __align__(16) __half        g_qkvwF[(size_t)3072 * KAUG];      // single fp16
__device__ __align__(16) __half        g_w1F[(size_t)NEXP * DFF * KAUG];  // single fp16
__device__ __align__(16) __half        g_w2F[(size_t)NEXP * DFF * KAUG];  // single fp16
__device__ __align__(16) __half        g_w3F[(size_t)NEXP * HID * KAUG];  // single fp16
__device__ __align__(16) __nv_bfloat16 g_owH[(size_t)HID * HID];
__device__ __align__(16) __nv_bfloat16 g_owL[(size_t)HID * HID];

__device__ float g_qkv[(size_t)TOK * 3 * HID];
__device__ float g_x2[(size_t)TOK * HID];
__device__ float g_t1[(size_t)NEXP * TOK * DFF];
__device__ float g_t2[(size_t)NEXP * TOK * DFF];
__device__ float g_logits[TOK * NEXP];
__device__ int   g_cnt[NEXP];
__device__ int   g_eidx[NEXP * TOK];
__device__ float g_ew[NEXP * TOK];

// ---------------- helpers ----------------------------------------------------------
__device__ __forceinline__ uint32_t smem_u32(const void* p) {
    uint32_t a;
    asm("{ .reg .u64 t; cvta.to.shared.u64 t, %1; cvt.u32.u64 %0, t; }" : "=r"(a) : "l"(p));
    return a;
}

__device__ __forceinline__ void hl_pair(float v, __nv_bfloat16& h, __nv_bfloat16& l) {
    h = __float2bfloat16_rn(v);
    l = __float2bfloat16_rn(v - __bfloat162float(h));
}
__device__ __forceinline__ void hl_pair_h(float v, __half& h, __half& l) {
    h = __float2half_rn(v);
    l = __float2half_rn(v - __half2float(h));
}

template <int ISF16>
__device__ __forceinline__ void mma_any(float* c, uint32_t a0, uint32_t a1, uint32_t a2,
                                        uint32_t a3, uint32_t b0, uint32_t b1) {
    if (ISF16) {
        asm volatile(
            "mma.sync.aligned.m16n8k16.row.col.f32.f16.f16.f32 "
            "{%0,%1,%2,%3}, {%4,%5,%6,%7}, {%8,%9}, {%0,%1,%2,%3};\n"
            : "+f"(c[0]), "+f"(c[1]), "+f"(c[2]), "+f"(c[3])
            : "r"(a0), "r"(a1), "r"(a2), "r"(a3), "r"(b0), "r"(b1));
    } else {
        asm volatile(
            "mma.sync.aligned.m16n8k16.row.col.f32.bf16.bf16.f32 "
            "{%0,%1,%2,%3}, {%4,%5,%6,%7}, {%8,%9}, {%0,%1,%2,%3};\n"
            : "+f"(c[0]), "+f"(c[1]), "+f"(c[2]), "+f"(c[3])
            : "r"(a0), "r"(a1), "r"(a2), "r"(a3), "r"(b0), "r"(b1));
    }
}

#define LDSM_X4(r0, r1, r2, r3, addr) \
    asm volatile("ldmatrix.sync.aligned.m8n8.x4.shared.b16 {%0,%1,%2,%3}, [%4];" \
                 : "=r"(r0), "=r"(r1), "=r"(r2), "=r"(r3) : "r"(addr))

// ---------------- cubic B-spline bases --------------------------------------------
__device__ __forceinline__ void bspline8(float v, float* out) {
    float b[11];
#pragma unroll
    for (int t = 0; t < 11; t++) {
        float g0 = 0.4f * (t - 3) - 1.0f;
        float g1 = 0.4f * (t - 2) - 1.0f;
        b[t] = (v >= g0 && v < g1) ? 1.0f : 0.0f;
    }
#pragma unroll
    for (int j = 1; j <= 3; j++) {
        float inv = 1.0f / (0.4f * (float)j);
#pragma unroll
        for (int t = 0; t < 10; t++) {
            if (t < 11 - j) {
                float gt   = 0.4f * (t - 3) - 1.0f;
                float gtj1 = 0.4f * (t + j - 2) - 1.0f;
                b[t] = (v - gt) * inv * b[t] + (gtj1 - v) * inv * b[t + 1];
            }
        }
    }
#pragma unroll
    for (int c = 0; c < 8; c++) out[c] = b[c];
}

// ---------------- weight conversion kernels ----------------------------------------
// single fp16, scaler folded (qkv, w1, w2, w3 — 2-pass B operand)
__global__ void conv_kan_w_h1(const float* __restrict__ base, const float* __restrict__ spline,
                              const float* __restrict__ scaler, int Kin,
                              __half* __restrict__ W) {
    int o = blockIdx.x;
    int KA = Kin * 9;
    const float* brow = base + (size_t)o * Kin;
    const float* srow = spline + (size_t)o * Kin * 8;
    const float* crow = scaler + (size_t)o * Kin;
    __half* row = W + (size_t)o * KA;
    for (int c = threadIdx.x; c < Kin; c += 256)
        row[c] = __float2half_rn(brow[c]);
    for (int c = threadIdx.x; c < Kin * 8; c += 256)
        row[Kin + c] = __float2half_rn(srow[c] * crow[c >> 3]);
}

__global__ void conv_plain(const float* __restrict__ W,
                           __nv_bfloat16* __restrict__ WH, __nv_bfloat16* __restrict__ WL,
                           int total) {
    int i = blockIdx.x * 256 + threadIdx.x;
    if (i < total) {
        __nv_bfloat16 h, l;
        hl_pair(W[i], h, l);
        WH[i] = h; WL[i] = l;
    }
}

// ---------------- rmsnorm + phi (fp16 hi/lo) + optional gate logits ----------------
__global__ void rmsnorm_phi_kernel(const float* __restrict__ x,
                                   const float* __restrict__ w,
                                   __half* __restrict__ phiH,
                                   __half* __restrict__ phiL,
                                   const float* __restrict__ gate_w,
                                   float* __restrict__ logits) {
    int m = blockIdx.x;
    int tid = threadIdx.x;
    __shared__ float sx[HID];
    __shared__ float sred[256];
    const float* xr = x + (size_t)m * HID;
    float ss = 0.f;
    for (int f = tid; f < HID; f += 256) { float v = xr[f]; sx[f] = v; ss += v * v; }
    sred[tid] = ss; __syncthreads();
    for (int o = 128; o > 0; o >>= 1) { if (tid < o) sred[tid] += sred[tid + o]; __syncthreads(); }
    float rms = rsqrtf(sred[0] / (float)HID + 1e-6f);
    float gacc[4] = {0.f, 0.f, 0.f, 0.f};
    __half* ph = phiH + (size_t)m * KAUG;
    __half* pl = phiL + (size_t)m * KAUG;
    for (int f = tid; f < HID; f += 256) {
        float hn = sx[f] * rms * w[f];
        __half h, l;
        hl_pair_h(hn / (1.0f + expf(-hn)), h, l);
        ph[f] = h; pl[f] = l;
        float bs[8];
        bspline8(hn, bs);
#pragma unroll
        for (int c = 0; c < 8; c++) {
            hl_pair_h(bs[c], h, l);
            ph[HID + f * 8 + c] = h; pl[HID + f * 8 + c] = l;
        }
        if (gate_w) {
#pragma unroll
            for (int e = 0; e < 4; e++) gacc[e] += hn * gate_w[e * HID + f];
        }
    }
    if (gate_w) {
#pragma unroll
        for (int e = 0; e < 4; e++) {
            __syncthreads();
            sred[tid] = gacc[e]; __syncthreads();
            for (int o = 128; o > 0; o >>= 1) { if (tid < o) sred[tid] += sred[tid + o]; __syncthreads(); }
            if (tid == 0) logits[m * 4 + e] = sred[0];
        }
    }
}

// ---------------- phi expansion of t1*t2, batched over experts (fp16 hi/lo) --------
__global__ void mul_phi_kernel() {
    int e = blockIdx.y;
    int r = blockIdx.x;
    if (r >= g_cnt[e]) return;
    int tid = threadIdx.x;
    const float* a = g_t1 + (size_t)e * TOK * DFF + (size_t)r * DFF;
    const float* b = g_t2 + (size_t)e * TOK * DFF + (size_t)r * DFF;
    __half* ph = g_phitH + (size_t)e * TOK * KAUG + (size_t)r * KAUG;
    __half* pl = g_phitL + (size_t)e * TOK * KAUG + (size_t)r * KAUG;
    for (int f = tid; f < DFF; f += 256) {
        float v = a[f] * b[f];
        __half h, l;
        hl_pair_h(v / (1.0f + expf(-v)), h, l);
        ph[f] = h; pl[f] = l;
        float bs[8];
        bspline8(v, bs);
#pragma unroll
        for (int c = 0; c < 8; c++) {
            hl_pair_h(bs[c], h, l);
            ph[DFF + f * 8 + c] = h; pl[DFF + f * 8 + c] = l;
        }
    }
}

// ---------------- tensor-core GEMM body --------------------------------------------
// PASSES=3: tiles AH AL BH BL; AhBh + AhBl + AlBh.
// PASSES=2: tiles AH AL B;     AhB  + AlB   (B single-rounded fp16).
// EPI 0: plain. EPI 1: +res+bias dual store. EPI 3: atomic scatter. EPI 4: RoPE store.
#define PITCH  80
#define TILEB  (128 * PITCH)
#define GM_DYN3 (512 + 2 * 4 * TILEB)
#define GM_DYN2 (512 + 2 * 3 * TILEB)

template <int EPI, int PASSES, int ISF16>
__device__ __forceinline__ void gemm_body(
    const uint16_t* __restrict__ AH, const uint16_t* __restrict__ AL,
    int lda, const int* __restrict__ a_idx,
    const uint16_t* __restrict__ BH, const uint16_t* __restrict__ BL, int ldb,
    float* __restrict__ C, int ldc, int M, int K,
    const int* __restrict__ cnt,
    const float* __restrict__ aux0, const float* __restrict__ aux1, float* __restrict__ C2,
    const int* __restrict__ out_idx, const float* __restrict__ out_wt) {
    const int NT = (PASSES == 3) ? 4 : 3;
    const uint32_t STAGEB = (uint32_t)NT * TILEB;

    int Meff = cnt ? *cnt : M;
    int mBase = blockIdx.y * 128;
    int nBase = blockIdx.x * 128;
    if (mBase >= Meff) return;

    extern __shared__ char sm[];
    int* rowmap = (int*)sm;
    uint32_t bufs_u = smem_u32(sm + 512);
    int tid = threadIdx.x;

    if (tid < 128) {
        int r = mBase + tid;
        int g = (r < Meff) ? r : mBase;
        rowmap[tid] = a_idx ? a_idx[g] : g;
    }
    __syncthreads();

    int w = tid >> 5, l = tid & 31;
    int wm = (w >> 2) * 64;
    int wn = (w & 3) * 32;
    int lq = l >> 2, lr = l & 3;
    uint32_t aOff = (uint32_t)(wm + (l & 15)) * PITCH + ((l >> 4) ? 16u : 0u);
    uint32_t bOff = (uint32_t)(wn + (l & 7) + ((l & 16) ? 8 : 0)) * PITCH + ((l & 8) ? 16u : 0u);

    float acc[4][4][4];
#pragma unroll
    for (int mf = 0; mf < 4; mf++)
#pragma unroll
        for (int nf = 0; nf < 4; nf++)
#pragma unroll
            for (int t = 0; t < 4; t++) acc[mf][nf][t] = 0.f;

    auto issue = [&](int s, int k0) {
#pragma unroll
        for (int it = 0; it < 2 * NT; it++) {
            int i = it * 256 + tid;
            int tens = i >> 9;
            int rem = i & 511;
            int row = rem >> 2;
            int seg = rem & 3;
            const uint16_t* src;
            if (tens == 0)      src = AH + (size_t)rowmap[row] * lda + k0 + 8 * seg;
            else if (tens == 1) src = AL + (size_t)rowmap[row] * lda + k0 + 8 * seg;
            else if (tens == 2) src = BH + (size_t)(nBase + row) * ldb + k0 + 8 * seg;
            else                src = BL + (size_t)(nBase + row) * ldb + k0 + 8 * seg;
            uint32_t dst = bufs_u + (uint32_t)s * STAGEB + (uint32_t)tens * TILEB +
                           (uint32_t)row * PITCH + (uint32_t)seg * 16;
            asm volatile("cp.async.cg.shared.global [%0], [%1], 16;" :: "r"(dst), "l"(src) : "memory");
        }
        asm volatile("cp.async.commit_group;" ::: "memory");
    };

    int nStages = K / 32;
    issue(0, 0);
    for (int ck = 0; ck < nStages; ck++) {
        if (ck) __syncthreads();
        bool pre = (ck + 1 < nStages);
        if (pre) issue((ck + 1) & 1, (ck + 1) * 32);
        if (pre) asm volatile("cp.async.wait_group 1;" ::: "memory");
        else     asm volatile("cp.async.wait_group 0;" ::: "memory");
        __syncthreads();

        uint32_t base = bufs_u + (uint32_t)(ck & 1) * STAGEB;
#pragma unroll
        for (int p = 0; p < 2; p++) {
            uint32_t koff = 32u * p;
            if (PASSES == 3) {
                uint32_t bH[4][2], bL[4][2], af[4][4];
#pragma unroll
                for (int nh = 0; nh < 2; nh++) {
                    uint32_t r0, r1, r2, r3;
                    LDSM_X4(r0, r1, r2, r3, base + 2 * TILEB + bOff + nh * 16 * PITCH + koff);
                    bH[2 * nh][0] = r0; bH[2 * nh][1] = r1; bH[2 * nh + 1][0] = r2; bH[2 * nh + 1][1] = r3;
                    LDSM_X4(r0, r1, r2, r3, base + 3 * TILEB + bOff + nh * 16 * PITCH + koff);
                    bL[2 * nh][0] = r0; bL[2 * nh][1] = r1; bL[2 * nh + 1][0] = r2; bL[2 * nh + 1][1] = r3;
                }
#pragma unroll
                for (int mf = 0; mf < 4; mf++)
                    LDSM_X4(af[mf][0], af[mf][1], af[mf][2], af[mf][3],
                            base + 0 * TILEB + aOff + mf * 16 * PITCH + koff);
#pragma unroll
                for (int mf = 0; mf < 4; mf++)
#pragma unroll
                    for (int nf = 0; nf < 4; nf++)
                        mma_any<ISF16>(acc[mf][nf], af[mf][0], af[mf][1], af[mf][2], af[mf][3],
                                       bH[nf][0], bH[nf][1]);
#pragma unroll
                for (int mf = 0; mf < 4; mf++)
#pragma unroll
                    for (int nf = 0; nf < 4; nf++)
                        mma_any<ISF16>(acc[mf][nf], af[mf][0], af[mf][1], af[mf][2], af[mf][3],
                                       bL[nf][0], bL[nf][1]);
#pragma unroll
                for (int mf = 0; mf < 4; mf++)
                    LDSM_X4(af[mf][0], af[mf][1], af[mf][2], af[mf][3],
                            base + 1 * TILEB + aOff + mf * 16 * PITCH + koff);
#pragma unroll
                for (int mf = 0; mf < 4; mf++)
#pragma unroll
                    for (int nf = 0; nf < 4; nf++)
                        mma_any<ISF16>(acc[mf][nf], af[mf][0], af[mf][1], af[mf][2], af[mf][3],
                                       bH[nf][0], bH[nf][1]);
            } else {
                uint32_t bb[4][2], af[4][4];
#pragma unroll
                for (int nh = 0; nh < 2; nh++) {
                    uint32_t r0, r1, r2, r3;
                    LDSM_X4(r0, r1, r2, r3, base + 2 * TILEB + bOff + nh * 16 * PITCH + koff);
                    bb[2 * nh][0] = r0; bb[2 * nh][1] = r1; bb[2 * nh + 1][0] = r2; bb[2 * nh + 1][1] = r3;
                }
#pragma unroll
                for (int mf = 0; mf < 4; mf++)
                    LDSM_X4(af[mf][0], af[mf][1], af[mf][2], af[mf][3],
                            base + 0 * TILEB + aOff + mf * 16 * PITCH + koff);
#pragma unroll
                for (int mf = 0; mf < 4; mf++)
#pragma unroll
                    for (int nf = 0; nf < 4; nf++)
                        mma_any<ISF16>(acc[mf][nf], af[mf][0], af[mf][1], af[mf][2], af[mf][3],
                                       bb[nf][0], bb[nf][1]);
#pragma unroll
                for (int mf = 0; mf < 4; mf++)
                    LDSM_X4(af[mf][0], af[mf][1], af[mf][2], af[mf][3],
                            base + 1 * TILEB + aOff + mf * 16 * PITCH + koff);
#pragma unroll
                for (int mf = 0; mf < 4; mf++)
#pragma unroll
                    for (int nf = 0; nf < 4; nf++)
                        mma_any<ISF16>(acc[mf][nf], af[mf][0], af[mf][1], af[mf][2], af[mf][3],
                                       bb[nf][0], bb[nf][1]);
            }
        }
    }

    // ---- epilogue ----
#pragma unroll
    for (int mf = 0; mf < 4; mf++) {
#pragma unroll
        for (int nf = 0; nf < 4; nf++) {
            float* c = acc[mf][nf];
            int r0 = mBase + wm + mf * 16 + lq;
            int c0 = nBase + wn + nf * 8 + 2 * lr;
#pragma unroll
            for (int half = 0; half < 2; half++) {
                int r = r0 + half * 8;
                if (r >= Meff) continue;
                float v0 = c[half * 2 + 0], v1 = c[half * 2 + 1];
                if (EPI == 0) {
                    C[(size_t)r * ldc + c0] = v0;
                    C[(size_t)r * ldc + c0 + 1] = v1;
                } else if (EPI == 1) {
                    float o0 = v0 + aux0[(size_t)r * ldc + c0] + aux1[c0];
                    float o1 = v1 + aux0[(size_t)r * ldc + c0 + 1] + aux1[c0 + 1];
                    C[(size_t)r * ldc + c0] = o0;  C2[(size_t)r * ldc + c0] = o0;
                    C[(size_t)r * ldc + c0 + 1] = o1; C2[(size_t)r * ldc + c0 + 1] = o1;
                } else if (EPI == 3) {
                    int tok = out_idx[r];
                    float wgt = out_wt[r];
                    atomicAdd(&C[(size_t)tok * ldc + c0], wgt * v0);
                    atomicAdd(&C[(size_t)tok * ldc + c0 + 1], wgt * v1);
                } else {   // EPI == 4: RoPE on q,k pairs then store
                    int s = r & (SEQ - 1);
                    int sub = c0 % 192;
                    if (sub < 128) {
                        int d2 = (sub & 63) >> 1;
                        float cc = aux0[s * 32 + d2], sn = aux1[s * 32 + d2];
                        C[(size_t)r * ldc + c0]     = v0 * cc - v1 * sn;
                        C[(size_t)r * ldc + c0 + 1] = v0 * sn + v1 * cc;
                    } else {
                        C[(size_t)r * ldc + c0] = v0;
                        C[(size_t)r * ldc + c0 + 1] = v1;
                    }
                }
            }
        }
    }
}

// QKV: fp16 2-pass + fused RoPE
__global__ void __launch_bounds__(256, 2)
kan_gemm_qkv(const float* __restrict__ rc, const float* __restrict__ rs,
             float* __restrict__ qkv) {
    gemm_body<4, 2, 1>((const uint16_t*)g_phiH, (const uint16_t*)g_phiL, KAUG, nullptr,
                       (const uint16_t*)g_qkvwF, nullptr, KAUG,
                       qkv, 3072, TOK, KAUG, nullptr, rc, rs, nullptr, nullptr, nullptr);
}

// out-proj: bf16 3-pass, residual+bias dual store
__global__ void __launch_bounds__(256, 2)
kan_gemm_op(const float* __restrict__ x, const float* __restrict__ bias,
            float* __restrict__ x2, float* __restrict__ out) {
    gemm_body<1, 3, 0>((const uint16_t*)g_ctxH, (const uint16_t*)g_ctxL, HID, nullptr,
                       (const uint16_t*)g_owH, (const uint16_t*)g_owL, HID,
                       x2, HID, TOK, HID, nullptr, x, bias, out, nullptr, nullptr);
}

// batched w1+w2: fp16 2-pass (B single)
__global__ void __launch_bounds__(256, 2)
kan_gemm_w12() {
    int z = blockIdx.z, e = z >> 1, sel = z & 1;
    const uint16_t* B = (const uint16_t*)((sel ? g_w2F : g_w1F) + (size_t)e * DFF * KAUG);
    float* C = (sel ? g_t2 : g_t1) + (size_t)e * TOK * DFF;
    gemm_body<0, 2, 1>((const uint16_t*)g_phiH, (const uint16_t*)g_phiL, KAUG,
                       g_eidx + e * TOK, B, nullptr, KAUG,
                       C, DFF, TOK, KAUG, g_cnt + e, nullptr, nullptr, nullptr, nullptr, nullptr);
}

// batched w3: fp16 2-pass, atomic scatter
__global__ void __launch_bounds__(256, 2)
kan_gemm_w3(float* __restrict__ out) {
    int e = blockIdx.z;
    gemm_body<3, 2, 1>((const uint16_t*)(g_phitH + (size_t)e * TOK * KAUG),
                       (const uint16_t*)(g_phitL + (size_t)e * TOK * KAUG), KAUG, nullptr,
                       (const uint16_t*)(g_w3F + (size_t)e * HID * KAUG), nullptr, KAUG,
                       out, HID, TOK, KAUG, g_cnt + e, nullptr, nullptr, nullptr,
                       g_eidx + e * TOK, g_ew + e * TOK);
}

// ---------------- flash attention (writes ctx as bf16 hi/lo) ------------------------
#define FA_STRIDE 68
#define FA_TILE   (64 * FA_STRIDE)
__global__ void flash_attn_kernel(const float* __restrict__ qkv,
                                  __nv_bfloat16* __restrict__ ctxH,
                                  __nv_bfloat16* __restrict__ ctxL) {
    extern __shared__ float smem[];
    float* Qs   = smem;
    float* Ks   = Qs + FA_TILE;
    float* Ss   = Ks + FA_TILE;
    float* Vs   = Ss + FA_TILE;
    float* Pred = Vs + FA_TILE;

    int qt = blockIdx.x, bh = blockIdx.y;
    int b = bh >> 4, h = bh & 15;
    int tid = threadIdx.x;
    int r  = tid >> 2;
    int c4 = (tid & 3) * 16;
    int q0 = (tid >> 4) * 4;
    int kc0 = (tid & 15) * 4;
    int pcol = tid & 15;

    const float* qbase = qkv + (size_t)(b * SEQ + qt * 64 + r) * 3072 + h * 192;
#pragma unroll
    for (int u = 0; u < 4; u++) {
        float4 qv = *(const float4*)(qbase + c4 + u * 4);
        Qs[(c4 + u * 4 + 0) * FA_STRIDE + r] = qv.x;
        Qs[(c4 + u * 4 + 1) * FA_STRIDE + r] = qv.y;
        Qs[(c4 + u * 4 + 2) * FA_STRIDE + r] = qv.z;
        Qs[(c4 + u * 4 + 3) * FA_STRIDE + r] = qv.w;
    }

    float o[4][4];
    float m_i[4], l_i[4];
#pragma unroll
    for (int i = 0; i < 4; i++) {
        m_i[i] = -1e30f; l_i[i] = 0.f;
#pragma unroll
        for (int j = 0; j < 4; j++) o[i][j] = 0.f;
    }

    for (int kt = 0; kt < SEQ / 64; kt++) {
        __syncthreads();
        const float* kbase = qkv + (size_t)(b * SEQ + kt * 64 + r) * 3072 + h * 192 + 64;
        const float* vbase = kbase + 64;
#pragma unroll
        for (int u = 0; u < 4; u++) {
            float4 kv = *(const float4*)(kbase + c4 + u * 4);
            Ks[(c4 + u * 4 + 0) * FA_STRIDE + r] = kv.x;
            Ks[(c4 + u * 4 + 1) * FA_STRIDE + r] = kv.y;
            Ks[(c4 + u * 4 + 2) * FA_STRIDE + r] = kv.z;
            Ks[(c4 + u * 4 + 3) * FA_STRIDE + r] = kv.w;
            *(float4*)&Vs[r * FA_STRIDE + c4 + u * 4] = *(const float4*)(vbase + c4 + u * 4);
        }
        __syncthreads();

        float s[4][4];
#pragma unroll
        for (int i = 0; i < 4; i++)
#pragma unroll
            for (int j = 0; j < 4; j++) s[i][j] = 0.f;
#pragma unroll 8
        for (int d = 0; d < 64; d++) {
            float a0[4], b0[4];
            *(float4*)a0 = *(const float4*)&Qs[d * FA_STRIDE + q0];
            *(float4*)b0 = *(const float4*)&Ks[d * FA_STRIDE + kc0];
#pragma unroll
            for (int i = 0; i < 4; i++)
#pragma unroll
                for (int j = 0; j < 4; j++) s[i][j] += a0[i] * b0[j];
        }
#pragma unroll
        for (int i = 0; i < 4; i++)
#pragma unroll
            for (int j = 0; j < 4; j++) s[i][j] *= 0.125f;

#pragma unroll
        for (int i = 0; i < 4; i++) {
            float pm = fmaxf(fmaxf(s[i][0], s[i][1]), fmaxf(s[i][2], s[i][3]));
            Pred[(q0 + i) * 20 + pcol] = pm;
        }
        __syncthreads();
        float mnew[4], corr[4];
#pragma unroll
        for (int i = 0; i < 4; i++) {
            float mx = m_i[i];
            const float* pr = &Pred[(q0 + i) * 20];
#pragma unroll
            for (int t = 0; t < 16; t++) mx = fmaxf(mx, pr[t]);
            mnew[i] = mx;
            corr[i] = expf(m_i[i] - mx);
            m_i[i] = mx;
        }
        __syncthreads();

#pragma unroll
        for (int i = 0; i < 4; i++) {
            float ps = 0.f;
#pragma unroll
            for (int j = 0; j < 4; j++) {
                float p = expf(s[i][j] - mnew[i]);
                Ss[(q0 + i) * FA_STRIDE + kc0 + j] = p;
                ps += p;
            }
            Pred[(q0 + i) * 20 + pcol] = ps;
        }
        __syncthreads();

#pragma unroll
        for (int i = 0; i < 4; i++) {
            float rs = 0.f;
            const float* pr = &Pred[(q0 + i) * 20];
#pragma unroll
            for (int t = 0; t < 16; t++) rs += pr[t];
            l_i[i] = corr[i] * l_i[i] + rs;
#pragma unroll
            for (int j = 0; j < 4; j++) o[i][j] *= corr[i];
        }

#pragma unroll 8
        for (int kk = 0; kk < 64; kk++) {
            float a0[4], b0[4];
            a0[0] = Ss[(q0 + 0) * FA_STRIDE + kk];
            a0[1] = Ss[(q0 + 1) * FA_STRIDE + kk];
            a0[2] = Ss[(q0 + 2) * FA_STRIDE + kk];
            a0[3] = Ss[(q0 + 3) * FA_STRIDE + kk];
            *(float4*)b0 = *(const float4*)&Vs[kk * FA_STRIDE + kc0];
#pragma unroll
            for (int i = 0; i < 4; i++)
#pragma unroll
                for (int j = 0; j < 4; j++) o[i][j] += a0[i] * b0[j];
        }
    }

#pragma unroll
    for (int i = 0; i < 4; i++) {
        float inv = 1.0f / l_i[i];
#pragma unroll
        for (int j = 0; j < 4; j++) {
            size_t off = (size_t)(b * SEQ + qt * 64 + q0 + i) * HID + h * 64 + kc0 + j;
            __nv_bfloat16 hh, ll;
            hl_pair(o[i][j] * inv, hh, ll);
            ctxH[off] = hh; ctxL[off] = ll;
        }
    }
}

// ---------------- MoE routing -----------------------------------------------------
__global__ void init_cnt_kernel() {
    if (threadIdx.x < NEXP) g_cnt[threadIdx.x] = 0;
}

__global__ void routing_kernel() {
    int m = blockIdx.x * 256 + threadIdx.x;
    if (m >= TOK) return;
    float l[4];
#pragma unroll
    for (int e = 0; e < 4; e++) l[e] = g_logits[m * 4 + e];
    int i0 = 0; float b0 = l[0];
#pragma unroll
    for (int e = 1; e < 4; e++) if (l[e] > b0) { b0 = l[e]; i0 = e; }
    int i1 = -1; float b1 = -1e30f;
#pragma unroll
    for (int e = 0; e < 4; e++) if (e != i0 && l[e] > b1) { b1 = l[e]; i1 = e; }
    float t = expf(b1 - b0);
    float w0 = 1.0f / (1.0f + t);
    float w1 = t / (1.0f + t);
    int p0 = atomicAdd(&g_cnt[i0], 1);
    g_eidx[i0 * TOK + p0] = m; g_ew[i0 * TOK + p0] = w0;
    int p1 = atomicAdd(&g_cnt[i1], 1);
    g_eidx[i1 * TOK + p1] = m; g_ew[i1 * TOK + p1] = w1;
}

// ---------------- host orchestration ----------------------------------------------
extern "C" void kernel_launch(void* const* d_in, const int* in_sizes, int n_in,
                              void* d_out, int out_size) {
    const float* x          = (const float*)d_in[0];
    const float* rot_cos    = (const float*)d_in[1];
    const float* rot_sin    = (const float*)d_in[2];
    const float* norm1_w    = (const float*)d_in[3];
    const float* norm2_w    = (const float*)d_in[4];
    const float* qkv_base   = (const float*)d_in[5];
    const float* qkv_spline = (const float*)d_in[6];
    const float* qkv_scaler = (const float*)d_in[7];
    const float* out_w      = (const float*)d_in[8];
    const float* out_b      = (const float*)d_in[9];
    const float* gate_w     = (const float*)d_in[10];
    const float* w1_base    = (const float*)d_in[11];
    const float* w1_spline  = (const float*)d_in[12];
    const float* w1_scaler  = (const float*)d_in[13];
    const float* w2_base    = (const float*)d_in[14];
    const float* w2_spline  = (const float*)d_in[15];
    const float* w2_scaler  = (const float*)d_in[16];
    const float* w3_base    = (const float*)d_in[17];
    const float* w3_spline  = (const float*)d_in[18];
    const float* w3_scaler  = (const float*)d_in[19];
    float* out = (float*)d_out;

    __half *phiH, *phiL, *qwF, *w1F, *w2F, *w3F;
    __nv_bfloat16 *ctxH, *ctxL, *owH, *owL;
    float *qkv, *x2, *logits;
    cudaGetSymbolAddress((void**)&phiH, g_phiH);   cudaGetSymbolAddress((void**)&phiL, g_phiL);
    cudaGetSymbolAddress((void**)&ctxH, g_ctxH);   cudaGetSymbolAddress((void**)&ctxL, g_ctxL);
    cudaGetSymbolAddress((void**)&qwF, g_qkvwF);
    cudaGetSymbolAddress((void**)&w1F, g_w1F);     cudaGetSymbolAddress((void**)&w2F, g_w2F);
    cudaGetSymbolAddress((void**)&w3F, g_w3F);
    cudaGetSymbolAddress((void**)&owH, g_owH);     cudaGetSymbolAddress((void**)&owL, g_owL);
    cudaGetSymbolAddress((void**)&qkv, g_qkv);     cudaGetSymbolAddress((void**)&x2, g_x2);
    cudaGetSymbolAddress((void**)&logits, g_logits);

    const int fa_smem = (4 * FA_TILE + 64 * 20) * sizeof(float);
    cudaFuncSetAttribute(flash_attn_kernel, cudaFuncAttributeMaxDynamicSharedMemorySize, fa_smem);
    cudaFuncSetAttribute(kan_gemm_qkv, cudaFuncAttributeMaxDynamicSharedMemorySize, GM_DYN2);
    cudaFuncSetAttribute(kan_gemm_op,  cudaFuncAttributeMaxDynamicSharedMemorySize, GM_DYN3);
    cudaFuncSetAttribute(kan_gemm_w12, cudaFuncAttributeMaxDynamicSharedMemorySize, GM_DYN2);
    cudaFuncSetAttribute(kan_gemm_w3,  cudaFuncAttributeMaxDynamicSharedMemorySize, GM_DYN2);

    // 0) weight conversion (single fp16 except out_w)
    conv_kan_w_h1<<<3072, 256>>>(qkv_base, qkv_spline, qkv_scaler, HID, qwF);
    conv_kan_w_h1<<<NEXP * DFF, 256>>>(w1_base, w1_spline, w1_scaler, HID, w1F);
    conv_kan_w_h1<<<NEXP * DFF, 256>>>(w2_base, w2_spline, w2_scaler, HID, w2F);
    conv_kan_w_h1<<<NEXP * HID, 256>>>(w3_base, w3_spline, w3_scaler, DFF, w3F);
    conv_plain<<<(HID * HID + 255) / 256, 256>>>(out_w, owH, owL, HID * HID);

    // 1) rmsnorm(x) -> phi fp16 hi/lo
    rmsnorm_phi_kernel<<<TOK, 256>>>(x, norm1_w, phiH, phiL, nullptr, nullptr);

    // 2) QKV = phi @ Waug^T with fused RoPE (2-pass fp16)
    kan_gemm_qkv<<<dim3(3072 / 128, TOK / 128), 256, GM_DYN2>>>(rot_cos, rot_sin, qkv);

    // 3) attention
    flash_attn_kernel<<<dim3(SEQ / 64, BATCH * NHEAD), 256, fa_smem>>>(qkv, ctxH, ctxL);

    // 4) x2 = x + ctx @ out_w^T + out_b (dual store into d_out)
    kan_gemm_op<<<dim3(HID / 128, TOK / 128), 256, GM_DYN3>>>(x, out_b, x2, out);

    // 5) rmsnorm(x2) -> phi fp16 hi/lo, gate logits
    rmsnorm_phi_kernel<<<TOK, 256>>>(x2, norm2_w, phiH, phiL, gate_w, logits);

    // 6) routing
    init_cnt_kernel<<<1, 32>>>();
    routing_kernel<<<TOK / 256, 256>>>();

    // 7) MoE batched
    kan_gemm_w12<<<dim3(DFF / 128, TOK / 128, 2 * NEXP), 256, GM_DYN2>>>();
    mul_phi_kernel<<<dim3(TOK, NEXP), 256>>>();
    kan_gemm_w3<<<dim3(HID / 128, TOK / 128, NEXP), 256, GM_DYN2>>>(out);
}

// round 12
// speedup vs baseline: 12.4218x; 1.5568x over previous
#include <cuda_runtime.h>
#include <cuda_bf16.h>
#include <cuda_fp16.h>
#include <math.h>
#include <stdint.h>

#define TOK   2048      // B*S
#define HID   1024
#define KAUG  9216      // H*(1+NB)
#define NB    8
#define NHEAD 16
#define HDIM  64
#define SEQ   1024
#define BATCH 2
#define DFF   1024
#define NEXP  4

// ---------------- scratch (static device globals; no runtime alloc) ----------------
__device__ __align__(16) __half        g_phiF[(size_t)TOK * KAUG];          // single fp16
__device__ __align__(16) __half        g_phitF[(size_t)NEXP * TOK * KAUG];  // single fp16
__device__ __align__(16) __nv_bfloat16 g_ctxH[(size_t)TOK * HID];
__device__ __align__(16) __nv_bfloat16 g_ctxL[(size_t)TOK * HID];
__device__ __align__(16) __half        g_qkvwF[(size_t)3072 * KAUG];
__device__ __align__(16) __half        g_w1F[(size_t)NEXP * DFF * KAUG];
__device__ __align__(16) __half        g_w2F[(size_t)NEXP * DFF * KAUG];
__device__ __align__(16) __half        g_w3F[(size_t)NEXP * HID * KAUG];
__device__ __align__(16) __nv_bfloat16 g_owH[(size_t)HID * HID];
__device__ __align__(16) __nv_bfloat16 g_owL[(size_t)HID * HID];

__device__ float g_qkv[(size_t)TOK * 3 * HID];
__device__ float g_x2[(size_t)TOK * HID];
__device__ float g_t1[(size_t)NEXP * TOK * DFF];
__device__ float g_t2[(size_t)NEXP * TOK * DFF];
__device__ float g_logits[TOK * NEXP];
__device__ int   g_cnt[NEXP];
__device__ int   g_eidx[NEXP * TOK];
__device__ float g_ew[NEXP * TOK];

// ---------------- helpers ----------------------------------------------------------
__device__ __forceinline__ uint32_t smem_u32(const void* p) {
    uint32_t a;
    asm("{ .reg .u64 t; cvta.to.shared.u64 t, %1; cvt.u32.u64 %0, t; }" : "=r"(a) : "l"(p));
    return a;
}

__device__ __forceinline__ void hl_pair(float v, __nv_bfloat16& h, __nv_bfloat16& l) {
    h = __float2bfloat16_rn(v);
    l = __float2bfloat16_rn(v - __bfloat162float(h));
}

template <int ISF16>
__device__ __forceinline__ void mma_any(float* c, uint32_t a0, uint32_t a1, uint32_t a2,
                                        uint32_t a3, uint32_t b0, uint32_t b1) {
    if (ISF16) {
        asm volatile(
            "mma.sync.aligned.m16n8k16.row.col.f32.f16.f16.f32 "
            "{%0,%1,%2,%3}, {%4,%5,%6,%7}, {%8,%9}, {%0,%1,%2,%3};\n"
            : "+f"(c[0]), "+f"(c[1]), "+f"(c[2]), "+f"(c[3])
            : "r"(a0), "r"(a1), "r"(a2), "r"(a3), "r"(b0), "r"(b1));
    } else {
        asm volatile(
            "mma.sync.aligned.m16n8k16.row.col.f32.bf16.bf16.f32 "
            "{%0,%1,%2,%3}, {%4,%5,%6,%7}, {%8,%9}, {%0,%1,%2,%3};\n"
            : "+f"(c[0]), "+f"(c[1]), "+f"(c[2]), "+f"(c[3])
            : "r"(a0), "r"(a1), "r"(a2), "r"(a3), "r"(b0), "r"(b1));
    }
}

#define LDSM_X4(r0, r1, r2, r3, addr) \
    asm volatile("ldmatrix.sync.aligned.m8n8.x4.shared.b16 {%0,%1,%2,%3}, [%4];" \
                 : "=r"(r0), "=r"(r1), "=r"(r2), "=r"(r3) : "r"(addr))

// ---------------- cubic B-spline bases --------------------------------------------
__device__ __forceinline__ void bspline8(float v, float* out) {
    float b[11];
#pragma unroll
    for (int t = 0; t < 11; t++) {
        float g0 = 0.4f * (t - 3) - 1.0f;
        float g1 = 0.4f * (t - 2) - 1.0f;
        b[t] = (v >= g0 && v < g1) ? 1.0f : 0.0f;
    }
#pragma unroll
    for (int j = 1; j <= 3; j++) {
        float inv = 1.0f / (0.4f * (float)j);
#pragma unroll
        for (int t = 0; t < 10; t++) {
            if (t < 11 - j) {
                float gt   = 0.4f * (t - 3) - 1.0f;
                float gtj1 = 0.4f * (t + j - 2) - 1.0f;
                b[t] = (v - gt) * inv * b[t] + (gtj1 - v) * inv * b[t + 1];
            }
        }
    }
#pragma unroll
    for (int c = 0; c < 8; c++) out[c] = b[c];
}

// ---------------- weight conversion kernels ----------------------------------------
__global__ void conv_kan_w_h1(const float* __restrict__ base, const float* __restrict__ spline,
                              const float* __restrict__ scaler, int Kin,
                              __half* __restrict__ W) {
    int o = blockIdx.x;
    int KA = Kin * 9;
    const float* brow = base + (size_t)o * Kin;
    const float* srow = spline + (size_t)o * Kin * 8;
    const float* crow = scaler + (size_t)o * Kin;
    __half* row = W + (size_t)o * KA;
    for (int c = threadIdx.x; c < Kin; c += 256)
        row[c] = __float2half_rn(brow[c]);
    for (int c = threadIdx.x; c < Kin * 8; c += 256)
        row[Kin + c] = __float2half_rn(srow[c] * crow[c >> 3]);
}

__global__ void conv_plain(const float* __restrict__ W,
                           __nv_bfloat16* __restrict__ WH, __nv_bfloat16* __restrict__ WL,
                           int total) {
    int i = blockIdx.x * 256 + threadIdx.x;
    if (i < total) {
        __nv_bfloat16 h, l;
        hl_pair(W[i], h, l);
        WH[i] = h; WL[i] = l;
    }
}

// ---------------- rmsnorm + phi (single fp16) + optional gate logits ---------------
__global__ void rmsnorm_phi_kernel(const float* __restrict__ x,
                                   const float* __restrict__ w,
                                   __half* __restrict__ phiF,
                                   const float* __restrict__ gate_w,
                                   float* __restrict__ logits) {
    int m = blockIdx.x;
    int tid = threadIdx.x;
    __shared__ float sx[HID];
    __shared__ float sred[256];
    const float* xr = x + (size_t)m * HID;
    float ss = 0.f;
    for (int f = tid; f < HID; f += 256) { float v = xr[f]; sx[f] = v; ss += v * v; }
    sred[tid] = ss; __syncthreads();
    for (int o = 128; o > 0; o >>= 1) { if (tid < o) sred[tid] += sred[tid + o]; __syncthreads(); }
    float rms = rsqrtf(sred[0] / (float)HID + 1e-6f);
    float gacc[4] = {0.f, 0.f, 0.f, 0.f};
    __half* ph = phiF + (size_t)m * KAUG;
    for (int f = tid; f < HID; f += 256) {
        float hn = sx[f] * rms * w[f];
        ph[f] = __float2half_rn(hn / (1.0f + expf(-hn)));
        float bs[8];
        bspline8(hn, bs);
#pragma unroll
        for (int c = 0; c < 8; c++)
            ph[HID + f * 8 + c] = __float2half_rn(bs[c]);
        if (gate_w) {
#pragma unroll
            for (int e = 0; e < 4; e++) gacc[e] += hn * gate_w[e * HID + f];
        }
    }
    if (gate_w) {
#pragma unroll
        for (int e = 0; e < 4; e++) {
            __syncthreads();
            sred[tid] = gacc[e]; __syncthreads();
            for (int o = 128; o > 0; o >>= 1) { if (tid < o) sred[tid] += sred[tid + o]; __syncthreads(); }
            if (tid == 0) logits[m * 4 + e] = sred[0];
        }
    }
}

// ---------------- phi expansion of t1*t2, batched over experts (single fp16) -------
__global__ void mul_phi_kernel() {
    int e = blockIdx.y;
    int r = blockIdx.x;
    if (r >= g_cnt[e]) return;
    int tid = threadIdx.x;
    const float* a = g_t1 + (size_t)e * TOK * DFF + (size_t)r * DFF;
    const float* b = g_t2 + (size_t)e * TOK * DFF + (size_t)r * DFF;
    __half* ph = g_phitF + (size_t)e * TOK * KAUG + (size_t)r * KAUG;
    for (int f = tid; f < DFF; f += 256) {
        float v = a[f] * b[f];
        ph[f] = __float2half_rn(v / (1.0f + expf(-v)));
        float bs[8];
        bspline8(v, bs);
#pragma unroll
        for (int c = 0; c < 8; c++)
            ph[DFF + f * 8 + c] = __float2half_rn(bs[c]);
    }
}

// ---------------- tensor-core GEMM body --------------------------------------------
// PASSES=3: tiles AH AL BH BL; AhBh + AhBl + AlBh (split precision).
// PASSES=1: tiles A B; single pass (single-rounded fp16 both sides).
// EPI 0: plain. EPI 1: +res+bias dual store. EPI 3: atomic scatter. EPI 4: RoPE store.
#define PITCH  80
#define TILEB  (128 * PITCH)
#define GM_DYN3 (512 + 2 * 4 * TILEB)
#define GM_DYN1 (512 + 2 * 2 * TILEB)

template <int EPI, int PASSES, int ISF16>
__device__ __forceinline__ void gemm_body(
    const uint16_t* __restrict__ AH, const uint16_t* __restrict__ AL,
    int lda, const int* __restrict__ a_idx,
    const uint16_t* __restrict__ BH, const uint16_t* __restrict__ BL, int ldb,
    float* __restrict__ C, int ldc, int M, int K,
    const int* __restrict__ cnt,
    const float* __restrict__ aux0, const float* __restrict__ aux1, float* __restrict__ C2,
    const int* __restrict__ out_idx, const float* __restrict__ out_wt) {
    const int NT = (PASSES == 3) ? 4 : 2;
    const int BT = (PASSES == 3) ? 2 : 1;            // B tile index
    const uint32_t STAGEB = (uint32_t)NT * TILEB;

    int Meff = cnt ? *cnt : M;
    int mBase = blockIdx.y * 128;
    int nBase = blockIdx.x * 128;
    if (mBase >= Meff) return;

    extern __shared__ char sm[];
    int* rowmap = (int*)sm;
    uint32_t bufs_u = smem_u32(sm + 512);
    int tid = threadIdx.x;

    if (tid < 128) {
        int r = mBase + tid;
        int g = (r < Meff) ? r : mBase;
        rowmap[tid] = a_idx ? a_idx[g] : g;
    }
    __syncthreads();

    int w = tid >> 5, l = tid & 31;
    int wm = (w >> 2) * 64;
    int wn = (w & 3) * 32;
    int lq = l >> 2, lr = l & 3;
    uint32_t aOff = (uint32_t)(wm + (l & 15)) * PITCH + ((l >> 4) ? 16u : 0u);
    uint32_t bOff = (uint32_t)(wn + (l & 7) + ((l & 16) ? 8 : 0)) * PITCH + ((l & 8) ? 16u : 0u);

    float acc[4][4][4];
#pragma unroll
    for (int mf = 0; mf < 4; mf++)
#pragma unroll
        for (int nf = 0; nf < 4; nf++)
#pragma unroll
            for (int t = 0; t < 4; t++) acc[mf][nf][t] = 0.f;

    auto issue = [&](int s, int k0) {
#pragma unroll
        for (int it = 0; it < 2 * NT; it++) {
            int i = it * 256 + tid;
            int tens = i >> 9;
            int rem = i & 511;
            int row = rem >> 2;
            int seg = rem & 3;
            const uint16_t* src;
            if (PASSES == 1) {
                src = (tens == 0) ? AH + (size_t)rowmap[row] * lda + k0 + 8 * seg
                                  : BH + (size_t)(nBase + row) * ldb + k0 + 8 * seg;
            } else {
                if (tens == 0)      src = AH + (size_t)rowmap[row] * lda + k0 + 8 * seg;
                else if (tens == 1) src = AL + (size_t)rowmap[row] * lda + k0 + 8 * seg;
                else if (tens == 2) src = BH + (size_t)(nBase + row) * ldb + k0 + 8 * seg;
                else                src = BL + (size_t)(nBase + row) * ldb + k0 + 8 * seg;
            }
            uint32_t dst = bufs_u + (uint32_t)s * STAGEB + (uint32_t)tens * TILEB +
                           (uint32_t)row * PITCH + (uint32_t)seg * 16;
            asm volatile("cp.async.cg.shared.global [%0], [%1], 16;" :: "r"(dst), "l"(src) : "memory");
        }
        asm volatile("cp.async.commit_group;" ::: "memory");
    };

    int nStages = K / 32;
    issue(0, 0);
    for (int ck = 0; ck < nStages; ck++) {
        if (ck) __syncthreads();
        bool pre = (ck + 1 < nStages);
        if (pre) issue((ck + 1) & 1, (ck + 1) * 32);
        if (pre) asm volatile("cp.async.wait_group 1;" ::: "memory");
        else     asm volatile("cp.async.wait_group 0;" ::: "memory");
        __syncthreads();

        uint32_t base = bufs_u + (uint32_t)(ck & 1) * STAGEB;
#pragma unroll
        for (int p = 0; p < 2; p++) {
            uint32_t koff = 32u * p;
            if (PASSES == 3) {
                uint32_t bH[4][2], bL[4][2], af[4][4];
#pragma unroll
                for (int nh = 0; nh < 2; nh++) {
                    uint32_t r0, r1, r2, r3;
                    LDSM_X4(r0, r1, r2, r3, base + 2 * TILEB + bOff + nh * 16 * PITCH + koff);
                    bH[2 * nh][0] = r0; bH[2 * nh][1] = r1; bH[2 * nh + 1][0] = r2; bH[2 * nh + 1][1] = r3;
                    LDSM_X4(r0, r1, r2, r3, base + 3 * TILEB + bOff + nh * 16 * PITCH + koff);
                    bL[2 * nh][0] = r0; bL[2 * nh][1] = r1; bL[2 * nh + 1][0] = r2; bL[2 * nh + 1][1] = r3;
                }
#pragma unroll
                for (int mf = 0; mf < 4; mf++)
                    LDSM_X4(af[mf][0], af[mf][1], af[mf][2], af[mf][3],
                            base + 0 * TILEB + aOff + mf * 16 * PITCH + koff);
#pragma unroll
                for (int mf = 0; mf < 4; mf++)
#pragma unroll
                    for (int nf = 0; nf < 4; nf++)
                        mma_any<ISF16>(acc[mf][nf], af[mf][0], af[mf][1], af[mf][2], af[mf][3],
                                       bH[nf][0], bH[nf][1]);
#pragma unroll
                for (int mf = 0; mf < 4; mf++)
#pragma unroll
                    for (int nf = 0; nf < 4; nf++)
                        mma_any<ISF16>(acc[mf][nf], af[mf][0], af[mf][1], af[mf][2], af[mf][3],
                                       bL[nf][0], bL[nf][1]);
#pragma unroll
                for (int mf = 0; mf < 4; mf++)
                    LDSM_X4(af[mf][0], af[mf][1], af[mf][2], af[mf][3],
                            base + 1 * TILEB + aOff + mf * 16 * PITCH + koff);
#pragma unroll
                for (int mf = 0; mf < 4; mf++)
#pragma unroll
                    for (int nf = 0; nf < 4; nf++)
                        mma_any<ISF16>(acc[mf][nf], af[mf][0], af[mf][1], af[mf][2], af[mf][3],
                                       bH[nf][0], bH[nf][1]);
            } else {
                uint32_t bb[4][2], af[4][4];
#pragma unroll
                for (int nh = 0; nh < 2; nh++) {
                    uint32_t r0, r1, r2, r3;
                    LDSM_X4(r0, r1, r2, r3, base + BT * TILEB + bOff + nh * 16 * PITCH + koff);
                    bb[2 * nh][0] = r0; bb[2 * nh][1] = r1; bb[2 * nh + 1][0] = r2; bb[2 * nh + 1][1] = r3;
                }
#pragma unroll
                for (int mf = 0; mf < 4; mf++)
                    LDSM_X4(af[mf][0], af[mf][1], af[mf][2], af[mf][3],
                            base + 0 * TILEB + aOff + mf * 16 * PITCH + koff);
#pragma unroll
                for (int mf = 0; mf < 4; mf++)
#pragma unroll
                    for (int nf = 0; nf < 4; nf++)
                        mma_any<ISF16>(acc[mf][nf], af[mf][0], af[mf][1], af[mf][2], af[mf][3],
                                       bb[nf][0], bb[nf][1]);
            }
        }
    }

    // ---- epilogue ----
#pragma unroll
    for (int mf = 0; mf < 4; mf++) {
#pragma unroll
        for (int nf = 0; nf < 4; nf++) {
            float* c = acc[mf][nf];
            int r0 = mBase + wm + mf * 16 + lq;
            int c0 = nBase + wn + nf * 8 + 2 * lr;
#pragma unroll
            for (int half = 0; half < 2; half++) {
                int r = r0 + half * 8;
                if (r >= Meff) continue;
                float v0 = c[half * 2 + 0], v1 = c[half * 2 + 1];
                if (EPI == 0) {
                    C[(size_t)r * ldc + c0] = v0;
                    C[(size_t)r * ldc + c0 + 1] = v1;
                } else if (EPI == 1) {
                    float o0 = v0 + aux0[(size_t)r * ldc + c0] + aux1[c0];
                    float o1 = v1 + aux0[(size_t)r * ldc + c0 + 1] + aux1[c0 + 1];
                    C[(size_t)r * ldc + c0] = o0;  C2[(size_t)r * ldc + c0] = o0;
                    C[(size_t)r * ldc + c0 + 1] = o1; C2[(size_t)r * ldc + c0 + 1] = o1;
                } else if (EPI == 3) {
                    int tok = out_idx[r];
                    float wgt = out_wt[r];
                    atomicAdd(&C[(size_t)tok * ldc + c0], wgt * v0);
                    atomicAdd(&C[(size_t)tok * ldc + c0 + 1], wgt * v1);
                } else {   // EPI == 4: RoPE on q,k pairs then store
                    int s = r & (SEQ - 1);
                    int sub = c0 % 192;
                    if (sub < 128) {
                        int d2 = (sub & 63) >> 1;
                        float cc = aux0[s * 32 + d2], sn = aux1[s * 32 + d2];
                        C[(size_t)r * ldc + c0]     = v0 * cc - v1 * sn;
                        C[(size_t)r * ldc + c0 + 1] = v0 * sn + v1 * cc;
                    } else {
                        C[(size_t)r * ldc + c0] = v0;
                        C[(size_t)r * ldc + c0 + 1] = v1;
                    }
                }
            }
        }
    }
}

// QKV: fp16 1-pass + fused RoPE
__global__ void __launch_bounds__(256, 2)
kan_gemm_qkv(const float* __restrict__ rc, const float* __restrict__ rs,
             float* __restrict__ qkv) {
    gemm_body<4, 1, 1>((const uint16_t*)g_phiF, nullptr, KAUG, nullptr,
                       (const uint16_t*)g_qkvwF, nullptr, KAUG,
                       qkv, 3072, TOK, KAUG, nullptr, rc, rs, nullptr, nullptr, nullptr);
}

// out-proj: bf16 3-pass, residual+bias dual store (precision anchor)
__global__ void __launch_bounds__(256, 2)
kan_gemm_op(const float* __restrict__ x, const float* __restrict__ bias,
            float* __restrict__ x2, float* __restrict__ out) {
    gemm_body<1, 3, 0>((const uint16_t*)g_ctxH, (const uint16_t*)g_ctxL, HID, nullptr,
                       (const uint16_t*)g_owH, (const uint16_t*)g_owL, HID,
                       x2, HID, TOK, HID, nullptr, x, bias, out, nullptr, nullptr);
}

// batched w1+w2: fp16 1-pass
__global__ void __launch_bounds__(256, 2)
kan_gemm_w12() {
    int z = blockIdx.z, e = z >> 1, sel = z & 1;
    const uint16_t* B = (const uint16_t*)((sel ? g_w2F : g_w1F) + (size_t)e * DFF * KAUG);
    float* C = (sel ? g_t2 : g_t1) + (size_t)e * TOK * DFF;
    gemm_body<0, 1, 1>((const uint16_t*)g_phiF, nullptr, KAUG,
                       g_eidx + e * TOK, B, nullptr, KAUG,
                       C, DFF, TOK, KAUG, g_cnt + e, nullptr, nullptr, nullptr, nullptr, nullptr);
}

// batched w3: fp16 1-pass, atomic scatter
__global__ void __launch_bounds__(256, 2)
kan_gemm_w3(float* __restrict__ out) {
    int e = blockIdx.z;
    gemm_body<3, 1, 1>((const uint16_t*)(g_phitF + (size_t)e * TOK * KAUG), nullptr,
                       KAUG, nullptr,
                       (const uint16_t*)(g_w3F + (size_t)e * HID * KAUG), nullptr, KAUG,
                       out, HID, TOK, KAUG, g_cnt + e, nullptr, nullptr, nullptr,
                       g_eidx + e * TOK, g_ew + e * TOK);
}

// ---------------- flash attention (writes ctx as bf16 hi/lo) ------------------------
#define FA_STRIDE 68
#define FA_TILE   (64 * FA_STRIDE)
__global__ void flash_attn_kernel(const float* __restrict__ qkv,
                                  __nv_bfloat16* __restrict__ ctxH,
                                  __nv_bfloat16* __restrict__ ctxL) {
    extern __shared__ float smem[];
    float* Qs   = smem;
    float* Ks   = Qs + FA_TILE;
    float* Ss   = Ks + FA_TILE;
    float* Vs   = Ss + FA_TILE;
    float* Pred = Vs + FA_TILE;

    int qt = blockIdx.x, bh = blockIdx.y;
    int b = bh >> 4, h = bh & 15;
    int tid = threadIdx.x;
    int r  = tid >> 2;
    int c4 = (tid & 3) * 16;
    int q0 = (tid >> 4) * 4;
    int kc0 = (tid & 15) * 4;
    int pcol = tid & 15;

    const float* qbase = qkv + (size_t)(b * SEQ + qt * 64 + r) * 3072 + h * 192;
#pragma unroll
    for (int u = 0; u < 4; u++) {
        float4 qv = *(const float4*)(qbase + c4 + u * 4);
        Qs[(c4 + u * 4 + 0) * FA_STRIDE + r] = qv.x;
        Qs[(c4 + u * 4 + 1) * FA_STRIDE + r] = qv.y;
        Qs[(c4 + u * 4 + 2) * FA_STRIDE + r] = qv.z;
        Qs[(c4 + u * 4 + 3) * FA_STRIDE + r] = qv.w;
    }

    float o[4][4];
    float m_i[4], l_i[4];
#pragma unroll
    for (int i = 0; i < 4; i++) {
        m_i[i] = -1e30f; l_i[i] = 0.f;
#pragma unroll
        for (int j = 0; j < 4; j++) o[i][j] = 0.f;
    }

    for (int kt = 0; kt < SEQ / 64; kt++) {
        __syncthreads();
        const float* kbase = qkv + (size_t)(b * SEQ + kt * 64 + r) * 3072 + h * 192 + 64;
        const float* vbase = kbase + 64;
#pragma unroll
        for (int u = 0; u < 4; u++) {
            float4 kv = *(const float4*)(kbase + c4 + u * 4);
            Ks[(c4 + u * 4 + 0) * FA_STRIDE + r] = kv.x;
            Ks[(c4 + u * 4 + 1) * FA_STRIDE + r] = kv.y;
            Ks[(c4 + u * 4 + 2) * FA_STRIDE + r] = kv.z;
            Ks[(c4 + u * 4 + 3) * FA_STRIDE + r] = kv.w;
            *(float4*)&Vs[r * FA_STRIDE + c4 + u * 4] = *(const float4*)(vbase + c4 + u * 4);
        }
        __syncthreads();

        float s[4][4];
#pragma unroll
        for (int i = 0; i < 4; i++)
#pragma unroll
            for (int j = 0; j < 4; j++) s[i][j] = 0.f;
#pragma unroll 8
        for (int d = 0; d < 64; d++) {
            float a0[4], b0[4];
            *(float4*)a0 = *(const float4*)&Qs[d * FA_STRIDE + q0];
            *(float4*)b0 = *(const float4*)&Ks[d * FA_STRIDE + kc0];
#pragma unroll
            for (int i = 0; i < 4; i++)
#pragma unroll
                for (int j = 0; j < 4; j++) s[i][j] += a0[i] * b0[j];
        }
#pragma unroll
        for (int i = 0; i < 4; i++)
#pragma unroll
            for (int j = 0; j < 4; j++) s[i][j] *= 0.125f;

#pragma unroll
        for (int i = 0; i < 4; i++) {
            float pm = fmaxf(fmaxf(s[i][0], s[i][1]), fmaxf(s[i][2], s[i][3]));
            Pred[(q0 + i) * 20 + pcol] = pm;
        }
        __syncthreads();
        float mnew[4], corr[4];
#pragma unroll
        for (int i = 0; i < 4; i++) {
            float mx = m_i[i];
            const float* pr = &Pred[(q0 + i) * 20];
#pragma unroll
            for (int t = 0; t < 16; t++) mx = fmaxf(mx, pr[t]);
            mnew[i] = mx;
            corr[i] = expf(m_i[i] - mx);
            m_i[i] = mx;
        }
        __syncthreads();

#pragma unroll
        for (int i = 0; i < 4; i++) {
            float ps = 0.f;
#pragma unroll
            for (int j = 0; j < 4; j++) {
                float p = expf(s[i][j] - mnew[i]);
                Ss[(q0 + i) * FA_STRIDE + kc0 + j] = p;
                ps += p;
            }
            Pred[(q0 + i) * 20 + pcol] = ps;
        }
        __syncthreads();

#pragma unroll
        for (int i = 0; i < 4; i++) {
            float rs = 0.f;
            const float* pr = &Pred[(q0 + i) * 20];
#pragma unroll
            for (int t = 0; t < 16; t++) rs += pr[t];
            l_i[i] = corr[i] * l_i[i] + rs;
#pragma unroll
            for (int j = 0; j < 4; j++) o[i][j] *= corr[i];
        }

#pragma unroll 8
        for (int kk = 0; kk < 64; kk++) {
            float a0[4], b0[4];
            a0[0] = Ss[(q0 + 0) * FA_STRIDE + kk];
            a0[1] = Ss[(q0 + 1) * FA_STRIDE + kk];
            a0[2] = Ss[(q0 + 2) * FA_STRIDE + kk];
            a0[3] = Ss[(q0 + 3) * FA_STRIDE + kk];
            *(float4*)b0 = *(const float4*)&Vs[kk * FA_STRIDE + kc0];
#pragma unroll
            for (int i = 0; i < 4; i++)
#pragma unroll
                for (int j = 0; j < 4; j++) o[i][j] += a0[i] * b0[j];
        }
    }

#pragma unroll
    for (int i = 0; i < 4; i++) {
        float inv = 1.0f / l_i[i];
#pragma unroll
        for (int j = 0; j < 4; j++) {
            size_t off = (size_t)(b * SEQ + qt * 64 + q0 + i) * HID + h * 64 + kc0 + j;
            __nv_bfloat16 hh, ll;
            hl_pair(o[i][j] * inv, hh, ll);
            ctxH[off] = hh; ctxL[off] = ll;
        }
    }
}

// ---------------- MoE routing -----------------------------------------------------
__global__ void init_cnt_kernel() {
    if (threadIdx.x < NEXP) g_cnt[threadIdx.x] = 0;
}

__global__ void routing_kernel() {
    int m = blockIdx.x * 256 + threadIdx.x;
    if (m >= TOK) return;
    float l[4];
#pragma unroll
    for (int e = 0; e < 4; e++) l[e] = g_logits[m * 4 + e];
    int i0 = 0; float b0 = l[0];
#pragma unroll
    for (int e = 1; e < 4; e++) if (l[e] > b0) { b0 = l[e]; i0 = e; }
    int i1 = -1; float b1 = -1e30f;
#pragma unroll
    for (int e = 0; e < 4; e++) if (e != i0 && l[e] > b1) { b1 = l[e]; i1 = e; }
    float t = expf(b1 - b0);
    float w0 = 1.0f / (1.0f + t);
    float w1 = t / (1.0f + t);
    int p0 = atomicAdd(&g_cnt[i0], 1);
    g_eidx[i0 * TOK + p0] = m; g_ew[i0 * TOK + p0] = w0;
    int p1 = atomicAdd(&g_cnt[i1], 1);
    g_eidx[i1 * TOK + p1] = m; g_ew[i1 * TOK + p1] = w1;
}

// ---------------- host orchestration ----------------------------------------------
extern "C" void kernel_launch(void* const* d_in, const int* in_sizes, int n_in,
                              void* d_out, int out_size) {
    const float* x          = (const float*)d_in[0];
    const float* rot_cos    = (const float*)d_in[1];
    const float* rot_sin    = (const float*)d_in[2];
    const float* norm1_w    = (const float*)d_in[3];
    const float* norm2_w    = (const float*)d_in[4];
    const float* qkv_base   = (const float*)d_in[5];
    const float* qkv_spline = (const float*)d_in[6];
    const float* qkv_scaler = (const float*)d_in[7];
    const float* out_w      = (const float*)d_in[8];
    const float* out_b      = (const float*)d_in[9];
    const float* gate_w     = (const float*)d_in[10];
    const float* w1_base    = (const float*)d_in[11];
    const float* w1_spline  = (const float*)d_in[12];
    const float* w1_scaler  = (const float*)d_in[13];
    const float* w2_base    = (const float*)d_in[14];
    const float* w2_spline  = (const float*)d_in[15];
    const float* w2_scaler  = (const float*)d_in[16];
    const float* w3_base    = (const float*)d_in[17];
    const float* w3_spline  = (const float*)d_in[18];
    const float* w3_scaler  = (const float*)d_in[19];
    float* out = (float*)d_out;

    __half *phiF, *qwF, *w1F, *w2F, *w3F;
    __nv_bfloat16 *ctxH, *ctxL, *owH, *owL;
    float *qkv, *x2, *logits;
    cudaGetSymbolAddress((void**)&phiF, g_phiF);
    cudaGetSymbolAddress((void**)&ctxH, g_ctxH);   cudaGetSymbolAddress((void**)&ctxL, g_ctxL);
    cudaGetSymbolAddress((void**)&qwF, g_qkvwF);
    cudaGetSymbolAddress((void**)&w1F, g_w1F);     cudaGetSymbolAddress((void**)&w2F, g_w2F);
    cudaGetSymbolAddress((void**)&w3F, g_w3F);
    cudaGetSymbolAddress((void**)&owH, g_owH);     cudaGetSymbolAddress((void**)&owL, g_owL);
    cudaGetSymbolAddress((void**)&qkv, g_qkv);     cudaGetSymbolAddress((void**)&x2, g_x2);
    cudaGetSymbolAddress((void**)&logits, g_logits);

    const int fa_smem = (4 * FA_TILE + 64 * 20) * sizeof(float);
    cudaFuncSetAttribute(flash_attn_kernel, cudaFuncAttributeMaxDynamicSharedMemorySize, fa_smem);
    cudaFuncSetAttribute(kan_gemm_qkv, cudaFuncAttributeMaxDynamicSharedMemorySize, GM_DYN1);
    cudaFuncSetAttribute(kan_gemm_op,  cudaFuncAttributeMaxDynamicSharedMemorySize, GM_DYN3);
    cudaFuncSetAttribute(kan_gemm_w12, cudaFuncAttributeMaxDynamicSharedMemorySize, GM_DYN1);
    cudaFuncSetAttribute(kan_gemm_w3,  cudaFuncAttributeMaxDynamicSharedMemorySize, GM_DYN1);

    // 0) weight conversion (single fp16 except out_w)
    conv_kan_w_h1<<<3072, 256>>>(qkv_base, qkv_spline, qkv_scaler, HID, qwF);
    conv_kan_w_h1<<<NEXP * DFF, 256>>>(w1_base, w1_spline, w1_scaler, HID, w1F);
    conv_kan_w_h1<<<NEXP * DFF, 256>>>(w2_base, w2_spline, w2_scaler, HID, w2F);
    conv_kan_w_h1<<<NEXP * HID, 256>>>(w3_base, w3_spline, w3_scaler, DFF, w3F);
    conv_plain<<<(HID * HID + 255) / 256, 256>>>(out_w, owH, owL, HID * HID);

    // 1) rmsnorm(x) -> phi fp16
    rmsnorm_phi_kernel<<<TOK, 256>>>(x, norm1_w, phiF, nullptr, nullptr);

    // 2) QKV = phi @ Waug^T with fused RoPE (1-pass fp16)
    kan_gemm_qkv<<<dim3(3072 / 128, TOK / 128), 256, GM_DYN1>>>(rot_cos, rot_sin, qkv);

    // 3) attention
    flash_attn_kernel<<<dim3(SEQ / 64, BATCH * NHEAD), 256, fa_smem>>>(qkv, ctxH, ctxL);

    // 4) x2 = x + ctx @ out_w^T + out_b (dual store into d_out)
    kan_gemm_op<<<dim3(HID / 128, TOK / 128), 256, GM_DYN3>>>(x, out_b, x2, out);

    // 5) rmsnorm(x2) -> phi fp16, gate logits
    rmsnorm_phi_kernel<<<TOK, 256>>>(x2, norm2_w, phiF, gate_w, logits);

    // 6) routing
    init_cnt_kernel<<<1, 32>>>();
    routing_kernel<<<TOK / 256, 256>>>();

    // 7) MoE batched
    kan_gemm_w12<<<dim3(DFF / 128, TOK / 128, 2 * NEXP), 256, GM_DYN1>>>();
    mul_phi_kernel<<<dim3(TOK, NEXP), 256>>>();
    kan_gemm_w3<<<dim3(HID / 128, TOK / 128, NEXP), 256, GM_DYN1>>>(out);
}

// round 13
// speedup vs baseline: 14.3524x; 1.1554x over previous
#include <cuda_runtime.h>
#include <cuda_bf16.h>
#include <cuda_fp16.h>
#include <math.h>
#include <stdint.h>

#define TOK   2048      // B*S
#define HID   1024
#define KAUG  9216      // H*(1+NB)
#define NB    8
#define NHEAD 16
#define HDIM  64
#define SEQ   1024
#define BATCH 2
#define DFF   1024
#define NEXP  4

// ---------------- scratch (static device globals; no runtime alloc) ----------------
__device__ __align__(16) __half        g_phiF[(size_t)TOK * KAUG];          // single fp16
__device__ __align__(16) __half        g_phitF[(size_t)NEXP * TOK * KAUG];  // single fp16
__device__ __align__(16) __nv_bfloat16 g_ctxH[(size_t)TOK * HID];
__device__ __align__(16) __nv_bfloat16 g_ctxL[(size_t)TOK * HID];
__device__ __align__(16) __half        g_qkvwF[(size_t)3072 * KAUG];
__device__ __align__(16) __half        g_w1F[(size_t)NEXP * DFF * KAUG];
__device__ __align__(16) __half        g_w2F[(size_t)NEXP * DFF * KAUG];
__device__ __align__(16) __half        g_w3F[(size_t)NEXP * HID * KAUG];
__device__ __align__(16) __nv_bfloat16 g_owH[(size_t)HID * HID];
__device__ __align__(16) __nv_bfloat16 g_owL[(size_t)HID * HID];

__device__ float g_qkv[(size_t)TOK * 3 * HID];
__device__ float g_x2[(size_t)TOK * HID];
__device__ float g_t1[(size_t)NEXP * TOK * DFF];
__device__ float g_t2[(size_t)NEXP * TOK * DFF];
__device__ float g_logits[TOK * NEXP];
__device__ int   g_cnt[NEXP];
__device__ int   g_eidx[NEXP * TOK];
__device__ float g_ew[NEXP * TOK];

// ---------------- helpers ----------------------------------------------------------
__device__ __forceinline__ uint32_t smem_u32(const void* p) {
    uint32_t a;
    asm("{ .reg .u64 t; cvta.to.shared.u64 t, %1; cvt.u32.u64 %0, t; }" : "=r"(a) : "l"(p));
    return a;
}

__device__ __forceinline__ void hl_pair(float v, __nv_bfloat16& h, __nv_bfloat16& l) {
    h = __float2bfloat16_rn(v);
    l = __float2bfloat16_rn(v - __bfloat162float(h));
}

template <int ISF16>
__device__ __forceinline__ void mma_any(float* c, uint32_t a0, uint32_t a1, uint32_t a2,
                                        uint32_t a3, uint32_t b0, uint32_t b1) {
    if (ISF16) {
        asm volatile(
            "mma.sync.aligned.m16n8k16.row.col.f32.f16.f16.f32 "
            "{%0,%1,%2,%3}, {%4,%5,%6,%7}, {%8,%9}, {%0,%1,%2,%3};\n"
            : "+f"(c[0]), "+f"(c[1]), "+f"(c[2]), "+f"(c[3])
            : "r"(a0), "r"(a1), "r"(a2), "r"(a3), "r"(b0), "r"(b1));
    } else {
        asm volatile(
            "mma.sync.aligned.m16n8k16.row.col.f32.bf16.bf16.f32 "
            "{%0,%1,%2,%3}, {%4,%5,%6,%7}, {%8,%9}, {%0,%1,%2,%3};\n"
            : "+f"(c[0]), "+f"(c[1]), "+f"(c[2]), "+f"(c[3])
            : "r"(a0), "r"(a1), "r"(a2), "r"(a3), "r"(b0), "r"(b1));
    }
}

#define LDSM_X4(r0, r1, r2, r3, addr) \
    asm volatile("ldmatrix.sync.aligned.m8n8.x4.shared.b16 {%0,%1,%2,%3}, [%4];" \
                 : "=r"(r0), "=r"(r1), "=r"(r2), "=r"(r3) : "r"(addr))

// ---------------- cubic B-spline bases --------------------------------------------
__device__ __forceinline__ void bspline8(float v, float* out) {
    float b[11];
#pragma unroll
    for (int t = 0; t < 11; t++) {
        float g0 = 0.4f * (t - 3) - 1.0f;
        float g1 = 0.4f * (t - 2) - 1.0f;
        b[t] = (v >= g0 && v < g1) ? 1.0f : 0.0f;
    }
#pragma unroll
    for (int j = 1; j <= 3; j++) {
        float inv = 1.0f / (0.4f * (float)j);
#pragma unroll
        for (int t = 0; t < 10; t++) {
            if (t < 11 - j) {
                float gt   = 0.4f * (t - 3) - 1.0f;
                float gtj1 = 0.4f * (t + j - 2) - 1.0f;
                b[t] = (v - gt) * inv * b[t] + (gtj1 - v) * inv * b[t + 1];
            }
        }
    }
#pragma unroll
    for (int c = 0; c < 8; c++) out[c] = b[c];
}

// ---------------- weight conversion kernels ----------------------------------------
__global__ void conv_kan_w_h1(const float* __restrict__ base, const float* __restrict__ spline,
                              const float* __restrict__ scaler, int Kin,
                              __half* __restrict__ W) {
    int o = blockIdx.x;
    int KA = Kin * 9;
    const float* brow = base + (size_t)o * Kin;
    const float* srow = spline + (size_t)o * Kin * 8;
    const float* crow = scaler + (size_t)o * Kin;
    __half* row = W + (size_t)o * KA;
    for (int c = threadIdx.x; c < Kin; c += 256)
        row[c] = __float2half_rn(brow[c]);
    for (int c = threadIdx.x; c < Kin * 8; c += 256)
        row[Kin + c] = __float2half_rn(srow[c] * crow[c >> 3]);
}

__global__ void conv_plain(const float* __restrict__ W,
                           __nv_bfloat16* __restrict__ WH, __nv_bfloat16* __restrict__ WL,
                           int total) {
    int i = blockIdx.x * 256 + threadIdx.x;
    if (i < total) {
        __nv_bfloat16 h, l;
        hl_pair(W[i], h, l);
        WH[i] = h; WL[i] = l;
    }
}

// ---------------- rmsnorm + phi (single fp16) + optional gate logits ---------------
__global__ void rmsnorm_phi_kernel(const float* __restrict__ x,
                                   const float* __restrict__ w,
                                   __half* __restrict__ phiF,
                                   const float* __restrict__ gate_w,
                                   float* __restrict__ logits) {
    int m = blockIdx.x;
    int tid = threadIdx.x;
    __shared__ float sx[HID];
    __shared__ float sred[256];
    const float* xr = x + (size_t)m * HID;
    float ss = 0.f;
    for (int f = tid; f < HID; f += 256) { float v = xr[f]; sx[f] = v; ss += v * v; }
    sred[tid] = ss; __syncthreads();
    for (int o = 128; o > 0; o >>= 1) { if (tid < o) sred[tid] += sred[tid + o]; __syncthreads(); }
    float rms = rsqrtf(sred[0] / (float)HID + 1e-6f);
    float gacc[4] = {0.f, 0.f, 0.f, 0.f};
    __half* ph = phiF + (size_t)m * KAUG;
    for (int f = tid; f < HID; f += 256) {
        float hn = sx[f] * rms * w[f];
        ph[f] = __float2half_rn(hn / (1.0f + expf(-hn)));
        float bs[8];
        bspline8(hn, bs);
#pragma unroll
        for (int c = 0; c < 8; c++)
            ph[HID + f * 8 + c] = __float2half_rn(bs[c]);
        if (gate_w) {
#pragma unroll
            for (int e = 0; e < 4; e++) gacc[e] += hn * gate_w[e * HID + f];
        }
    }
    if (gate_w) {
#pragma unroll
        for (int e = 0; e < 4; e++) {
            __syncthreads();
            sred[tid] = gacc[e]; __syncthreads();
            for (int o = 128; o > 0; o >>= 1) { if (tid < o) sred[tid] += sred[tid + o]; __syncthreads(); }
            if (tid == 0) logits[m * 4 + e] = sred[0];
        }
    }
}

// ---------------- phi expansion of t1*t2, batched over experts (single fp16) -------
__global__ void mul_phi_kernel() {
    int e = blockIdx.y;
    int r = blockIdx.x;
    if (r >= g_cnt[e]) return;
    int tid = threadIdx.x;
    const float* a = g_t1 + (size_t)e * TOK * DFF + (size_t)r * DFF;
    const float* b = g_t2 + (size_t)e * TOK * DFF + (size_t)r * DFF;
    __half* ph = g_phitF + (size_t)e * TOK * KAUG + (size_t)r * KAUG;
    for (int f = tid; f < DFF; f += 256) {
        float v = a[f] * b[f];
        ph[f] = __float2half_rn(v / (1.0f + expf(-v)));
        float bs[8];
        bspline8(v, bs);
#pragma unroll
        for (int c = 0; c < 8; c++)
            ph[DFF + f * 8 + c] = __float2half_rn(bs[c]);
    }
}

// ---------------- tensor-core GEMM body --------------------------------------------
// PASSES=3: tiles AH AL BH BL; AhBh + AhBl + AlBh (split precision).
// PASSES=1: tiles A B; single pass (single-rounded fp16 both sides).
// EPI 0: plain. EPI 1: +res+bias dual store. EPI 3: atomic scatter. EPI 4: RoPE store.
#define PITCH  80
#define TILEB  (128 * PITCH)
#define GM_DYN3 (512 + 2 * 4 * TILEB)
#define GM_DYN1 (512 + 2 * 2 * TILEB)

template <int EPI, int PASSES, int ISF16>
__device__ __forceinline__ void gemm_body(
    const uint16_t* __restrict__ AH, const uint16_t* __restrict__ AL,
    int lda, const int* __restrict__ a_idx,
    const uint16_t* __restrict__ BH, const uint16_t* __restrict__ BL, int ldb,
    float* __restrict__ C, int ldc, int M, int K,
    const int* __restrict__ cnt,
    const float* __restrict__ aux0, const float* __restrict__ aux1, float* __restrict__ C2,
    const int* __restrict__ out_idx, const float* __restrict__ out_wt) {
    const int NT = (PASSES == 3) ? 4 : 2;
    const int BT = (PASSES == 3) ? 2 : 1;            // B tile index
    const uint32_t STAGEB = (uint32_t)NT * TILEB;

    int Meff = cnt ? *cnt : M;
    int mBase = blockIdx.y * 128;
    int nBase = blockIdx.x * 128;
    if (mBase >= Meff) return;

    extern __shared__ char sm[];
    int* rowmap = (int*)sm;
    uint32_t bufs_u = smem_u32(sm + 512);
    int tid = threadIdx.x;

    if (tid < 128) {
        int r = mBase + tid;
        int g = (r < Meff) ? r : mBase;
        rowmap[tid] = a_idx ? a_idx[g] : g;
    }
    __syncthreads();

    int w = tid >> 5, l = tid & 31;
    int wm = (w >> 2) * 64;
    int wn = (w & 3) * 32;
    int lq = l >> 2, lr = l & 3;
    uint32_t aOff = (uint32_t)(wm + (l & 15)) * PITCH + ((l >> 4) ? 16u : 0u);
    uint32_t bOff = (uint32_t)(wn + (l & 7) + ((l & 16) ? 8 : 0)) * PITCH + ((l & 8) ? 16u : 0u);

    float acc[4][4][4];
#pragma unroll
    for (int mf = 0; mf < 4; mf++)
#pragma unroll
        for (int nf = 0; nf < 4; nf++)
#pragma unroll
            for (int t = 0; t < 4; t++) acc[mf][nf][t] = 0.f;

    auto issue = [&](int s, int k0) {
#pragma unroll
        for (int it = 0; it < 2 * NT; it++) {
            int i = it * 256 + tid;
            int tens = i >> 9;
            int rem = i & 511;
            int row = rem >> 2;
            int seg = rem & 3;
            const uint16_t* src;
            if (PASSES == 1) {
                src = (tens == 0) ? AH + (size_t)rowmap[row] * lda + k0 + 8 * seg
                                  : BH + (size_t)(nBase + row) * ldb + k0 + 8 * seg;
            } else {
                if (tens == 0)      src = AH + (size_t)rowmap[row] * lda + k0 + 8 * seg;
                else if (tens == 1) src = AL + (size_t)rowmap[row] * lda + k0 + 8 * seg;
                else if (tens == 2) src = BH + (size_t)(nBase + row) * ldb + k0 + 8 * seg;
                else                src = BL + (size_t)(nBase + row) * ldb + k0 + 8 * seg;
            }
            uint32_t dst = bufs_u + (uint32_t)s * STAGEB + (uint32_t)tens * TILEB +
                           (uint32_t)row * PITCH + (uint32_t)seg * 16;
            asm volatile("cp.async.cg.shared.global [%0], [%1], 16;" :: "r"(dst), "l"(src) : "memory");
        }
        asm volatile("cp.async.commit_group;" ::: "memory");
    };

    int nStages = K / 32;
    issue(0, 0);
    for (int ck = 0; ck < nStages; ck++) {
        if (ck) __syncthreads();
        bool pre = (ck + 1 < nStages);
        if (pre) issue((ck + 1) & 1, (ck + 1) * 32);
        if (pre) asm volatile("cp.async.wait_group 1;" ::: "memory");
        else     asm volatile("cp.async.wait_group 0;" ::: "memory");
        __syncthreads();

        uint32_t base = bufs_u + (uint32_t)(ck & 1) * STAGEB;
#pragma unroll
        for (int p = 0; p < 2; p++) {
            uint32_t koff = 32u * p;
            if (PASSES == 3) {
                uint32_t bH[4][2], bL[4][2], af[4][4];
#pragma unroll
                for (int nh = 0; nh < 2; nh++) {
                    uint32_t r0, r1, r2, r3;
                    LDSM_X4(r0, r1, r2, r3, base + 2 * TILEB + bOff + nh * 16 * PITCH + koff);
                    bH[2 * nh][0] = r0; bH[2 * nh][1] = r1; bH[2 * nh + 1][0] = r2; bH[2 * nh + 1][1] = r3;
                    LDSM_X4(r0, r1, r2, r3, base + 3 * TILEB + bOff + nh * 16 * PITCH + koff);
                    bL[2 * nh][0] = r0; bL[2 * nh][1] = r1; bL[2 * nh + 1][0] = r2; bL[2 * nh + 1][1] = r3;
                }
#pragma unroll
                for (int mf = 0; mf < 4; mf++)
                    LDSM_X4(af[mf][0], af[mf][1], af[mf][2], af[mf][3],
                            base + 0 * TILEB + aOff + mf * 16 * PITCH + koff);
#pragma unroll
                for (int mf = 0; mf < 4; mf++)
#pragma unroll
                    for (int nf = 0; nf < 4; nf++)
                        mma_any<ISF16>(acc[mf][nf], af[mf][0], af[mf][1], af[mf][2], af[mf][3],
                                       bH[nf][0], bH[nf][1]);
#pragma unroll
                for (int mf = 0; mf < 4; mf++)
#pragma unroll
                    for (int nf = 0; nf < 4; nf++)
                        mma_any<ISF16>(acc[mf][nf], af[mf][0], af[mf][1], af[mf][2], af[mf][3],
                                       bL[nf][0], bL[nf][1]);
#pragma unroll
                for (int mf = 0; mf < 4; mf++)
                    LDSM_X4(af[mf][0], af[mf][1], af[mf][2], af[mf][3],
                            base + 1 * TILEB + aOff + mf * 16 * PITCH + koff);
#pragma unroll
                for (int mf = 0; mf < 4; mf++)
#pragma unroll
                    for (int nf = 0; nf < 4; nf++)
                        mma_any<ISF16>(acc[mf][nf], af[mf][0], af[mf][1], af[mf][2], af[mf][3],
                                       bH[nf][0], bH[nf][1]);
            } else {
                uint32_t bb[4][2], af[4][4];
#pragma unroll
                for (int nh = 0; nh < 2; nh++) {
                    uint32_t r0, r1, r2, r3;
                    LDSM_X4(r0, r1, r2, r3, base + BT * TILEB + bOff + nh * 16 * PITCH + koff);
                    bb[2 * nh][0] = r0; bb[2 * nh][1] = r1; bb[2 * nh + 1][0] = r2; bb[2 * nh + 1][1] = r3;
                }
#pragma unroll
                for (int mf = 0; mf < 4; mf++)
                    LDSM_X4(af[mf][0], af[mf][1], af[mf][2], af[mf][3],
                            base + 0 * TILEB + aOff + mf * 16 * PITCH + koff);
#pragma unroll
                for (int mf = 0; mf < 4; mf++)
#pragma unroll
                    for (int nf = 0; nf < 4; nf++)
                        mma_any<ISF16>(acc[mf][nf], af[mf][0], af[mf][1], af[mf][2], af[mf][3],
                                       bb[nf][0], bb[nf][1]);
            }
        }
    }

    // ---- epilogue ----
#pragma unroll
    for (int mf = 0; mf < 4; mf++) {
#pragma unroll
        for (int nf = 0; nf < 4; nf++) {
            float* c = acc[mf][nf];
            int r0 = mBase + wm + mf * 16 + lq;
            int c0 = nBase + wn + nf * 8 + 2 * lr;
#pragma unroll
            for (int half = 0; half < 2; half++) {
                int r = r0 + half * 8;
                if (r >= Meff) continue;
                float v0 = c[half * 2 + 0], v1 = c[half * 2 + 1];
                if (EPI == 0) {
                    C[(size_t)r * ldc + c0] = v0;
                    C[(size_t)r * ldc + c0 + 1] = v1;
                } else if (EPI == 1) {
                    float o0 = v0 + aux0[(size_t)r * ldc + c0] + aux1[c0];
                    float o1 = v1 + aux0[(size_t)r * ldc + c0 + 1] + aux1[c0 + 1];
                    C[(size_t)r * ldc + c0] = o0;  C2[(size_t)r * ldc + c0] = o0;
                    C[(size_t)r * ldc + c0 + 1] = o1; C2[(size_t)r * ldc + c0 + 1] = o1;
                } else if (EPI == 3) {
                    int tok = out_idx[r];
                    float wgt = out_wt[r];
                    atomicAdd(&C[(size_t)tok * ldc + c0], wgt * v0);
                    atomicAdd(&C[(size_t)tok * ldc + c0 + 1], wgt * v1);
                } else {   // EPI == 4: RoPE on q,k pairs then store
                    int s = r & (SEQ - 1);
                    int sub = c0 % 192;
                    if (sub < 128) {
                        int d2 = (sub & 63) >> 1;
                        float cc = aux0[s * 32 + d2], sn = aux1[s * 32 + d2];
                        C[(size_t)r * ldc + c0]     = v0 * cc - v1 * sn;
                        C[(size_t)r * ldc + c0 + 1] = v0 * sn + v1 * cc;
                    } else {
                        C[(size_t)r * ldc + c0] = v0;
                        C[(size_t)r * ldc + c0 + 1] = v1;
                    }
                }
            }
        }
    }
}

// QKV: fp16 1-pass + fused RoPE
__global__ void __launch_bounds__(256, 2)
kan_gemm_qkv(const float* __restrict__ rc, const float* __restrict__ rs,
             float* __restrict__ qkv) {
    gemm_body<4, 1, 1>((const uint16_t*)g_phiF, nullptr, KAUG, nullptr,
                       (const uint16_t*)g_qkvwF, nullptr, KAUG,
                       qkv, 3072, TOK, KAUG, nullptr, rc, rs, nullptr, nullptr, nullptr);
}

// out-proj: bf16 3-pass, residual+bias dual store (precision anchor)
__global__ void __launch_bounds__(256, 2)
kan_gemm_op(const float* __restrict__ x, const float* __restrict__ bias,
            float* __restrict__ x2, float* __restrict__ out) {
    gemm_body<1, 3, 0>((const uint16_t*)g_ctxH, (const uint16_t*)g_ctxL, HID, nullptr,
                       (const uint16_t*)g_owH, (const uint16_t*)g_owL, HID,
                       x2, HID, TOK, HID, nullptr, x, bias, out, nullptr, nullptr);
}

// batched w1+w2: fp16 1-pass
__global__ void __launch_bounds__(256, 2)
kan_gemm_w12() {
    int z = blockIdx.z, e = z >> 1, sel = z & 1;
    const uint16_t* B = (const uint16_t*)((sel ? g_w2F : g_w1F) + (size_t)e * DFF * KAUG);
    float* C = (sel ? g_t2 : g_t1) + (size_t)e * TOK * DFF;
    gemm_body<0, 1, 1>((const uint16_t*)g_phiF, nullptr, KAUG,
                       g_eidx + e * TOK, B, nullptr, KAUG,
                       C, DFF, TOK, KAUG, g_cnt + e, nullptr, nullptr, nullptr, nullptr, nullptr);
}

// batched w3: fp16 1-pass, atomic scatter
__global__ void __launch_bounds__(256, 2)
kan_gemm_w3(float* __restrict__ out) {
    int e = blockIdx.z;
    gemm_body<3, 1, 1>((const uint16_t*)(g_phitF + (size_t)e * TOK * KAUG), nullptr,
                       KAUG, nullptr,
                       (const uint16_t*)(g_w3F + (size_t)e * HID * KAUG), nullptr, KAUG,
                       out, HID, TOK, KAUG, g_cnt + e, nullptr, nullptr, nullptr,
                       g_eidx + e * TOK, g_ew + e * TOK);
}

// ---------------- FlashAttention-2 on tensor cores --------------------------------
// 128 q-rows per CTA, 8 warps x 16 rows; each warp owns full rows (warp-local softmax).
// Q/K fp16 in smem (K-major, pitch 72 halves); V fp16 transposed [d][k].
#define FAQ   128
#define FAP   72      // smem pitch in halves (144B, 16B-aligned, conflict-free ldmatrix)
__global__ void __launch_bounds__(256, 1)
flash_attn_kernel(const float* __restrict__ qkv,
                  __nv_bfloat16* __restrict__ ctxH,
                  __nv_bfloat16* __restrict__ ctxL) {
    __shared__ __half Qs[FAQ * FAP];
    __shared__ __half Ks[64 * FAP];
    __shared__ __half Vs[64 * FAP];   // transposed: [d][kpos]

    int qt = blockIdx.x, bh = blockIdx.y;
    int b = bh >> 4, h = bh & 15;
    int tid = threadIdx.x;
    int w = tid >> 5, l = tid & 31;
    int lq = l >> 2, lr = l & 3;
    uint32_t qs_u = smem_u32(Qs), ks_u = smem_u32(Ks), vs_u = smem_u32(Vs);

    // ---- load Q tile (fp32 -> fp16) ----
    {
        int row = tid >> 1;
        int cb = (tid & 1) * 32;
        const float* src = qkv + (size_t)(b * SEQ + qt * FAQ + row) * 3072 + h * 192 + cb;
        __half* dst = Qs + row * FAP + cb;
#pragma unroll
        for (int u = 0; u < 8; u++) {
            float4 v = *(const float4*)(src + u * 4);
            dst[u * 4 + 0] = __float2half_rn(v.x);
            dst[u * 4 + 1] = __float2half_rn(v.y);
            dst[u * 4 + 2] = __float2half_rn(v.z);
            dst[u * 4 + 3] = __float2half_rn(v.w);
        }
    }

    float o[8][4];
#pragma unroll
    for (int t = 0; t < 8; t++)
#pragma unroll
        for (int j = 0; j < 4; j++) o[t][j] = 0.f;
    float m0 = -1e30f, m1 = -1e30f, l0 = 0.f, l1 = 0.f;

    for (int kt = 0; kt < SEQ / 64; kt++) {
        __syncthreads();   // prior compute done reading Ks/Vs (and Q stores on iter 0)
        // ---- load K,V tile ----
        {
            int row = tid >> 2;
            int cb = (tid & 3) * 16;
            const float* ks = qkv + (size_t)(b * SEQ + kt * 64 + row) * 3072 + h * 192 + 64 + cb;
            const float* vs = ks + 64;
            __half* kd = Ks + row * FAP + cb;
#pragma unroll
            for (int u = 0; u < 4; u++) {
                float4 kv = *(const float4*)(ks + u * 4);
                kd[u * 4 + 0] = __float2half_rn(kv.x);
                kd[u * 4 + 1] = __float2half_rn(kv.y);
                kd[u * 4 + 2] = __float2half_rn(kv.z);
                kd[u * 4 + 3] = __float2half_rn(kv.w);
                float4 vv = *(const float4*)(vs + u * 4);
                Vs[(cb + u * 4 + 0) * FAP + row] = __float2half_rn(vv.x);
                Vs[(cb + u * 4 + 1) * FAP + row] = __float2half_rn(vv.y);
                Vs[(cb + u * 4 + 2) * FAP + row] = __float2half_rn(vv.z);
                Vs[(cb + u * 4 + 3) * FAP + row] = __float2half_rn(vv.w);
            }
        }
        __syncthreads();

        // ---- S = Q K^T (8 n8-tiles per warp, fp32 accum) ----
        float s[8][4];
#pragma unroll
        for (int t = 0; t < 8; t++)
#pragma unroll
            for (int j = 0; j < 4; j++) s[t][j] = 0.f;
#pragma unroll
        for (int kk = 0; kk < 4; kk++) {
            uint32_t a0, a1, a2, a3;
            LDSM_X4(a0, a1, a2, a3,
                    qs_u + ((w * 16 + (l & 15)) * FAP + (l >> 4) * 8 + kk * 16) * 2);
#pragma unroll
            for (int jp = 0; jp < 4; jp++) {
                uint32_t r0, r1, r2, r3;
                LDSM_X4(r0, r1, r2, r3,
                        ks_u + ((jp * 16 + (l & 7) + ((l & 16) ? 8 : 0)) * FAP + kk * 16) * 2 +
                        ((l & 8) ? 16u : 0u));
                mma_any<1>(s[2 * jp],     a0, a1, a2, a3, r0, r1);
                mma_any<1>(s[2 * jp + 1], a0, a1, a2, a3, r2, r3);
            }
        }

        // ---- softmax update (rows lq and lq+8, warp-local) ----
        float mx0 = m0, mx1 = m1;
#pragma unroll
        for (int t = 0; t < 8; t++) {
#pragma unroll
            for (int j = 0; j < 4; j++) s[t][j] *= 0.125f;
            mx0 = fmaxf(mx0, fmaxf(s[t][0], s[t][1]));
            mx1 = fmaxf(mx1, fmaxf(s[t][2], s[t][3]));
        }
        mx0 = fmaxf(mx0, __shfl_xor_sync(0xffffffff, mx0, 1));
        mx0 = fmaxf(mx0, __shfl_xor_sync(0xffffffff, mx0, 2));
        mx1 = fmaxf(mx1, __shfl_xor_sync(0xffffffff, mx1, 1));
        mx1 = fmaxf(mx1, __shfl_xor_sync(0xffffffff, mx1, 2));
        float corr0 = __expf(m0 - mx0), corr1 = __expf(m1 - mx1);
        m0 = mx0; m1 = mx1;

        uint32_t ph[8], pl[8];
        float sum0 = 0.f, sum1 = 0.f;
#pragma unroll
        for (int t = 0; t < 8; t++) {
            float p0 = __expf(s[t][0] - mx0);
            float p1 = __expf(s[t][1] - mx0);
            float p2 = __expf(s[t][2] - mx1);
            float p3 = __expf(s[t][3] - mx1);
            sum0 += p0 + p1; sum1 += p2 + p3;
            __half2 h0 = __floats2half2_rn(p0, p1);
            __half2 h1 = __floats2half2_rn(p2, p3);
            ph[t] = *reinterpret_cast<uint32_t*>(&h0);
            pl[t] = *reinterpret_cast<uint32_t*>(&h1);
        }
        sum0 += __shfl_xor_sync(0xffffffff, sum0, 1);
        sum0 += __shfl_xor_sync(0xffffffff, sum0, 2);
        sum1 += __shfl_xor_sync(0xffffffff, sum1, 1);
        sum1 += __shfl_xor_sync(0xffffffff, sum1, 2);
        l0 = corr0 * l0 + sum0;
        l1 = corr1 * l1 + sum1;
#pragma unroll
        for (int t = 0; t < 8; t++) {
            o[t][0] *= corr0; o[t][1] *= corr0;
            o[t][2] *= corr1; o[t][3] *= corr1;
        }

        // ---- O += P V  (P fragments reused directly as A operands) ----
#pragma unroll
        for (int kk = 0; kk < 4; kk++) {
            uint32_t a0 = ph[2 * kk], a1 = pl[2 * kk];
            uint32_t a2 = ph[2 * kk + 1], a3 = pl[2 * kk + 1];
#pragma unroll
            for (int jp = 0; jp < 4; jp++) {
                uint32_t r0, r1, r2, r3;
                LDSM_X4(r0, r1, r2, r3,
                        vs_u + ((jp * 16 + (l & 7) + ((l & 16) ? 8 : 0)) * FAP + kk * 16) * 2 +
                        ((l & 8) ? 16u : 0u));
                mma_any<1>(o[2 * jp],     a0, a1, a2, a3, r0, r1);
                mma_any<1>(o[2 * jp + 1], a0, a1, a2, a3, r2, r3);
            }
        }
    }

    // ---- normalize + store ctx as bf16 hi/lo ----
    float inv0 = 1.0f / l0, inv1 = 1.0f / l1;
    int r0g = b * SEQ + qt * FAQ + w * 16 + lq;
#pragma unroll
    for (int t = 0; t < 8; t++) {
        int col = h * 64 + t * 8 + 2 * lr;
        __nv_bfloat16 hh, ll;
        size_t off0 = (size_t)r0g * HID + col;
        size_t off1 = (size_t)(r0g + 8) * HID + col;
        hl_pair(o[t][0] * inv0, hh, ll); ctxH[off0] = hh;     ctxL[off0] = ll;
        hl_pair(o[t][1] * inv0, hh, ll); ctxH[off0 + 1] = hh; ctxL[off0 + 1] = ll;
        hl_pair(o[t][2] * inv1, hh, ll); ctxH[off1] = hh;     ctxL[off1] = ll;
        hl_pair(o[t][3] * inv1, hh, ll); ctxH[off1 + 1] = hh; ctxL[off1 + 1] = ll;
    }
}

// ---------------- MoE routing -----------------------------------------------------
__global__ void init_cnt_kernel() {
    if (threadIdx.x < NEXP) g_cnt[threadIdx.x] = 0;
}

__global__ void routing_kernel() {
    int m = blockIdx.x * 256 + threadIdx.x;
    if (m >= TOK) return;
    float l[4];
#pragma unroll
    for (int e = 0; e < 4; e++) l[e] = g_logits[m * 4 + e];
    int i0 = 0; float b0 = l[0];
#pragma unroll
    for (int e = 1; e < 4; e++) if (l[e] > b0) { b0 = l[e]; i0 = e; }
    int i1 = -1; float b1 = -1e30f;
#pragma unroll
    for (int e = 0; e < 4; e++) if (e != i0 && l[e] > b1) { b1 = l[e]; i1 = e; }
    float t = expf(b1 - b0);
    float w0 = 1.0f / (1.0f + t);
    float w1 = t / (1.0f + t);
    int p0 = atomicAdd(&g_cnt[i0], 1);
    g_eidx[i0 * TOK + p0] = m; g_ew[i0 * TOK + p0] = w0;
    int p1 = atomicAdd(&g_cnt[i1], 1);
    g_eidx[i1 * TOK + p1] = m; g_ew[i1 * TOK + p1] = w1;
}

// ---------------- host orchestration ----------------------------------------------
extern "C" void kernel_launch(void* const* d_in, const int* in_sizes, int n_in,
                              void* d_out, int out_size) {
    const float* x          = (const float*)d_in[0];
    const float* rot_cos    = (const float*)d_in[1];
    const float* rot_sin    = (const float*)d_in[2];
    const float* norm1_w    = (const float*)d_in[3];
    const float* norm2_w    = (const float*)d_in[4];
    const float* qkv_base   = (const float*)d_in[5];
    const float* qkv_spline = (const float*)d_in[6];
    const float* qkv_scaler = (const float*)d_in[7];
    const float* out_w      = (const float*)d_in[8];
    const float* out_b      = (const float*)d_in[9];
    const float* gate_w     = (const float*)d_in[10];
    const float* w1_base    = (const float*)d_in[11];
    const float* w1_spline  = (const float*)d_in[12];
    const float* w1_scaler  = (const float*)d_in[13];
    const float* w2_base    = (const float*)d_in[14];
    const float* w2_spline  = (const float*)d_in[15];
    const float* w2_scaler  = (const float*)d_in[16];
    const float* w3_base    = (const float*)d_in[17];
    const float* w3_spline  = (const float*)d_in[18];
    const float* w3_scaler  = (const float*)d_in[19];
    float* out = (float*)d_out;

    __half *phiF, *qwF, *w1F, *w2F, *w3F;
    __nv_bfloat16 *ctxH, *ctxL, *owH, *owL;
    float *qkv, *x2, *logits;
    cudaGetSymbolAddress((void**)&phiF, g_phiF);
    cudaGetSymbolAddress((void**)&ctxH, g_ctxH);   cudaGetSymbolAddress((void**)&ctxL, g_ctxL);
    cudaGetSymbolAddress((void**)&qwF, g_qkvwF);
    cudaGetSymbolAddress((void**)&w1F, g_w1F);     cudaGetSymbolAddress((void**)&w2F, g_w2F);
    cudaGetSymbolAddress((void**)&w3F, g_w3F);
    cudaGetSymbolAddress((void**)&owH, g_owH);     cudaGetSymbolAddress((void**)&owL, g_owL);
    cudaGetSymbolAddress((void**)&qkv, g_qkv);     cudaGetSymbolAddress((void**)&x2, g_x2);
    cudaGetSymbolAddress((void**)&logits, g_logits);

    cudaFuncSetAttribute(kan_gemm_qkv, cudaFuncAttributeMaxDynamicSharedMemorySize, GM_DYN1);
    cudaFuncSetAttribute(kan_gemm_op,  cudaFuncAttributeMaxDynamicSharedMemorySize, GM_DYN3);
    cudaFuncSetAttribute(kan_gemm_w12, cudaFuncAttributeMaxDynamicSharedMemorySize, GM_DYN1);
    cudaFuncSetAttribute(kan_gemm_w3,  cudaFuncAttributeMaxDynamicSharedMemorySize, GM_DYN1);

    // 0) weight conversion (single fp16 except out_w)
    conv_kan_w_h1<<<3072, 256>>>(qkv_base, qkv_spline, qkv_scaler, HID, qwF);
    conv_kan_w_h1<<<NEXP * DFF, 256>>>(w1_base, w1_spline, w1_scaler, HID, w1F);
    conv_kan_w_h1<<<NEXP * DFF, 256>>>(w2_base, w2_spline, w2_scaler, HID, w2F);
    conv_kan_w_h1<<<NEXP * HID, 256>>>(w3_base, w3_spline, w3_scaler, DFF, w3F);
    conv_plain<<<(HID * HID + 255) / 256, 256>>>(out_w, owH, owL, HID * HID);

    // 1) rmsnorm(x) -> phi fp16
    rmsnorm_phi_kernel<<<TOK, 256>>>(x, norm1_w, phiF, nullptr, nullptr);

    // 2) QKV = phi @ Waug^T with fused RoPE (1-pass fp16)
    kan_gemm_qkv<<<dim3(3072 / 128, TOK / 128), 256, GM_DYN1>>>(rot_cos, rot_sin, qkv);

    // 3) attention (FA2 on tensor cores)
    flash_attn_kernel<<<dim3(SEQ / FAQ, BATCH * NHEAD), 256>>>(qkv, ctxH, ctxL);

    // 4) x2 = x + ctx @ out_w^T + out_b (dual store into d_out)
    kan_gemm_op<<<dim3(HID / 128, TOK / 128), 256, GM_DYN3>>>(x, out_b, x2, out);

    // 5) rmsnorm(x2) -> phi fp16, gate logits
    rmsnorm_phi_kernel<<<TOK, 256>>>(x2, norm2_w, phiF, gate_w, logits);

    // 6) routing
    init_cnt_kernel<<<1, 32>>>();
    routing_kernel<<<TOK / 256, 256>>>();

    // 7) MoE batched
    kan_gemm_w12<<<dim3(DFF / 128, TOK / 128, 2 * NEXP), 256, GM_DYN1>>>();
    mul_phi_kernel<<<dim3(TOK, NEXP), 256>>>();
    kan_gemm_w3<<<dim3(HID / 128, TOK / 128, NEXP), 256, GM_DYN1>>>(out);
}